// round 2
// baseline (speedup 1.0000x reference)
#include <cuda_runtime.h>
#include <math_constants.h>

#define T_LEN   4096
#define DIM     1024
#define QKV_DIM 3072
#define MLP_DIM 4096
#define NHEADS  16
#define HD      64
#define WIN     512
#define EPS_F   1.1920929e-07f

// ---------------- scratch (static device arrays; no allocations) ----------------
__device__ float g_xn  [T_LEN * DIM];      // rmsnorm(x)
__device__ float g_qkv [T_LEN * QKV_DIM];  // qkv projection
__device__ float g_qrot[T_LEN * DIM];      // q after head-rmsnorm + rope
__device__ float g_krot[T_LEN * DIM];      // k after head-rmsnorm + rope
__device__ float g_attn[T_LEN * DIM];      // attention output
__device__ float g_x1  [T_LEN * DIM];      // x + o  (residual 1)
__device__ float g_x1n [T_LEN * DIM];      // rmsnorm(x1)
__device__ float g_h   [T_LEN * MLP_DIM];  // relu(h)^2

// ---------------- rmsnorm over rows of length 1024 ----------------
__global__ __launch_bounds__(256) void rmsnorm_k(const float* __restrict__ x,
                                                 float* __restrict__ y) {
    __shared__ float red[8];
    const int row = blockIdx.x;
    const int tid = threadIdx.x;
    float4 v = ((const float4*)(x + (size_t)row * DIM))[tid];
    float ss = v.x * v.x + v.y * v.y + v.z * v.z + v.w * v.w;
    #pragma unroll
    for (int off = 16; off; off >>= 1) ss += __shfl_xor_sync(0xffffffffu, ss, off);
    if ((tid & 31) == 0) red[tid >> 5] = ss;
    __syncthreads();
    float tot = 0.f;
    #pragma unroll
    for (int i = 0; i < 8; i++) tot += red[i];
    const float r = rsqrtf(tot * (1.0f / DIM) + EPS_F);
    v.x *= r; v.y *= r; v.z *= r; v.w *= r;
    ((float4*)(y + (size_t)row * DIM))[tid] = v;
}

// ---------------- per-head q/k rmsnorm + partial rotary ----------------
// one warp = one (token, head) norm; blockIdx.y*8 + warp in [0,32): <16 -> q head, else k head
__global__ __launch_bounds__(256) void qk_prep(const float* __restrict__ qkv,
                                               float* __restrict__ qr,
                                               float* __restrict__ kr) {
    const int t    = blockIdx.x;
    const int idx  = blockIdx.y * 8 + (threadIdx.x >> 5);
    const int lane = threadIdx.x & 31;
    const float* src;
    float* dst;
    if (idx < NHEADS) {
        src = qkv + (size_t)t * QKV_DIM + idx * HD;
        dst = qr + (size_t)t * DIM + idx * HD;
    } else {
        src = qkv + (size_t)t * QKV_DIM + DIM + (idx - NHEADS) * HD;
        dst = kr + (size_t)t * DIM + (idx - NHEADS) * HD;
    }
    float a = src[lane];
    float b = src[lane + 32];
    float ss = a * a + b * b;
    #pragma unroll
    for (int off = 16; off; off >>= 1) ss += __shfl_xor_sync(0xffffffffu, ss, off);
    const float r = rsqrtf(ss * (1.0f / HD) + EPS_F);
    a *= r; b *= r;
    float sn = 0.f, cs = 1.f;
    if (lane < 16) {
        const float f = powf(1e-4f, (float)lane * (1.0f / 15.0f));
        sincosf((float)t * f, &sn, &cs);
    }
    dst[lane]      =  a * cs + b * sn;
    dst[lane + 32] = -a * sn + b * cs;
}

// ---------------- sliding-window attention ----------------
// grid (T/64, NHEADS), 512 threads. Warp w handles queries q0+4w..q0+4w+3.
// Keys processed in chunks of 32. Key k valid for query q iff q-512 < k <= q.
#define ACH 32
__global__ __launch_bounds__(512) void attn_kernel(const float* __restrict__ qrot,
                                                   const float* __restrict__ krot,
                                                   const float* __restrict__ qkv,
                                                   float* __restrict__ out) {
    __shared__ float4 q_s4[64 * 16];     // [qlocal][d4]          16 KB
    __shared__ float4 kT4 [16 * 33];     // [d4][key] padded      ~8.4 KB
    __shared__ float4 vs4 [ACH * 16];    // [key][d4]              8 KB
    __shared__ float4 p_s4[16 * 32];     // [warp][key] -> 4 q's   8 KB
    const int h    = blockIdx.y;
    const int q0   = blockIdx.x * 64;
    const int tid  = threadIdx.x;
    const int w    = tid >> 5;
    const int lane = tid & 31;

    for (int i = tid; i < 64 * 16; i += 512) {
        const int qi = i >> 4, d4 = i & 15;
        q_s4[i] = *(const float4*)&qrot[(size_t)(q0 + qi) * DIM + h * HD + d4 * 4];
    }

    int kb = q0 - (WIN - 1);
    if (kb < 0) kb = 0;
    const int nch = (q0 + 64 - kb + ACH - 1) / ACH;

    float m[4], l[4], o0[4], o1[4];
    #pragma unroll
    for (int i = 0; i < 4; i++) { m[i] = -CUDART_INF_F; l[i] = 0.f; o0[i] = 0.f; o1[i] = 0.f; }
    const int qbase = q0 + w * 4;

    for (int c = 0; c < nch; c++) {
        const int kc = kb + c * ACH;
        __syncthreads();  // prior chunk's reads complete before overwrite
        {   // load K chunk transposed + V chunk, 512 float4 total = 1/thread
            const int key = tid >> 4, d4 = tid & 15;
            const int kg = kc + key;
            float4 kv = make_float4(0.f, 0.f, 0.f, 0.f);
            float4 vv = make_float4(0.f, 0.f, 0.f, 0.f);
            if (kg < T_LEN) {
                kv = *(const float4*)&krot[(size_t)kg * DIM + h * HD + d4 * 4];
                vv = *(const float4*)&qkv[(size_t)kg * QKV_DIM + 2 * DIM + h * HD + d4 * 4];
            }
            kT4[d4 * 33 + key]  = kv;
            vs4[key * 16 + d4]  = vv;
        }
        __syncthreads();

        const int key = lane;
        const int kg  = kc + key;
        float s[4] = {0.f, 0.f, 0.f, 0.f};
        #pragma unroll
        for (int d4 = 0; d4 < 16; d4++) {
            const float4 kv = kT4[d4 * 33 + key];
            const float4 qa = q_s4[(w * 4 + 0) * 16 + d4];
            const float4 qb = q_s4[(w * 4 + 1) * 16 + d4];
            const float4 qc = q_s4[(w * 4 + 2) * 16 + d4];
            const float4 qd = q_s4[(w * 4 + 3) * 16 + d4];
            s[0] += qa.x * kv.x + qa.y * kv.y + qa.z * kv.z + qa.w * kv.w;
            s[1] += qb.x * kv.x + qb.y * kv.y + qb.z * kv.z + qb.w * kv.w;
            s[2] += qc.x * kv.x + qc.y * kv.y + qc.z * kv.z + qc.w * kv.w;
            s[3] += qd.x * kv.x + qd.y * kv.y + qd.z * kv.z + qd.w * kv.w;
        }
        float* pw = (float*)&p_s4[w * 32];
        #pragma unroll
        for (int qi = 0; qi < 4; qi++) {
            const int q = qbase + qi;
            const bool valid = (kg <= q) && (kg > q - WIN);
            const float sv = valid ? s[qi] * 0.125f : -CUDART_INF_F;
            float smax = sv;
            #pragma unroll
            for (int off = 16; off; off >>= 1)
                smax = fmaxf(smax, __shfl_xor_sync(0xffffffffu, smax, off));
            float p = 0.f;
            if (smax != -CUDART_INF_F) {   // warp-uniform branch
                const float mn = fmaxf(m[qi], smax);
                const float corr = __expf(m[qi] - mn);  // 0 if m was -inf
                p = __expf(sv - mn);
                float ps = p;
                #pragma unroll
                for (int off = 16; off; off >>= 1)
                    ps += __shfl_xor_sync(0xffffffffu, ps, off);
                l[qi] = l[qi] * corr + ps;
                o0[qi] *= corr; o1[qi] *= corr;
                m[qi] = mn;
            }
            pw[lane * 4 + qi] = p;
        }
        __syncwarp();
        #pragma unroll 8
        for (int kk = 0; kk < ACH; kk++) {
            const float4 p4 = p_s4[w * 32 + kk];
            const float2 v2 = ((const float2*)(vs4 + kk * 16))[lane];
            o0[0] += p4.x * v2.x; o1[0] += p4.x * v2.y;
            o0[1] += p4.y * v2.x; o1[1] += p4.y * v2.y;
            o0[2] += p4.z * v2.x; o1[2] += p4.z * v2.y;
            o0[3] += p4.w * v2.x; o1[3] += p4.w * v2.y;
        }
        __syncwarp();
    }
    #pragma unroll
    for (int qi = 0; qi < 4; qi++) {
        const float inv = 1.0f / l[qi];
        const int q = qbase + qi;
        float2 r;
        r.x = o0[qi] * inv;
        r.y = o1[qi] * inv;
        *(float2*)&out[(size_t)q * DIM + h * HD + lane * 2] = r;
    }
}

// ---------------- SGEMM: C[M,N] = f( A[M,K] @ B[N,K]^T ) ----------------
// MODE 0: C = acc
// MODE 1: C = res + scale[n] * acc
// MODE 2: C = relu(acc)^2
template <int MODE>
__global__ __launch_bounds__(256) void sgemm(const float* __restrict__ A,
                                             const float* __restrict__ B,
                                             float* __restrict__ C,
                                             const float* __restrict__ res,
                                             const float* __restrict__ scale,
                                             int M, int N, int K) {
    __shared__ float As[8][128];
    __shared__ float Bs[8][128];
    const int m0 = blockIdx.y * 128, n0 = blockIdx.x * 128;
    const int tid  = threadIdx.x;
    const int lrow = tid >> 1;
    const int lcol = (tid & 1) * 4;
    const float* Ag = A + (size_t)(m0 + lrow) * K + lcol;
    const float* Bg = B + (size_t)(n0 + lrow) * K + lcol;
    const int tx = tid & 15, ty = tid >> 4;

    float acc[8][8];
    #pragma unroll
    for (int i = 0; i < 8; i++)
        #pragma unroll
        for (int j = 0; j < 8; j++) acc[i][j] = 0.f;

    float4 pa = *(const float4*)Ag;
    float4 pb = *(const float4*)Bg;

    for (int k0 = 0; k0 < K; k0 += 8) {
        As[lcol + 0][lrow] = pa.x; As[lcol + 1][lrow] = pa.y;
        As[lcol + 2][lrow] = pa.z; As[lcol + 3][lrow] = pa.w;
        Bs[lcol + 0][lrow] = pb.x; Bs[lcol + 1][lrow] = pb.y;
        Bs[lcol + 2][lrow] = pb.z; Bs[lcol + 3][lrow] = pb.w;
        __syncthreads();
        if (k0 + 8 < K) {
            pa = *(const float4*)(Ag + k0 + 8);
            pb = *(const float4*)(Bg + k0 + 8);
        }
        #pragma unroll
        for (int kk = 0; kk < 8; kk++) {
            float a[8], b[8];
            *(float4*)(a)     = *(const float4*)&As[kk][ty * 8];
            *(float4*)(a + 4) = *(const float4*)&As[kk][ty * 8 + 4];
            *(float4*)(b)     = *(const float4*)&Bs[kk][tx * 8];
            *(float4*)(b + 4) = *(const float4*)&Bs[kk][tx * 8 + 4];
            #pragma unroll
            for (int i = 0; i < 8; i++)
                #pragma unroll
                for (int j = 0; j < 8; j++)
                    acc[i][j] += a[i] * b[j];
        }
        __syncthreads();
    }

    const int nc = n0 + tx * 8;
    float4 s0, s1;
    if (MODE == 1) {
        s0 = *(const float4*)&scale[nc];
        s1 = *(const float4*)&scale[nc + 4];
    }
    #pragma unroll
    for (int i = 0; i < 8; i++) {
        const int mr = m0 + ty * 8 + i;
        float4 v0, v1;
        if (MODE == 0) {
            v0 = make_float4(acc[i][0], acc[i][1], acc[i][2], acc[i][3]);
            v1 = make_float4(acc[i][4], acc[i][5], acc[i][6], acc[i][7]);
        } else if (MODE == 1) {
            const float4 r0 = *(const float4*)&res[(size_t)mr * N + nc];
            const float4 r1 = *(const float4*)&res[(size_t)mr * N + nc + 4];
            v0 = make_float4(r0.x + s0.x * acc[i][0], r0.y + s0.y * acc[i][1],
                             r0.z + s0.z * acc[i][2], r0.w + s0.w * acc[i][3]);
            v1 = make_float4(r1.x + s1.x * acc[i][4], r1.y + s1.y * acc[i][5],
                             r1.z + s1.z * acc[i][6], r1.w + s1.w * acc[i][7]);
        } else {
            float t[8];
            #pragma unroll
            for (int j = 0; j < 8; j++) {
                const float rr = fmaxf(acc[i][j], 0.f);
                t[j] = rr * rr;
            }
            v0 = make_float4(t[0], t[1], t[2], t[3]);
            v1 = make_float4(t[4], t[5], t[6], t[7]);
        }
        *(float4*)&C[(size_t)mr * N + nc]     = v0;
        *(float4*)&C[(size_t)mr * N + nc + 4] = v1;
    }
}

// ---------------- host launcher ----------------
extern "C" void kernel_launch(void* const* d_in, const int* in_sizes, int n_in,
                              void* d_out, int out_size) {
    const float* x        = (const float*)d_in[0];
    const float* qkv_w    = (const float*)d_in[1];
    const float* o_w      = (const float*)d_in[2];
    const float* o_scale  = (const float*)d_in[3];
    const float* w1       = (const float*)d_in[4];
    const float* w2       = (const float*)d_in[5];
    const float* w2_scale = (const float*)d_in[6];
    float* out = (float*)d_out;

    float *xn, *qkv, *qrot, *krot, *attn, *x1, *x1n, *hb;
    cudaGetSymbolAddress((void**)&xn,   g_xn);
    cudaGetSymbolAddress((void**)&qkv,  g_qkv);
    cudaGetSymbolAddress((void**)&qrot, g_qrot);
    cudaGetSymbolAddress((void**)&krot, g_krot);
    cudaGetSymbolAddress((void**)&attn, g_attn);
    cudaGetSymbolAddress((void**)&x1,   g_x1);
    cudaGetSymbolAddress((void**)&x1n,  g_x1n);
    cudaGetSymbolAddress((void**)&hb,   g_h);

    // 1. xn = rmsnorm(x)
    rmsnorm_k<<<T_LEN, 256>>>(x, xn);
    // 2. qkv = xn @ qkv_w^T
    sgemm<0><<<dim3(QKV_DIM / 128, T_LEN / 128), 256>>>(xn, qkv_w, qkv,
                                                        nullptr, nullptr,
                                                        T_LEN, QKV_DIM, DIM);
    // 3. per-head rmsnorm + rope for q, k
    qk_prep<<<dim3(T_LEN, 4), 256>>>(qkv, qrot, krot);
    // 4. sliding-window attention
    attn_kernel<<<dim3(T_LEN / 64, NHEADS), 512>>>(qrot, krot, qkv, attn);
    // 5. x1 = x + o_scale[n] * (attn @ o_w^T)
    sgemm<1><<<dim3(DIM / 128, T_LEN / 128), 256>>>(attn, o_w, x1,
                                                    x, o_scale,
                                                    T_LEN, DIM, DIM);
    // 6. x1n = rmsnorm(x1)
    rmsnorm_k<<<T_LEN, 256>>>(x1, x1n);
    // 7. h = relu(x1n @ w1^T)^2
    sgemm<2><<<dim3(MLP_DIM / 128, T_LEN / 128), 256>>>(x1n, w1, hb,
                                                        nullptr, nullptr,
                                                        T_LEN, MLP_DIM, DIM);
    // 8. out = x1 + w2_scale[n] * (h @ w2^T)
    sgemm<1><<<dim3(DIM / 128, T_LEN / 128), 256>>>(hb, w2, out,
                                                    x1, w2_scale,
                                                    T_LEN, DIM, MLP_DIM);
}

// round 4
// speedup vs baseline: 1.9302x; 1.9302x over previous
#include <cuda_runtime.h>
#include <cuda_bf16.h>
#include <math_constants.h>
#include <cstdint>

#define T_LEN   4096
#define DIM     1024
#define QKV_DIM 3072
#define MLP_DIM 4096
#define NHEADS  16
#define HD      64
#define WIN     512
#define EPS_F   1.1920929e-07f

// ================= helpers =================
__device__ __forceinline__ uint32_t smem_u32(const void* p) {
    uint32_t a;
    asm("{ .reg .u64 t; cvta.to.shared.u64 t, %1; cvt.u32.u64 %0, t; }" : "=r"(a) : "l"(p));
    return a;
}
__device__ __forceinline__ void cp16(uint32_t s, const void* g) {
    asm volatile("cp.async.cg.shared.global [%0], [%1], 16;" :: "r"(s), "l"(g));
}
__device__ __forceinline__ void ldsm_x4(uint32_t* r, uint32_t addr) {
    asm volatile("ldmatrix.sync.aligned.m8n8.x4.shared.b16 {%0,%1,%2,%3}, [%4];"
                 : "=r"(r[0]), "=r"(r[1]), "=r"(r[2]), "=r"(r[3]) : "r"(addr));
}
__device__ __forceinline__ void mma16816(float* c, const uint32_t* a, const uint32_t* b) {
    asm volatile("mma.sync.aligned.m16n8k16.row.col.f32.bf16.bf16.f32 "
        "{%0,%1,%2,%3}, {%4,%5,%6,%7}, {%8,%9}, {%0,%1,%2,%3};"
        : "+f"(c[0]), "+f"(c[1]), "+f"(c[2]), "+f"(c[3])
        : "r"(a[0]), "r"(a[1]), "r"(a[2]), "r"(a[3]), "r"(b[0]), "r"(b[1]));
}
__device__ __forceinline__ void split_bf16(float a, __nv_bfloat16& hi, __nv_bfloat16& lo) {
    hi = __float2bfloat16(a);
    lo = __float2bfloat16(a - __bfloat162float(hi));
}

// ================= scratch =================
__device__ float g_qkv [T_LEN * QKV_DIM];
__device__ float g_qrot[T_LEN * DIM];
__device__ float g_krot[T_LEN * DIM];
__device__ float g_x1  [T_LEN * DIM];

#define BF16A __device__ __align__(16) __nv_bfloat16
BF16A g_xnh [T_LEN * DIM];     BF16A g_xnl [T_LEN * DIM];
BF16A g_ath [T_LEN * DIM];     BF16A g_atl [T_LEN * DIM];
BF16A g_x1nh[T_LEN * DIM];     BF16A g_x1nl[T_LEN * DIM];
BF16A g_hh  [T_LEN * MLP_DIM]; BF16A g_hl  [T_LEN * MLP_DIM];
BF16A g_wqh [QKV_DIM * DIM];   BF16A g_wql [QKV_DIM * DIM];
BF16A g_woh [DIM * DIM];       BF16A g_wol [DIM * DIM];
BF16A g_w1h [MLP_DIM * DIM];   BF16A g_w1l [MLP_DIM * DIM];
BF16A g_w2h [DIM * MLP_DIM];   BF16A g_w2l [DIM * MLP_DIM];

// ================= weight split =================
__global__ __launch_bounds__(256) void conv_split(const float* __restrict__ w,
                                                  __nv_bfloat16* __restrict__ hi,
                                                  __nv_bfloat16* __restrict__ lo, int n4) {
    const int i = blockIdx.x * 256 + threadIdx.x;
    if (i >= n4) return;
    float4 v = ((const float4*)w)[i];
    __nv_bfloat16 h0, h1, h2, h3, l0, l1, l2, l3;
    split_bf16(v.x, h0, l0); split_bf16(v.y, h1, l1);
    split_bf16(v.z, h2, l2); split_bf16(v.w, h3, l3);
    ((__nv_bfloat162*)hi)[i * 2]     = __halves2bfloat162(h0, h1);
    ((__nv_bfloat162*)hi)[i * 2 + 1] = __halves2bfloat162(h2, h3);
    ((__nv_bfloat162*)lo)[i * 2]     = __halves2bfloat162(l0, l1);
    ((__nv_bfloat162*)lo)[i * 2 + 1] = __halves2bfloat162(l2, l3);
}

// ================= rmsnorm -> bf16 hi/lo =================
__global__ __launch_bounds__(256) void rmsnorm_bf16(const float* __restrict__ x,
                                                    __nv_bfloat16* __restrict__ yh,
                                                    __nv_bfloat16* __restrict__ yl) {
    __shared__ float red[8];
    const int row = blockIdx.x;
    const int tid = threadIdx.x;
    float4 v = ((const float4*)(x + (size_t)row * DIM))[tid];
    float ss = v.x * v.x + v.y * v.y + v.z * v.z + v.w * v.w;
    #pragma unroll
    for (int off = 16; off; off >>= 1) ss += __shfl_xor_sync(0xffffffffu, ss, off);
    if ((tid & 31) == 0) red[tid >> 5] = ss;
    __syncthreads();
    float tot = 0.f;
    #pragma unroll
    for (int i = 0; i < 8; i++) tot += red[i];
    const float r = rsqrtf(tot * (1.0f / DIM) + EPS_F);
    __nv_bfloat16 h0, h1, h2, h3, l0, l1, l2, l3;
    split_bf16(v.x * r, h0, l0); split_bf16(v.y * r, h1, l1);
    split_bf16(v.z * r, h2, l2); split_bf16(v.w * r, h3, l3);
    const size_t base2 = (size_t)row * (DIM / 2) + tid * 2;
    ((__nv_bfloat162*)yh)[base2]     = __halves2bfloat162(h0, h1);
    ((__nv_bfloat162*)yh)[base2 + 1] = __halves2bfloat162(h2, h3);
    ((__nv_bfloat162*)yl)[base2]     = __halves2bfloat162(l0, l1);
    ((__nv_bfloat162*)yl)[base2 + 1] = __halves2bfloat162(l2, l3);
}

// ================= per-head q/k rmsnorm + partial rotary =================
__global__ __launch_bounds__(256) void qk_prep(const float* __restrict__ qkv,
                                               float* __restrict__ qr,
                                               float* __restrict__ kr) {
    const int t    = blockIdx.x;
    const int idx  = blockIdx.y * 8 + (threadIdx.x >> 5);
    const int lane = threadIdx.x & 31;
    const float* src;
    float* dst;
    if (idx < NHEADS) {
        src = qkv + (size_t)t * QKV_DIM + idx * HD;
        dst = qr + (size_t)t * DIM + idx * HD;
    } else {
        src = qkv + (size_t)t * QKV_DIM + DIM + (idx - NHEADS) * HD;
        dst = kr + (size_t)t * DIM + (idx - NHEADS) * HD;
    }
    float a = src[lane];
    float b = src[lane + 32];
    float ss = a * a + b * b;
    #pragma unroll
    for (int off = 16; off; off >>= 1) ss += __shfl_xor_sync(0xffffffffu, ss, off);
    const float r = rsqrtf(ss * (1.0f / HD) + EPS_F);
    a *= r; b *= r;
    float sn = 0.f, cs = 1.f;
    if (lane < 16) {
        const float f = powf(1e-4f, (float)lane * (1.0f / 15.0f));
        sincosf((float)t * f, &sn, &cs);
    }
    dst[lane]      =  a * cs + b * sn;
    dst[lane + 32] = -a * sn + b * cs;
}

// ================= sliding-window attention (bf16 hi/lo out) =================
#define ACH 32
__global__ __launch_bounds__(512) void attn_kernel(const float* __restrict__ qrot,
                                                   const float* __restrict__ krot,
                                                   const float* __restrict__ qkv,
                                                   __nv_bfloat16* __restrict__ oh,
                                                   __nv_bfloat16* __restrict__ ol) {
    __shared__ float4 q_s4[64 * 16];
    __shared__ float4 kT4 [16 * 33];
    __shared__ float4 vs4 [ACH * 16];
    __shared__ float4 p_s4[16 * 32];
    const int h    = blockIdx.y;
    const int q0   = blockIdx.x * 64;
    const int tid  = threadIdx.x;
    const int w    = tid >> 5;
    const int lane = tid & 31;

    for (int i = tid; i < 64 * 16; i += 512) {
        const int qi = i >> 4, d4 = i & 15;
        q_s4[i] = *(const float4*)&qrot[(size_t)(q0 + qi) * DIM + h * HD + d4 * 4];
    }

    int kb = q0 - (WIN - 1);
    if (kb < 0) kb = 0;
    const int nch = (q0 + 64 - kb + ACH - 1) / ACH;

    float m[4], l[4], o0[4], o1[4];
    #pragma unroll
    for (int i = 0; i < 4; i++) { m[i] = -CUDART_INF_F; l[i] = 0.f; o0[i] = 0.f; o1[i] = 0.f; }
    const int qbase = q0 + w * 4;

    for (int c = 0; c < nch; c++) {
        const int kc = kb + c * ACH;
        __syncthreads();
        {
            const int key = tid >> 4, d4 = tid & 15;
            const int kg = kc + key;
            float4 kv = make_float4(0.f, 0.f, 0.f, 0.f);
            float4 vv = make_float4(0.f, 0.f, 0.f, 0.f);
            if (kg < T_LEN) {
                kv = *(const float4*)&krot[(size_t)kg * DIM + h * HD + d4 * 4];
                vv = *(const float4*)&qkv[(size_t)kg * QKV_DIM + 2 * DIM + h * HD + d4 * 4];
            }
            kT4[d4 * 33 + key]  = kv;
            vs4[key * 16 + d4]  = vv;
        }
        __syncthreads();

        const int key = lane;
        const int kg  = kc + key;
        float s[4] = {0.f, 0.f, 0.f, 0.f};
        #pragma unroll
        for (int d4 = 0; d4 < 16; d4++) {
            const float4 kv = kT4[d4 * 33 + key];
            const float4 qa = q_s4[(w * 4 + 0) * 16 + d4];
            const float4 qb = q_s4[(w * 4 + 1) * 16 + d4];
            const float4 qc = q_s4[(w * 4 + 2) * 16 + d4];
            const float4 qd = q_s4[(w * 4 + 3) * 16 + d4];
            s[0] += qa.x * kv.x + qa.y * kv.y + qa.z * kv.z + qa.w * kv.w;
            s[1] += qb.x * kv.x + qb.y * kv.y + qb.z * kv.z + qb.w * kv.w;
            s[2] += qc.x * kv.x + qc.y * kv.y + qc.z * kv.z + qc.w * kv.w;
            s[3] += qd.x * kv.x + qd.y * kv.y + qd.z * kv.z + qd.w * kv.w;
        }
        float* pw = (float*)&p_s4[w * 32];
        #pragma unroll
        for (int qi = 0; qi < 4; qi++) {
            const int q = qbase + qi;
            const bool valid = (kg <= q) && (kg > q - WIN);
            const float sv = valid ? s[qi] * 0.125f : -CUDART_INF_F;
            float smax = sv;
            #pragma unroll
            for (int off = 16; off; off >>= 1)
                smax = fmaxf(smax, __shfl_xor_sync(0xffffffffu, smax, off));
            float p = 0.f;
            if (smax != -CUDART_INF_F) {
                const float mn = fmaxf(m[qi], smax);
                const float corr = __expf(m[qi] - mn);
                p = __expf(sv - mn);
                float ps = p;
                #pragma unroll
                for (int off = 16; off; off >>= 1)
                    ps += __shfl_xor_sync(0xffffffffu, ps, off);
                l[qi] = l[qi] * corr + ps;
                o0[qi] *= corr; o1[qi] *= corr;
                m[qi] = mn;
            }
            pw[lane * 4 + qi] = p;
        }
        __syncwarp();
        #pragma unroll 8
        for (int kk = 0; kk < ACH; kk++) {
            const float4 p4 = p_s4[w * 32 + kk];
            const float2 v2 = ((const float2*)(vs4 + kk * 16))[lane];
            o0[0] += p4.x * v2.x; o1[0] += p4.x * v2.y;
            o0[1] += p4.y * v2.x; o1[1] += p4.y * v2.y;
            o0[2] += p4.z * v2.x; o1[2] += p4.z * v2.y;
            o0[3] += p4.w * v2.x; o1[3] += p4.w * v2.y;
        }
        __syncwarp();
    }
    #pragma unroll
    for (int qi = 0; qi < 4; qi++) {
        const float inv = 1.0f / l[qi];
        const int q = qbase + qi;
        const float a0 = o0[qi] * inv, a1 = o1[qi] * inv;
        __nv_bfloat16 h0, h1, l0b, l1b;
        split_bf16(a0, h0, l0b);
        split_bf16(a1, h1, l1b);
        const size_t off2 = (size_t)q * (DIM / 2) + (h * HD) / 2 + lane;
        ((__nv_bfloat162*)oh)[off2] = __halves2bfloat162(h0, h1);
        ((__nv_bfloat162*)ol)[off2] = __halves2bfloat162(l0b, l1b);
    }
}

// ================= mma.sync bf16-split GEMM =================
// C[M,N] = A[M,K] @ B[N,K]^T with A = Ah+Al, B = Bh+Bl.
// CTA tile 128x128, BK=32, 3-stage cp.async pipeline, 8 warps (2x4), warp 64x32.
// MODE 0: C fp32 = acc
// MODE 1: C fp32 = res + scale[n]*acc
// MODE 2: C bf16 hi/lo = relu(acc)^2
#define BM 128
#define BN 128
#define BK 32
#define LDT 40                       // smem row stride (elems), pad 8
#define ROWB (LDT * 2)               // 80 bytes
#define SPLIT_BYTES (BM * ROWB)      // 10240
#define STAGE_BYTES (4 * SPLIT_BYTES)
#define GSTAGES 3
#define GSMEM (GSTAGES * STAGE_BYTES)  // 122880

template <int MODE>
__global__ __launch_bounds__(256, 1) void gemm_mma(
    const __nv_bfloat16* __restrict__ Ah, const __nv_bfloat16* __restrict__ Al,
    const __nv_bfloat16* __restrict__ Bh, const __nv_bfloat16* __restrict__ Bl,
    int K, int Ntot,
    float* __restrict__ Cf,
    const float* __restrict__ res, const float* __restrict__ scale,
    __nv_bfloat16* __restrict__ Chi, __nv_bfloat16* __restrict__ Clo) {
    extern __shared__ char smem[];
    const uint32_t sb = smem_u32(smem);
    const int tid  = threadIdx.x;
    const int lane = tid & 31;
    const int wid  = tid >> 5;
    const int wm   = wid & 1;       // 2 warp rows of 64
    const int wn   = wid >> 1;      // 4 warp cols of 32
    const int m0 = blockIdx.y * BM, n0 = blockIdx.x * BN;

    float acc[4][4][4];
    #pragma unroll
    for (int i = 0; i < 4; i++)
        #pragma unroll
        for (int j = 0; j < 4; j++)
            #pragma unroll
            for (int k = 0; k < 4; k++) acc[i][j][k] = 0.f;

    auto load_stage = [&](int kc, int s) {
        const uint32_t base = sb + s * STAGE_BYTES;
        #pragma unroll
        for (int it = 0; it < 2; it++) {
            const int g = tid + it * 256;      // 512 granules per sub-tile
            const int row = g >> 2, cg = g & 3;
            const uint32_t off = (uint32_t)(row * ROWB + cg * 16);
            const size_t ga = (size_t)(m0 + row) * K + kc + cg * 8;
            const size_t gb = (size_t)(n0 + row) * K + kc + cg * 8;
            cp16(base + off,                   Ah + ga);
            cp16(base + SPLIT_BYTES + off,     Al + ga);
            cp16(base + 2 * SPLIT_BYTES + off, Bh + gb);
            cp16(base + 3 * SPLIT_BYTES + off, Bl + gb);
        }
        asm volatile("cp.async.commit_group;" ::: "memory");
    };

    const int NC = K / BK;
    load_stage(0, 0);
    load_stage(BK, 1);
    asm volatile("cp.async.wait_group 1;" ::: "memory");
    __syncthreads();

    for (int c = 0; c < NC; c++) {
        const uint32_t stb = sb + (c % 3) * STAGE_BYTES;
        if (c + 2 < NC) load_stage((c + 2) * BK, (c + 2) % 3);
        else asm volatile("cp.async.commit_group;" ::: "memory");

        #pragma unroll
        for (int ks = 0; ks < 2; ks++) {
            uint32_t ah[16], al[16], bh[8], bl[8];
            const uint32_t arow = (uint32_t)(wm * 64 + (lane & 15));
            const uint32_t akb  = (uint32_t)(((lane >> 4) * 16) + ks * 32);
            #pragma unroll
            for (int mf = 0; mf < 4; mf++) {
                const uint32_t ad = stb + (arow + mf * 16) * ROWB + akb;
                ldsm_x4(ah + mf * 4, ad);
                ldsm_x4(al + mf * 4, ad + SPLIT_BYTES);
            }
            const uint32_t brow = (uint32_t)(wn * 32 + ((lane >> 4) * 8) + (lane & 7));
            const uint32_t bkb  = (uint32_t)((((lane >> 3) & 1) * 16) + ks * 32);
            #pragma unroll
            for (int p = 0; p < 2; p++) {
                const uint32_t bd = stb + 2 * SPLIT_BYTES + (brow + p * 16) * ROWB + bkb;
                ldsm_x4(bh + p * 4, bd);
                ldsm_x4(bl + p * 4, bd + SPLIT_BYTES);
            }
            #pragma unroll
            for (int mf = 0; mf < 4; mf++)
                #pragma unroll
                for (int nf = 0; nf < 4; nf++) {
                    float* cc = acc[mf][nf];
                    mma16816(cc, ah + mf * 4, bh + nf * 2);
                    mma16816(cc, al + mf * 4, bh + nf * 2);
                    mma16816(cc, ah + mf * 4, bl + nf * 2);
                }
        }
        asm volatile("cp.async.wait_group 1;" ::: "memory");
        __syncthreads();
    }

    // ---- epilogue ----
    const int rb = m0 + wm * 64 + (lane >> 2);
    const int cb = n0 + wn * 32 + (lane & 3) * 2;
    #pragma unroll
    for (int mf = 0; mf < 4; mf++) {
        #pragma unroll
        for (int nf = 0; nf < 4; nf++) {
            const float* cc = acc[mf][nf];
            const int r0 = rb + mf * 16;
            const int r1 = r0 + 8;
            const int cn = cb + nf * 8;
            if (MODE == 0) {
                *(float2*)(Cf + (size_t)r0 * Ntot + cn) = make_float2(cc[0], cc[1]);
                *(float2*)(Cf + (size_t)r1 * Ntot + cn) = make_float2(cc[2], cc[3]);
            } else if (MODE == 1) {
                const float2 sc = *(const float2*)(scale + cn);
                const float2 q0 = *(const float2*)(res + (size_t)r0 * Ntot + cn);
                const float2 q1 = *(const float2*)(res + (size_t)r1 * Ntot + cn);
                *(float2*)(Cf + (size_t)r0 * Ntot + cn) =
                    make_float2(q0.x + sc.x * cc[0], q0.y + sc.y * cc[1]);
                *(float2*)(Cf + (size_t)r1 * Ntot + cn) =
                    make_float2(q1.x + sc.x * cc[2], q1.y + sc.y * cc[3]);
            } else {
                float v0 = fmaxf(cc[0], 0.f), v1 = fmaxf(cc[1], 0.f);
                float v2 = fmaxf(cc[2], 0.f), v3 = fmaxf(cc[3], 0.f);
                v0 *= v0; v1 *= v1; v2 *= v2; v3 *= v3;
                __nv_bfloat16 h0, h1, h2, h3, l0, l1, l2, l3;
                split_bf16(v0, h0, l0); split_bf16(v1, h1, l1);
                split_bf16(v2, h2, l2); split_bf16(v3, h3, l3);
                *(__nv_bfloat162*)(Chi + (size_t)r0 * Ntot + cn) = __halves2bfloat162(h0, h1);
                *(__nv_bfloat162*)(Chi + (size_t)r1 * Ntot + cn) = __halves2bfloat162(h2, h3);
                *(__nv_bfloat162*)(Clo + (size_t)r0 * Ntot + cn) = __halves2bfloat162(l0, l1);
                *(__nv_bfloat162*)(Clo + (size_t)r1 * Ntot + cn) = __halves2bfloat162(l2, l3);
            }
        }
    }
}

// ================= host launcher =================
extern "C" void kernel_launch(void* const* d_in, const int* in_sizes, int n_in,
                              void* d_out, int out_size) {
    const float* x        = (const float*)d_in[0];
    const float* qkv_w    = (const float*)d_in[1];
    const float* o_w      = (const float*)d_in[2];
    const float* o_scale  = (const float*)d_in[3];
    const float* w1       = (const float*)d_in[4];
    const float* w2       = (const float*)d_in[5];
    const float* w2_scale = (const float*)d_in[6];
    float* out = (float*)d_out;

    float *qkv, *qrot, *krot, *x1;
    cudaGetSymbolAddress((void**)&qkv,  g_qkv);
    cudaGetSymbolAddress((void**)&qrot, g_qrot);
    cudaGetSymbolAddress((void**)&krot, g_krot);
    cudaGetSymbolAddress((void**)&x1,   g_x1);
    __nv_bfloat16 *xnh, *xnl, *ath, *atl, *x1nh, *x1nl, *hh, *hl;
    __nv_bfloat16 *wqh, *wql, *woh, *wol, *w1h, *w1l, *w2h, *w2l;
    cudaGetSymbolAddress((void**)&xnh,  g_xnh);  cudaGetSymbolAddress((void**)&xnl,  g_xnl);
    cudaGetSymbolAddress((void**)&ath,  g_ath);  cudaGetSymbolAddress((void**)&atl,  g_atl);
    cudaGetSymbolAddress((void**)&x1nh, g_x1nh); cudaGetSymbolAddress((void**)&x1nl, g_x1nl);
    cudaGetSymbolAddress((void**)&hh,   g_hh);   cudaGetSymbolAddress((void**)&hl,   g_hl);
    cudaGetSymbolAddress((void**)&wqh,  g_wqh);  cudaGetSymbolAddress((void**)&wql,  g_wql);
    cudaGetSymbolAddress((void**)&woh,  g_woh);  cudaGetSymbolAddress((void**)&wol,  g_wol);
    cudaGetSymbolAddress((void**)&w1h,  g_w1h);  cudaGetSymbolAddress((void**)&w1l,  g_w1l);
    cudaGetSymbolAddress((void**)&w2h,  g_w2h);  cudaGetSymbolAddress((void**)&w2l,  g_w2l);

    cudaFuncSetAttribute(gemm_mma<0>, cudaFuncAttributeMaxDynamicSharedMemorySize, GSMEM);
    cudaFuncSetAttribute(gemm_mma<1>, cudaFuncAttributeMaxDynamicSharedMemorySize, GSMEM);
    cudaFuncSetAttribute(gemm_mma<2>, cudaFuncAttributeMaxDynamicSharedMemorySize, GSMEM);

    // weight hi/lo splits
    conv_split<<<(QKV_DIM * DIM / 4 + 255) / 256, 256>>>(qkv_w, wqh, wql, QKV_DIM * DIM / 4);
    conv_split<<<(DIM * DIM / 4 + 255) / 256, 256>>>(o_w, woh, wol, DIM * DIM / 4);
    conv_split<<<(MLP_DIM * DIM / 4 + 255) / 256, 256>>>(w1, w1h, w1l, MLP_DIM * DIM / 4);
    conv_split<<<(DIM * MLP_DIM / 4 + 255) / 256, 256>>>(w2, w2h, w2l, DIM * MLP_DIM / 4);

    // 1. xn = rmsnorm(x) -> bf16 hi/lo
    rmsnorm_bf16<<<T_LEN, 256>>>(x, xnh, xnl);
    // 2. qkv = xn @ qkv_w^T (fp32 out)
    gemm_mma<0><<<dim3(QKV_DIM / BN, T_LEN / BM), 256, GSMEM>>>(
        xnh, xnl, wqh, wql, DIM, QKV_DIM, qkv, nullptr, nullptr, nullptr, nullptr);
    // 3. per-head q/k rmsnorm + rope
    qk_prep<<<dim3(T_LEN, 4), 256>>>(qkv, qrot, krot);
    // 4. sliding-window attention -> bf16 hi/lo
    attn_kernel<<<dim3(T_LEN / 64, NHEADS), 512>>>(qrot, krot, qkv, ath, atl);
    // 5. x1 = x + o_scale[n] * (attn @ o_w^T)
    gemm_mma<1><<<dim3(DIM / BN, T_LEN / BM), 256, GSMEM>>>(
        ath, atl, woh, wol, DIM, DIM, x1, x, o_scale, nullptr, nullptr);
    // 6. x1n = rmsnorm(x1) -> bf16 hi/lo
    rmsnorm_bf16<<<T_LEN, 256>>>(x1, x1nh, x1nl);
    // 7. h = relu(x1n @ w1^T)^2 -> bf16 hi/lo
    gemm_mma<2><<<dim3(MLP_DIM / BN, T_LEN / BM), 256, GSMEM>>>(
        x1nh, x1nl, w1h, w1l, DIM, MLP_DIM, nullptr, nullptr, nullptr, hh, hl);
    // 8. out = x1 + w2_scale[n] * (h @ w2^T)
    gemm_mma<1><<<dim3(DIM / BN, T_LEN / BM), 256, GSMEM>>>(
        hh, hl, w2h, w2l, MLP_DIM, DIM, out, x1, w2_scale, nullptr, nullptr);
}

// round 6
// speedup vs baseline: 2.6805x; 1.3887x over previous
#include <cuda_runtime.h>
#include <cuda_bf16.h>
#include <math_constants.h>
#include <cstdint>

#define T_LEN   4096
#define DIM     1024
#define QKV_DIM 3072
#define MLP_DIM 4096
#define NHEADS  16
#define HD      64
#define WIN     512
#define EPS_F   1.1920929e-07f

// ================= helpers =================
__device__ __forceinline__ uint32_t smem_u32(const void* p) {
    uint32_t a;
    asm("{ .reg .u64 t; cvta.to.shared.u64 t, %1; cvt.u32.u64 %0, t; }" : "=r"(a) : "l"(p));
    return a;
}
__device__ __forceinline__ void cp16(uint32_t s, const void* g) {
    asm volatile("cp.async.cg.shared.global [%0], [%1], 16;" :: "r"(s), "l"(g));
}
__device__ __forceinline__ void ldsm_x4(uint32_t* r, uint32_t addr) {
    asm volatile("ldmatrix.sync.aligned.m8n8.x4.shared.b16 {%0,%1,%2,%3}, [%4];"
                 : "=r"(r[0]), "=r"(r[1]), "=r"(r[2]), "=r"(r[3]) : "r"(addr));
}
__device__ __forceinline__ void ldsm_x4_t(uint32_t* r, uint32_t addr) {
    asm volatile("ldmatrix.sync.aligned.m8n8.x4.trans.shared.b16 {%0,%1,%2,%3}, [%4];"
                 : "=r"(r[0]), "=r"(r[1]), "=r"(r[2]), "=r"(r[3]) : "r"(addr));
}
__device__ __forceinline__ void mma16816(float* c, const uint32_t* a, const uint32_t* b) {
    asm volatile("mma.sync.aligned.m16n8k16.row.col.f32.bf16.bf16.f32 "
        "{%0,%1,%2,%3}, {%4,%5,%6,%7}, {%8,%9}, {%0,%1,%2,%3};"
        : "+f"(c[0]), "+f"(c[1]), "+f"(c[2]), "+f"(c[3])
        : "r"(a[0]), "r"(a[1]), "r"(a[2]), "r"(a[3]), "r"(b[0]), "r"(b[1]));
}
__device__ __forceinline__ void split_bf16(float a, __nv_bfloat16& hi, __nv_bfloat16& lo) {
    hi = __float2bfloat16(a);
    lo = __float2bfloat16(a - __bfloat162float(hi));
}
__device__ __forceinline__ uint32_t pack2(__nv_bfloat16 a, __nv_bfloat16 b) {
    return (uint32_t)__bfloat16_as_ushort(a) | ((uint32_t)__bfloat16_as_ushort(b) << 16);
}
__device__ __forceinline__ uint32_t pack_hi(float a, float b) {
    return pack2(__float2bfloat16(a), __float2bfloat16(b));
}
__device__ __forceinline__ uint32_t pack_lo(float a, float b) {
    __nv_bfloat16 ha = __float2bfloat16(a), hb = __float2bfloat16(b);
    return pack2(__float2bfloat16(a - __bfloat162float(ha)),
                 __float2bfloat16(b - __bfloat162float(hb)));
}

// ================= scratch =================
__device__ float g_qkv [T_LEN * QKV_DIM];
__device__ float g_x1  [T_LEN * DIM];

#define BF16A __device__ __align__(16) __nv_bfloat16
BF16A g_xnh [T_LEN * DIM];     BF16A g_xnl [T_LEN * DIM];
BF16A g_qh  [T_LEN * DIM];     BF16A g_ql  [T_LEN * DIM];
BF16A g_kh  [T_LEN * DIM];     BF16A g_kl  [T_LEN * DIM];
BF16A g_vh  [T_LEN * DIM];     BF16A g_vl  [T_LEN * DIM];
BF16A g_ath [T_LEN * DIM];     BF16A g_atl [T_LEN * DIM];
BF16A g_x1nh[T_LEN * DIM];     BF16A g_x1nl[T_LEN * DIM];
BF16A g_hh  [T_LEN * MLP_DIM]; BF16A g_hl  [T_LEN * MLP_DIM];
BF16A g_wqh [QKV_DIM * DIM];   BF16A g_wql [QKV_DIM * DIM];
BF16A g_woh [DIM * DIM];       BF16A g_wol [DIM * DIM];
BF16A g_w1h [MLP_DIM * DIM];   BF16A g_w1l [MLP_DIM * DIM];
BF16A g_w2h [DIM * MLP_DIM];   BF16A g_w2l [DIM * MLP_DIM];

// ================= weight split =================
__global__ __launch_bounds__(256) void conv_split(const float* __restrict__ w,
                                                  __nv_bfloat16* __restrict__ hi,
                                                  __nv_bfloat16* __restrict__ lo, int n4) {
    const int i = blockIdx.x * 256 + threadIdx.x;
    if (i >= n4) return;
    float4 v = ((const float4*)w)[i];
    ((uint32_t*)hi)[i * 2]     = pack_hi(v.x, v.y);
    ((uint32_t*)hi)[i * 2 + 1] = pack_hi(v.z, v.w);
    ((uint32_t*)lo)[i * 2]     = pack_lo(v.x, v.y);
    ((uint32_t*)lo)[i * 2 + 1] = pack_lo(v.z, v.w);
}

// ================= rmsnorm -> bf16 hi/lo =================
__global__ __launch_bounds__(256) void rmsnorm_bf16(const float* __restrict__ x,
                                                    __nv_bfloat16* __restrict__ yh,
                                                    __nv_bfloat16* __restrict__ yl) {
    __shared__ float red[8];
    const int row = blockIdx.x;
    const int tid = threadIdx.x;
    float4 v = ((const float4*)(x + (size_t)row * DIM))[tid];
    float ss = v.x * v.x + v.y * v.y + v.z * v.z + v.w * v.w;
    #pragma unroll
    for (int off = 16; off; off >>= 1) ss += __shfl_xor_sync(0xffffffffu, ss, off);
    if ((tid & 31) == 0) red[tid >> 5] = ss;
    __syncthreads();
    float tot = 0.f;
    #pragma unroll
    for (int i = 0; i < 8; i++) tot += red[i];
    const float r = rsqrtf(tot * (1.0f / DIM) + EPS_F);
    const size_t base2 = (size_t)row * (DIM / 2) + tid * 2;
    ((uint32_t*)yh)[base2]     = pack_hi(v.x * r, v.y * r);
    ((uint32_t*)yh)[base2 + 1] = pack_hi(v.z * r, v.w * r);
    ((uint32_t*)yl)[base2]     = pack_lo(v.x * r, v.y * r);
    ((uint32_t*)yl)[base2 + 1] = pack_lo(v.z * r, v.w * r);
}

// ================= per-head q/k rmsnorm + rope; v split -> bf16 hi/lo =================
__global__ __launch_bounds__(256) void qk_prep(const float* __restrict__ qkv,
                                               __nv_bfloat16* __restrict__ qh, __nv_bfloat16* __restrict__ ql,
                                               __nv_bfloat16* __restrict__ kh, __nv_bfloat16* __restrict__ kl,
                                               __nv_bfloat16* __restrict__ vh, __nv_bfloat16* __restrict__ vl) {
    const int t    = blockIdx.x;
    const int idx  = blockIdx.y * 8 + (threadIdx.x >> 5);
    const int lane = threadIdx.x & 31;
    const int head = idx & 15;
    const size_t dsto = (size_t)t * DIM + head * HD;
    __nv_bfloat16 *dh, *dl;
    const float* src;
    if (idx < 16) {
        src = qkv + (size_t)t * QKV_DIM + head * HD;
        dh = qh + dsto; dl = ql + dsto;
    } else if (idx < 32) {
        src = qkv + (size_t)t * QKV_DIM + DIM + head * HD;
        dh = kh + dsto; dl = kl + dsto;
    } else {
        src = qkv + (size_t)t * QKV_DIM + 2 * DIM + head * HD;
        dh = vh + dsto; dl = vl + dsto;
    }
    float a = src[lane];
    float b = src[lane + 32];
    if (idx < 32) {
        float ss = a * a + b * b;
        #pragma unroll
        for (int off = 16; off; off >>= 1) ss += __shfl_xor_sync(0xffffffffu, ss, off);
        const float r = rsqrtf(ss * (1.0f / HD) + EPS_F);
        a *= r; b *= r;
        float sn = 0.f, cs = 1.f;
        if (lane < 16) {
            const float f = powf(1e-4f, (float)lane * (1.0f / 15.0f));
            sincosf((float)t * f, &sn, &cs);
        }
        const float y1 =  a * cs + b * sn;
        const float y2 = -a * sn + b * cs;
        a = y1; b = y2;
    }
    __nv_bfloat16 ha, la, hb, lb;
    split_bf16(a, ha, la);
    split_bf16(b, hb, lb);
    dh[lane] = ha;      dl[lane] = la;
    dh[lane + 32] = hb; dl[lane + 32] = lb;
}

// ================= tensor-core sliding-window attention =================
// grid (T/64, NHEADS), 128 threads (4 warps). Warp w: query rows q0+16w..+15.
// Key chunks of 64, double-buffered cp.async. Valid: q-512 < k <= q.
#define KVS_B 144                       // 72 bf16 row stride
#define KVSPLIT 9216                    // 64 rows * 144B
#define ABUF (2 * KVSPLIT)              // Q hi/lo region
#define KVBUF (4 * KVSPLIT)             // K hi/lo + V hi/lo per buffer
#define ATTN_SMEM (ABUF + 2 * KVBUF)    // 92160

__global__ __launch_bounds__(128) void attn_mma(
    const __nv_bfloat16* __restrict__ qh, const __nv_bfloat16* __restrict__ ql,
    const __nv_bfloat16* __restrict__ kh, const __nv_bfloat16* __restrict__ kl,
    const __nv_bfloat16* __restrict__ vh, const __nv_bfloat16* __restrict__ vl,
    __nv_bfloat16* __restrict__ oh, __nv_bfloat16* __restrict__ ol) {
    extern __shared__ char smem[];
    const uint32_t sb = smem_u32(smem);
    const int h    = blockIdx.y;
    const int q0   = blockIdx.x * 64;
    const int tid  = threadIdx.x;
    const int wid  = tid >> 5;
    const int lane = tid & 31;

    // ---- load Q block (64 x 64, hi/lo) ----
    #pragma unroll
    for (int it = 0; it < 4; it++) {
        const int g = tid + it * 128;            // 512 granules
        const int row = g >> 3, cg = g & 7;
        const size_t src = (size_t)(q0 + row) * DIM + h * HD + cg * 8;
        const uint32_t off = (uint32_t)(row * KVS_B + cg * 16);
        cp16(sb + off, qh + src);
        cp16(sb + KVSPLIT + off, ql + src);
    }
    asm volatile("cp.async.commit_group;" ::: "memory");

    auto load_kv = [&](int kc, int buf) {
        const uint32_t base = sb + ABUF + buf * KVBUF;
        #pragma unroll
        for (int it = 0; it < 4; it++) {
            const int g = tid + it * 128;
            const int row = g >> 3, cg = g & 7;
            const size_t src = (size_t)(kc + row) * DIM + h * HD + cg * 8;
            const uint32_t off = (uint32_t)(row * KVS_B + cg * 16);
            cp16(base + off, kh + src);
            cp16(base + KVSPLIT + off, kl + src);
            cp16(base + 2 * KVSPLIT + off, vh + src);
            cp16(base + 3 * KVSPLIT + off, vl + src);
        }
        asm volatile("cp.async.commit_group;" ::: "memory");
    };

    const int kc0 = (q0 >= WIN) ? (q0 - WIN) : 0;
    const int nch = (q0 + 64 - kc0) >> 6;
    load_kv(kc0, 0);

    // wait for Q (<=1 pending), sync, load Q fragments
    asm volatile("cp.async.wait_group 1;" ::: "memory");
    __syncthreads();
    uint32_t qfh[16], qfl[16];
    #pragma unroll
    for (int ks = 0; ks < 4; ks++) {
        const uint32_t ad = sb + (uint32_t)((wid * 16 + (lane & 15)) * KVS_B)
                          + ((lane >> 4) * 16) + ks * 32;
        ldsm_x4(qfh + ks * 4, ad);
        ldsm_x4(qfl + ks * 4, ad + KVSPLIT);
    }

    float m[2] = {-1e30f, -1e30f}, lsum[2] = {0.f, 0.f};
    float o[8][4];
    #pragma unroll
    for (int i = 0; i < 8; i++)
        #pragma unroll
        for (int j = 0; j < 4; j++) o[i][j] = 0.f;

    const int r0 = lane >> 2;
    const int qrow0 = q0 + wid * 16 + r0;       // row for c[0],c[1]
    const int qrow1 = qrow0 + 8;                // row for c[2],c[3]
    const int colb = (lane & 3) * 2;

    for (int c = 0; c < nch; c++) {
        const int b = c & 1;
        const int kc = kc0 + c * 64;
        if (c + 1 < nch) load_kv(kc + 64, b ^ 1);
        if (c + 1 < nch) { asm volatile("cp.async.wait_group 1;" ::: "memory"); }
        else             { asm volatile("cp.async.wait_group 0;" ::: "memory"); }
        __syncthreads();

        const uint32_t Kb = sb + ABUF + b * KVBUF;
        const uint32_t Vb = Kb + 2 * KVSPLIT;

        // ---- scores: S = Q K^T ----
        float sc[8][4];
        #pragma unroll
        for (int i = 0; i < 8; i++)
            #pragma unroll
            for (int j = 0; j < 4; j++) sc[i][j] = 0.f;
        #pragma unroll
        for (int ks = 0; ks < 4; ks++) {
            #pragma unroll
            for (int np = 0; np < 4; np++) {
                uint32_t bh4[4], bl4[4];
                const uint32_t bd = Kb
                    + (uint32_t)((np * 16 + ((lane >> 4) * 8) + (lane & 7)) * KVS_B)
                    + (((lane >> 3) & 1) * 16) + ks * 32;
                ldsm_x4(bh4, bd);
                ldsm_x4(bl4, bd + KVSPLIT);
                float* c0 = sc[np * 2];
                float* c1 = sc[np * 2 + 1];
                mma16816(c0, qfh + ks * 4, bh4);
                mma16816(c0, qfl + ks * 4, bh4);
                mma16816(c0, qfh + ks * 4, bl4);
                mma16816(c1, qfh + ks * 4, bh4 + 2);
                mma16816(c1, qfl + ks * 4, bh4 + 2);
                mma16816(c1, qfh + ks * 4, bl4 + 2);
            }
        }

        // ---- mask + scale ----
        #pragma unroll
        for (int nf = 0; nf < 8; nf++) {
            #pragma unroll
            for (int j = 0; j < 4; j++) {
                const int kg = kc + nf * 8 + colb + (j & 1);
                const int q  = (j < 2) ? qrow0 : qrow1;
                const bool valid = (kg <= q) && (kg > q - WIN);
                sc[nf][j] = valid ? sc[nf][j] * 0.125f : -1e30f;
            }
        }
        // ---- online softmax ----
        float mx0 = -1e30f, mx1 = -1e30f;
        #pragma unroll
        for (int nf = 0; nf < 8; nf++) {
            mx0 = fmaxf(mx0, fmaxf(sc[nf][0], sc[nf][1]));
            mx1 = fmaxf(mx1, fmaxf(sc[nf][2], sc[nf][3]));
        }
        #pragma unroll
        for (int off = 1; off <= 2; off <<= 1) {
            mx0 = fmaxf(mx0, __shfl_xor_sync(0xffffffffu, mx0, off));
            mx1 = fmaxf(mx1, __shfl_xor_sync(0xffffffffu, mx1, off));
        }
        const float mn0 = fmaxf(m[0], mx0);
        const float mn1 = fmaxf(m[1], mx1);
        const float cr0 = __expf(m[0] - mn0);
        const float cr1 = __expf(m[1] - mn1);
        m[0] = mn0; m[1] = mn1;
        float sm0 = 0.f, sm1 = 0.f;
        #pragma unroll
        for (int nf = 0; nf < 8; nf++) {
            sc[nf][0] = __expf(sc[nf][0] - mn0);
            sc[nf][1] = __expf(sc[nf][1] - mn0);
            sc[nf][2] = __expf(sc[nf][2] - mn1);
            sc[nf][3] = __expf(sc[nf][3] - mn1);
            sm0 += sc[nf][0] + sc[nf][1];
            sm1 += sc[nf][2] + sc[nf][3];
        }
        #pragma unroll
        for (int off = 1; off <= 2; off <<= 1) {
            sm0 += __shfl_xor_sync(0xffffffffu, sm0, off);
            sm1 += __shfl_xor_sync(0xffffffffu, sm1, off);
        }
        lsum[0] = lsum[0] * cr0 + sm0;
        lsum[1] = lsum[1] * cr1 + sm1;
        #pragma unroll
        for (int nf = 0; nf < 8; nf++) {
            o[nf][0] *= cr0; o[nf][1] *= cr0;
            o[nf][2] *= cr1; o[nf][3] *= cr1;
        }

        // ---- O += P V ----
        #pragma unroll
        for (int ks = 0; ks < 4; ks++) {          // 16 keys per step
            uint32_t ah4[4], al4[4];
            const float* p0 = sc[ks * 2];
            const float* p1 = sc[ks * 2 + 1];
            ah4[0] = pack_hi(p0[0], p0[1]);  al4[0] = pack_lo(p0[0], p0[1]);
            ah4[1] = pack_hi(p0[2], p0[3]);  al4[1] = pack_lo(p0[2], p0[3]);
            ah4[2] = pack_hi(p1[0], p1[1]);  al4[2] = pack_lo(p1[0], p1[1]);
            ah4[3] = pack_hi(p1[2], p1[3]);  al4[3] = pack_lo(p1[2], p1[3]);
            #pragma unroll
            for (int dg = 0; dg < 4; dg++) {      // 16 dims per step
                uint32_t vh4[4], vl4[4];
                const uint32_t vd = Vb
                    + (uint32_t)((ks * 16 + (lane & 7) + ((lane >> 3) & 1) * 8) * KVS_B)
                    + dg * 32 + (((lane >> 4) & 1) * 16);
                ldsm_x4_t(vh4, vd);
                ldsm_x4_t(vl4, vd + KVSPLIT);
                float* c0 = o[dg * 2];
                float* c1 = o[dg * 2 + 1];
                mma16816(c0, ah4, vh4);
                mma16816(c0, al4, vh4);
                mma16816(c0, ah4, vl4);
                mma16816(c1, ah4, vh4 + 2);
                mma16816(c1, al4, vh4 + 2);
                mma16816(c1, ah4, vl4 + 2);
            }
        }
        __syncthreads();
    }

    // ---- epilogue ----
    const float inv0 = 1.0f / lsum[0];
    const float inv1 = 1.0f / lsum[1];
    #pragma unroll
    for (int nf = 0; nf < 8; nf++) {
        const int col = h * HD + nf * 8 + colb;
        const float v0 = o[nf][0] * inv0, v1 = o[nf][1] * inv0;
        const float v2 = o[nf][2] * inv1, v3 = o[nf][3] * inv1;
        *(uint32_t*)(oh + (size_t)qrow0 * DIM + col) = pack_hi(v0, v1);
        *(uint32_t*)(ol + (size_t)qrow0 * DIM + col) = pack_lo(v0, v1);
        *(uint32_t*)(oh + (size_t)qrow1 * DIM + col) = pack_hi(v2, v3);
        *(uint32_t*)(ol + (size_t)qrow1 * DIM + col) = pack_lo(v2, v3);
    }
}

// ================= mma.sync bf16-split GEMM (CTA 128x256, warp 64x64) =================
#define BM 128
#define BN 256
#define BK 32
#define LDT 40
#define ROWB (LDT * 2)                   // 80 bytes
#define A_SPLIT (BM * ROWB)              // 10240
#define B_SPLIT (BN * ROWB)              // 20480
#define STAGE_BYTES (2 * A_SPLIT + 2 * B_SPLIT)   // 61440
#define GSTAGES 3
#define GSMEM (GSTAGES * STAGE_BYTES)    // 184320

template <int MODE>
__global__ __launch_bounds__(256, 1) void gemm_mma(
    const __nv_bfloat16* __restrict__ Ah, const __nv_bfloat16* __restrict__ Al,
    const __nv_bfloat16* __restrict__ Bh, const __nv_bfloat16* __restrict__ Bl,
    int K, int Ntot,
    float* __restrict__ Cf,
    const float* __restrict__ res, const float* __restrict__ scale,
    __nv_bfloat16* __restrict__ Chi, __nv_bfloat16* __restrict__ Clo) {
    extern __shared__ char smem[];
    const uint32_t sb = smem_u32(smem);
    const int tid  = threadIdx.x;
    const int lane = tid & 31;
    const int wid  = tid >> 5;
    const int wm   = wid & 1;        // 2 warp rows of 64
    const int wn   = wid >> 1;       // 4 warp cols of 64
    const int m0 = blockIdx.y * BM, n0 = blockIdx.x * BN;

    float acc[4][8][4];
    #pragma unroll
    for (int i = 0; i < 4; i++)
        #pragma unroll
        for (int j = 0; j < 8; j++)
            #pragma unroll
            for (int k = 0; k < 4; k++) acc[i][j][k] = 0.f;

    auto load_stage = [&](int kc, int s) {
        const uint32_t base = sb + s * STAGE_BYTES;
        #pragma unroll
        for (int it = 0; it < 2; it++) {           // A: 512 granules/split
            const int g = tid + it * 256;
            const int row = g >> 2, cg = g & 3;
            const uint32_t off = (uint32_t)(row * ROWB + cg * 16);
            const size_t ga = (size_t)(m0 + row) * K + kc + cg * 8;
            cp16(base + off, Ah + ga);
            cp16(base + A_SPLIT + off, Al + ga);
        }
        #pragma unroll
        for (int it = 0; it < 4; it++) {           // B: 1024 granules/split
            const int g = tid + it * 256;
            const int row = g >> 2, cg = g & 3;
            const uint32_t off = (uint32_t)(row * ROWB + cg * 16);
            const size_t gb = (size_t)(n0 + row) * K + kc + cg * 8;
            cp16(base + 2 * A_SPLIT + off, Bh + gb);
            cp16(base + 2 * A_SPLIT + B_SPLIT + off, Bl + gb);
        }
        asm volatile("cp.async.commit_group;" ::: "memory");
    };

    const int NC = K / BK;
    load_stage(0, 0);
    load_stage(BK, 1);
    asm volatile("cp.async.wait_group 1;" ::: "memory");
    __syncthreads();

    for (int c = 0; c < NC; c++) {
        const uint32_t stb = sb + (c % 3) * STAGE_BYTES;
        if (c + 2 < NC) load_stage((c + 2) * BK, (c + 2) % 3);
        else asm volatile("cp.async.commit_group;" ::: "memory");

        #pragma unroll
        for (int ks = 0; ks < 2; ks++) {
            uint32_t ah[16], al[16];
            #pragma unroll
            for (int mf = 0; mf < 4; mf++) {
                const uint32_t ad = stb
                    + (uint32_t)((wm * 64 + mf * 16 + (lane & 15)) * ROWB)
                    + ((lane >> 4) * 16) + ks * 32;
                ldsm_x4(ah + mf * 4, ad);
                ldsm_x4(al + mf * 4, ad + A_SPLIT);
            }
            #pragma unroll
            for (int np = 0; np < 4; np++) {
                uint32_t bh4[4], bl4[4];
                const uint32_t bd = stb + 2 * A_SPLIT
                    + (uint32_t)((wn * 64 + np * 16 + ((lane >> 4) * 8) + (lane & 7)) * ROWB)
                    + (((lane >> 3) & 1) * 16) + ks * 32;
                ldsm_x4(bh4, bd);
                ldsm_x4(bl4, bd + B_SPLIT);
                #pragma unroll
                for (int mf = 0; mf < 4; mf++) {
                    float* c0 = acc[mf][np * 2];
                    float* c1 = acc[mf][np * 2 + 1];
                    mma16816(c0, ah + mf * 4, bh4);
                    mma16816(c0, al + mf * 4, bh4);
                    mma16816(c0, ah + mf * 4, bl4);
                    mma16816(c1, ah + mf * 4, bh4 + 2);
                    mma16816(c1, al + mf * 4, bh4 + 2);
                    mma16816(c1, ah + mf * 4, bl4 + 2);
                }
            }
        }
        asm volatile("cp.async.wait_group 1;" ::: "memory");
        __syncthreads();
    }

    // ---- epilogue ----
    const int rb = m0 + wm * 64 + (lane >> 2);
    const int cb = n0 + wn * 64 + (lane & 3) * 2;
    #pragma unroll
    for (int mf = 0; mf < 4; mf++) {
        #pragma unroll
        for (int nf = 0; nf < 8; nf++) {
            const float* cc = acc[mf][nf];
            const int rr0 = rb + mf * 16;
            const int rr1 = rr0 + 8;
            const int cn = cb + nf * 8;
            if (MODE == 0) {
                *(float2*)(Cf + (size_t)rr0 * Ntot + cn) = make_float2(cc[0], cc[1]);
                *(float2*)(Cf + (size_t)rr1 * Ntot + cn) = make_float2(cc[2], cc[3]);
            } else if (MODE == 1) {
                const float2 sc2 = *(const float2*)(scale + cn);
                const float2 q0 = *(const float2*)(res + (size_t)rr0 * Ntot + cn);
                const float2 q1 = *(const float2*)(res + (size_t)rr1 * Ntot + cn);
                *(float2*)(Cf + (size_t)rr0 * Ntot + cn) =
                    make_float2(q0.x + sc2.x * cc[0], q0.y + sc2.y * cc[1]);
                *(float2*)(Cf + (size_t)rr1 * Ntot + cn) =
                    make_float2(q1.x + sc2.x * cc[2], q1.y + sc2.y * cc[3]);
            } else {
                float v0 = fmaxf(cc[0], 0.f), v1 = fmaxf(cc[1], 0.f);
                float v2 = fmaxf(cc[2], 0.f), v3 = fmaxf(cc[3], 0.f);
                v0 *= v0; v1 *= v1; v2 *= v2; v3 *= v3;
                *(uint32_t*)(Chi + (size_t)rr0 * Ntot + cn) = pack_hi(v0, v1);
                *(uint32_t*)(Clo + (size_t)rr0 * Ntot + cn) = pack_lo(v0, v1);
                *(uint32_t*)(Chi + (size_t)rr1 * Ntot + cn) = pack_hi(v2, v3);
                *(uint32_t*)(Clo + (size_t)rr1 * Ntot + cn) = pack_lo(v2, v3);
            }
        }
    }
}

// ================= host launcher =================
extern "C" void kernel_launch(void* const* d_in, const int* in_sizes, int n_in,
                              void* d_out, int out_size) {
    const float* x        = (const float*)d_in[0];
    const float* qkv_w    = (const float*)d_in[1];
    const float* o_w      = (const float*)d_in[2];
    const float* o_scale  = (const float*)d_in[3];
    const float* w1       = (const float*)d_in[4];
    const float* w2       = (const float*)d_in[5];
    const float* w2_scale = (const float*)d_in[6];
    float* out = (float*)d_out;

    float *qkv, *x1;
    cudaGetSymbolAddress((void**)&qkv, g_qkv);
    cudaGetSymbolAddress((void**)&x1,  g_x1);
    __nv_bfloat16 *xnh, *xnl, *qh, *ql, *kh, *kl, *vh, *vl, *ath, *atl, *x1nh, *x1nl, *hh, *hl;
    __nv_bfloat16 *wqh, *wql, *woh, *wol, *w1h, *w1l, *w2h, *w2l;
    cudaGetSymbolAddress((void**)&xnh,  g_xnh);  cudaGetSymbolAddress((void**)&xnl,  g_xnl);
    cudaGetSymbolAddress((void**)&qh,   g_qh);   cudaGetSymbolAddress((void**)&ql,   g_ql);
    cudaGetSymbolAddress((void**)&kh,   g_kh);   cudaGetSymbolAddress((void**)&kl,   g_kl);
    cudaGetSymbolAddress((void**)&vh,   g_vh);   cudaGetSymbolAddress((void**)&vl,   g_vl);
    cudaGetSymbolAddress((void**)&ath,  g_ath);  cudaGetSymbolAddress((void**)&atl,  g_atl);
    cudaGetSymbolAddress((void**)&x1nh, g_x1nh); cudaGetSymbolAddress((void**)&x1nl, g_x1nl);
    cudaGetSymbolAddress((void**)&hh,   g_hh);   cudaGetSymbolAddress((void**)&hl,   g_hl);
    cudaGetSymbolAddress((void**)&wqh,  g_wqh);  cudaGetSymbolAddress((void**)&wql,  g_wql);
    cudaGetSymbolAddress((void**)&woh,  g_woh);  cudaGetSymbolAddress((void**)&wol,  g_wol);
    cudaGetSymbolAddress((void**)&w1h,  g_w1h);  cudaGetSymbolAddress((void**)&w1l,  g_w1l);
    cudaGetSymbolAddress((void**)&w2h,  g_w2h);  cudaGetSymbolAddress((void**)&w2l,  g_w2l);

    cudaFuncSetAttribute(gemm_mma<0>, cudaFuncAttributeMaxDynamicSharedMemorySize, GSMEM);
    cudaFuncSetAttribute(gemm_mma<1>, cudaFuncAttributeMaxDynamicSharedMemorySize, GSMEM);
    cudaFuncSetAttribute(gemm_mma<2>, cudaFuncAttributeMaxDynamicSharedMemorySize, GSMEM);
    cudaFuncSetAttribute(attn_mma, cudaFuncAttributeMaxDynamicSharedMemorySize, ATTN_SMEM);

    // weight hi/lo splits
    conv_split<<<(QKV_DIM * DIM / 4 + 255) / 256, 256>>>(qkv_w, wqh, wql, QKV_DIM * DIM / 4);
    conv_split<<<(DIM * DIM / 4 + 255) / 256, 256>>>(o_w, woh, wol, DIM * DIM / 4);
    conv_split<<<(MLP_DIM * DIM / 4 + 255) / 256, 256>>>(w1, w1h, w1l, MLP_DIM * DIM / 4);
    conv_split<<<(DIM * MLP_DIM / 4 + 255) / 256, 256>>>(w2, w2h, w2l, DIM * MLP_DIM / 4);

    // 1. xn = rmsnorm(x)
    rmsnorm_bf16<<<T_LEN, 256>>>(x, xnh, xnl);
    // 2. qkv = xn @ qkv_w^T
    gemm_mma<0><<<dim3(QKV_DIM / BN, T_LEN / BM), 256, GSMEM>>>(
        xnh, xnl, wqh, wql, DIM, QKV_DIM, qkv, nullptr, nullptr, nullptr, nullptr);
    // 3. q/k norm+rope, v split -> bf16 hi/lo
    qk_prep<<<dim3(T_LEN, 6), 256>>>(qkv, qh, ql, kh, kl, vh, vl);
    // 4. attention (tensor cores)
    attn_mma<<<dim3(T_LEN / 64, NHEADS), 128, ATTN_SMEM>>>(qh, ql, kh, kl, vh, vl, ath, atl);
    // 5. x1 = x + o_scale[n] * (attn @ o_w^T)
    gemm_mma<1><<<dim3(DIM / BN, T_LEN / BM), 256, GSMEM>>>(
        ath, atl, woh, wol, DIM, DIM, x1, x, o_scale, nullptr, nullptr);
    // 6. x1n = rmsnorm(x1)
    rmsnorm_bf16<<<T_LEN, 256>>>(x1, x1nh, x1nl);
    // 7. h = relu(x1n @ w1^T)^2
    gemm_mma<2><<<dim3(MLP_DIM / BN, T_LEN / BM), 256, GSMEM>>>(
        x1nh, x1nl, w1h, w1l, DIM, MLP_DIM, nullptr, nullptr, nullptr, hh, hl);
    // 8. out = x1 + w2_scale[n] * (h @ w2^T)
    gemm_mma<1><<<dim3(DIM / BN, T_LEN / BM), 256, GSMEM>>>(
        hh, hl, w2h, w2l, MLP_DIM, DIM, out, x1, w2_scale, nullptr, nullptr);
}

// round 7
// speedup vs baseline: 3.7072x; 1.3830x over previous
#include <cuda_runtime.h>
#include <cuda_bf16.h>
#include <math_constants.h>
#include <cstdint>

#define T_LEN   4096
#define DIM     1024
#define QKV_DIM 3072
#define MLP_DIM 4096
#define NHEADS  16
#define HD      64
#define WIN     512
#define EPS_F   1.1920929e-07f
#define QMAX    16256.0f            // 127*128

// ================= helpers =================
__device__ __forceinline__ uint32_t smem_u32(const void* p) {
    uint32_t a;
    asm("{ .reg .u64 t; cvta.to.shared.u64 t, %1; cvt.u32.u64 %0, t; }" : "=r"(a) : "l"(p));
    return a;
}
__device__ __forceinline__ void cp16(uint32_t s, const void* g) {
    asm volatile("cp.async.cg.shared.global [%0], [%1], 16;" :: "r"(s), "l"(g));
}
__device__ __forceinline__ void ldsm_x4(uint32_t* r, uint32_t addr) {
    asm volatile("ldmatrix.sync.aligned.m8n8.x4.shared.b16 {%0,%1,%2,%3}, [%4];"
                 : "=r"(r[0]), "=r"(r[1]), "=r"(r[2]), "=r"(r[3]) : "r"(addr));
}
__device__ __forceinline__ void ldsm_x4_t(uint32_t* r, uint32_t addr) {
    asm volatile("ldmatrix.sync.aligned.m8n8.x4.trans.shared.b16 {%0,%1,%2,%3}, [%4];"
                 : "=r"(r[0]), "=r"(r[1]), "=r"(r[2]), "=r"(r[3]) : "r"(addr));
}
__device__ __forceinline__ void mma16816(float* c, const uint32_t* a, const uint32_t* b) {
    asm volatile("mma.sync.aligned.m16n8k16.row.col.f32.bf16.bf16.f32 "
        "{%0,%1,%2,%3}, {%4,%5,%6,%7}, {%8,%9}, {%0,%1,%2,%3};"
        : "+f"(c[0]), "+f"(c[1]), "+f"(c[2]), "+f"(c[3])
        : "r"(a[0]), "r"(a[1]), "r"(a[2]), "r"(a[3]), "r"(b[0]), "r"(b[1]));
}
__device__ __forceinline__ void imma16832(int* c, const uint32_t* a, const uint32_t* b) {
    asm volatile("mma.sync.aligned.m16n8k32.row.col.s32.s8.s8.s32 "
        "{%0,%1,%2,%3}, {%4,%5,%6,%7}, {%8,%9}, {%0,%1,%2,%3};"
        : "+r"(c[0]), "+r"(c[1]), "+r"(c[2]), "+r"(c[3])
        : "r"(a[0]), "r"(a[1]), "r"(a[2]), "r"(a[3]), "r"(b[0]), "r"(b[1]));
}
__device__ __forceinline__ void split_bf16(float a, __nv_bfloat16& hi, __nv_bfloat16& lo) {
    hi = __float2bfloat16(a);
    lo = __float2bfloat16(a - __bfloat162float(hi));
}
__device__ __forceinline__ uint32_t pack2(__nv_bfloat16 a, __nv_bfloat16 b) {
    return (uint32_t)__bfloat16_as_ushort(a) | ((uint32_t)__bfloat16_as_ushort(b) << 16);
}
__device__ __forceinline__ uint32_t pack_hi(float a, float b) {
    return pack2(__float2bfloat16(a), __float2bfloat16(b));
}
__device__ __forceinline__ uint32_t pack_lo(float a, float b) {
    __nv_bfloat16 ha = __float2bfloat16(a), hb = __float2bfloat16(b);
    return pack2(__float2bfloat16(a - __bfloat162float(ha)),
                 __float2bfloat16(b - __bfloat162float(hb)));
}

// ================= scratch =================
__device__ float g_qkv [T_LEN * QKV_DIM];
__device__ float g_x1  [T_LEN * DIM];
__device__ float g_attn[T_LEN * DIM];
__device__ float g_hf  [T_LEN * MLP_DIM];
__device__ float2 g_rope[T_LEN * 16];

#define BF16A __device__ __align__(16) __nv_bfloat16
BF16A g_qh[T_LEN * DIM]; BF16A g_ql[T_LEN * DIM];
BF16A g_kh[T_LEN * DIM]; BF16A g_kl[T_LEN * DIM];
BF16A g_vh[T_LEN * DIM]; BF16A g_vl[T_LEN * DIM];

#define I8A __device__ __align__(16) int8_t
I8A g_xq_h [T_LEN * DIM];     I8A g_xq_l [T_LEN * DIM];     __device__ float g_sx [T_LEN];
I8A g_aq_h [T_LEN * DIM];     I8A g_aq_l [T_LEN * DIM];     __device__ float g_sa [T_LEN];
I8A g_x1q_h[T_LEN * DIM];     I8A g_x1q_l[T_LEN * DIM];     __device__ float g_sx1[T_LEN];
I8A g_hq_h [T_LEN * MLP_DIM]; I8A g_hq_l [T_LEN * MLP_DIM]; __device__ float g_sh [T_LEN];
I8A g_wq_h [QKV_DIM * DIM];   I8A g_wq_l [QKV_DIM * DIM];   __device__ float g_swq[QKV_DIM];
I8A g_wo_h [DIM * DIM];       I8A g_wo_l [DIM * DIM];       __device__ float g_swo[DIM];
I8A g_w1_h [MLP_DIM * DIM];   I8A g_w1_l [MLP_DIM * DIM];   __device__ float g_sw1[MLP_DIM];
I8A g_w2_h [DIM * MLP_DIM];   I8A g_w2_l [DIM * MLP_DIM];   __device__ float g_sw2[DIM];

// ================= row quantization (block = one row, 256 threads) =================
__device__ __forceinline__ float block_max256(float v, float* red) {
    #pragma unroll
    for (int off = 16; off; off >>= 1) v = fmaxf(v, __shfl_xor_sync(0xffffffffu, v, off));
    if ((threadIdx.x & 31) == 0) red[threadIdx.x >> 5] = v;
    __syncthreads();
    float m = red[0];
    #pragma unroll
    for (int i = 1; i < 8; i++) m = fmaxf(m, red[i]);
    return m;
}
__device__ __forceinline__ void quant4(float4 v, float inv128, float s128, float invS,
                                       char4& qh, char4& ql) {
    float h0 = rintf(v.x * inv128), h1 = rintf(v.y * inv128);
    float h2 = rintf(v.z * inv128), h3 = rintf(v.w * inv128);
    qh = make_char4((signed char)__float2int_rn(h0), (signed char)__float2int_rn(h1),
                    (signed char)__float2int_rn(h2), (signed char)__float2int_rn(h3));
    ql = make_char4((signed char)__float2int_rn((v.x - h0 * s128) * invS),
                    (signed char)__float2int_rn((v.y - h1 * s128) * invS),
                    (signed char)__float2int_rn((v.z - h2 * s128) * invS),
                    (signed char)__float2int_rn((v.w - h3 * s128) * invS));
}

__device__ __forceinline__ void quant_row_body(const float* __restrict__ src, int ncols,
                                               int8_t* __restrict__ qh, int8_t* __restrict__ ql,
                                               float* __restrict__ Srow, int row) {
    __shared__ float red[8];
    const float* r = src + (size_t)row * ncols;
    const int tid = threadIdx.x;
    const int n4 = ncols >> 2;
    float amax = 0.f;
    for (int i = tid; i < n4; i += 256) {
        float4 v = ((const float4*)r)[i];
        amax = fmaxf(amax, fmaxf(fmaxf(fabsf(v.x), fabsf(v.y)), fmaxf(fabsf(v.z), fabsf(v.w))));
    }
    const float m = block_max256(amax, red);
    const float S = fmaxf(m, 1e-20f) * (1.0f / QMAX);
    const float inv128 = 1.0f / (128.0f * S), s128 = 128.0f * S, invS = 1.0f / S;
    for (int i = tid; i < n4; i += 256) {
        float4 v = ((const float4*)r)[i];
        char4 h4, l4;
        quant4(v, inv128, s128, invS, h4, l4);
        ((char4*)(qh + (size_t)row * ncols))[i] = h4;
        ((char4*)(ql + (size_t)row * ncols))[i] = l4;
    }
    if (tid == 0) Srow[row] = S;
}

__global__ __launch_bounds__(256) void quant_rows(const float* __restrict__ src, int ncols,
                                                  int8_t* __restrict__ qh, int8_t* __restrict__ ql,
                                                  float* __restrict__ S) {
    quant_row_body(src, ncols, qh, ql, S, blockIdx.x);
}

// all 4 weight tensors in one launch (rows: qkv 3072 | o 1024 | w1 4096 | w2 1024)
__global__ __launch_bounds__(256) void quant_weights(
    const float* qkv_w, const float* o_w, const float* w1, const float* w2,
    int8_t* wqh, int8_t* wql, float* swq,
    int8_t* woh, int8_t* wol, float* swo,
    int8_t* w1h, int8_t* w1l, float* sw1,
    int8_t* w2h, int8_t* w2l, float* sw2) {
    int r = blockIdx.x;
    if (r < 3072)       quant_row_body(qkv_w, 1024, wqh, wql, swq, r);
    else if (r < 4096)  quant_row_body(o_w,   1024, woh, wol, swo, r - 3072);
    else if (r < 8192)  quant_row_body(w1,    1024, w1h, w1l, sw1, r - 4096);
    else                quant_row_body(w2,    4096, w2h, w2l, sw2, r - 8192);
}

// ================= rmsnorm -> int8 two-digit =================
__global__ __launch_bounds__(256) void rmsnorm_quant(const float* __restrict__ x,
                                                     int8_t* __restrict__ qh,
                                                     int8_t* __restrict__ ql,
                                                     float* __restrict__ S) {
    __shared__ float red[8], redm[8];
    const int row = blockIdx.x;
    const int tid = threadIdx.x;
    float4 v = ((const float4*)(x + (size_t)row * DIM))[tid];
    float ss = v.x * v.x + v.y * v.y + v.z * v.z + v.w * v.w;
    float am = fmaxf(fmaxf(fabsf(v.x), fabsf(v.y)), fmaxf(fabsf(v.z), fabsf(v.w)));
    #pragma unroll
    for (int off = 16; off; off >>= 1) {
        ss += __shfl_xor_sync(0xffffffffu, ss, off);
        am = fmaxf(am, __shfl_xor_sync(0xffffffffu, am, off));
    }
    if ((tid & 31) == 0) { red[tid >> 5] = ss; redm[tid >> 5] = am; }
    __syncthreads();
    float tot = 0.f, m = 0.f;
    #pragma unroll
    for (int i = 0; i < 8; i++) { tot += red[i]; m = fmaxf(m, redm[i]); }
    const float r = rsqrtf(tot * (1.0f / DIM) + EPS_F);
    v.x *= r; v.y *= r; v.z *= r; v.w *= r;
    const float Sv = fmaxf(m * r, 1e-20f) * (1.0f / QMAX);
    const float inv128 = 1.0f / (128.0f * Sv), s128 = 128.0f * Sv, invS = 1.0f / Sv;
    char4 h4, l4;
    quant4(v, inv128, s128, invS, h4, l4);
    ((char4*)(qh + (size_t)row * DIM))[tid] = h4;
    ((char4*)(ql + (size_t)row * DIM))[tid] = l4;
    if (tid == 0) S[row] = Sv;
}

// ================= rope table =================
__global__ __launch_bounds__(256) void rope_tab(float2* __restrict__ tab) {
    const int idx = blockIdx.x * 256 + threadIdx.x;     // 65536 entries
    const int t = idx >> 4, j = idx & 15;
    const float f = powf(1e-4f, (float)j * (1.0f / 15.0f));
    float sn, cs;
    sincosf((float)t * f, &sn, &cs);
    tab[idx] = make_float2(cs, sn);
}

// ================= per-head q/k rmsnorm + rope; v split -> bf16 hi/lo =================
__global__ __launch_bounds__(256) void qk_prep(const float* __restrict__ qkv,
                                               const float2* __restrict__ rope,
                                               __nv_bfloat16* __restrict__ qh, __nv_bfloat16* __restrict__ ql,
                                               __nv_bfloat16* __restrict__ kh, __nv_bfloat16* __restrict__ kl,
                                               __nv_bfloat16* __restrict__ vh, __nv_bfloat16* __restrict__ vl) {
    const int t    = blockIdx.x;
    const int idx  = blockIdx.y * 8 + (threadIdx.x >> 5);
    const int lane = threadIdx.x & 31;
    const int head = idx & 15;
    const size_t dsto = (size_t)t * DIM + head * HD;
    __nv_bfloat16 *dh, *dl;
    const float* src;
    if (idx < 16) {
        src = qkv + (size_t)t * QKV_DIM + head * HD;
        dh = qh + dsto; dl = ql + dsto;
    } else if (idx < 32) {
        src = qkv + (size_t)t * QKV_DIM + DIM + head * HD;
        dh = kh + dsto; dl = kl + dsto;
    } else {
        src = qkv + (size_t)t * QKV_DIM + 2 * DIM + head * HD;
        dh = vh + dsto; dl = vl + dsto;
    }
    float a = src[lane];
    float b = src[lane + 32];
    if (idx < 32) {
        float ss = a * a + b * b;
        #pragma unroll
        for (int off = 16; off; off >>= 1) ss += __shfl_xor_sync(0xffffffffu, ss, off);
        const float r = rsqrtf(ss * (1.0f / HD) + EPS_F);
        a *= r; b *= r;
        float sn = 0.f, cs = 1.f;
        if (lane < 16) {
            const float2 e = rope[t * 16 + lane];
            cs = e.x; sn = e.y;
        }
        const float y1 =  a * cs + b * sn;
        const float y2 = -a * sn + b * cs;
        a = y1; b = y2;
    }
    __nv_bfloat16 ha, la, hb, lb;
    split_bf16(a, ha, la);
    split_bf16(b, hb, lb);
    dh[lane] = ha;      dl[lane] = la;
    dh[lane + 32] = hb; dl[lane + 32] = lb;
}

// ================= tensor-core sliding-window attention (bf16 hi/lo, fp32 out) ============
#define KVS_B 144
#define KVSPLIT 9216
#define ABUF (2 * KVSPLIT)
#define KVBUF (4 * KVSPLIT)
#define ATTN_SMEM (ABUF + 2 * KVBUF)    // 92160

__global__ __launch_bounds__(128) void attn_mma(
    const __nv_bfloat16* __restrict__ qh, const __nv_bfloat16* __restrict__ ql,
    const __nv_bfloat16* __restrict__ kh, const __nv_bfloat16* __restrict__ kl,
    const __nv_bfloat16* __restrict__ vh, const __nv_bfloat16* __restrict__ vl,
    float* __restrict__ outf) {
    extern __shared__ char smem[];
    const uint32_t sb = smem_u32(smem);
    const int h    = blockIdx.y;
    const int q0   = blockIdx.x * 64;
    const int tid  = threadIdx.x;
    const int wid  = tid >> 5;
    const int lane = tid & 31;

    #pragma unroll
    for (int it = 0; it < 4; it++) {
        const int g = tid + it * 128;
        const int row = g >> 3, cg = g & 7;
        const size_t src = (size_t)(q0 + row) * DIM + h * HD + cg * 8;
        const uint32_t off = (uint32_t)(row * KVS_B + cg * 16);
        cp16(sb + off, qh + src);
        cp16(sb + KVSPLIT + off, ql + src);
    }
    asm volatile("cp.async.commit_group;" ::: "memory");

    auto load_kv = [&](int kc, int buf) {
        const uint32_t base = sb + ABUF + buf * KVBUF;
        #pragma unroll
        for (int it = 0; it < 4; it++) {
            const int g = tid + it * 128;
            const int row = g >> 3, cg = g & 7;
            const size_t src = (size_t)(kc + row) * DIM + h * HD + cg * 8;
            const uint32_t off = (uint32_t)(row * KVS_B + cg * 16);
            cp16(base + off, kh + src);
            cp16(base + KVSPLIT + off, kl + src);
            cp16(base + 2 * KVSPLIT + off, vh + src);
            cp16(base + 3 * KVSPLIT + off, vl + src);
        }
        asm volatile("cp.async.commit_group;" ::: "memory");
    };

    const int kc0 = (q0 >= WIN) ? (q0 - WIN) : 0;
    const int nch = (q0 + 64 - kc0) >> 6;
    load_kv(kc0, 0);

    asm volatile("cp.async.wait_group 1;" ::: "memory");
    __syncthreads();
    uint32_t qfh[16], qfl[16];
    #pragma unroll
    for (int ks = 0; ks < 4; ks++) {
        const uint32_t ad = sb + (uint32_t)((wid * 16 + (lane & 15)) * KVS_B)
                          + ((lane >> 4) * 16) + ks * 32;
        ldsm_x4(qfh + ks * 4, ad);
        ldsm_x4(qfl + ks * 4, ad + KVSPLIT);
    }

    float m[2] = {-1e30f, -1e30f}, lsum[2] = {0.f, 0.f};
    float o[8][4];
    #pragma unroll
    for (int i = 0; i < 8; i++)
        #pragma unroll
        for (int j = 0; j < 4; j++) o[i][j] = 0.f;

    const int r0 = lane >> 2;
    const int qrow0 = q0 + wid * 16 + r0;
    const int qrow1 = qrow0 + 8;
    const int colb = (lane & 3) * 2;

    for (int c = 0; c < nch; c++) {
        const int b = c & 1;
        const int kc = kc0 + c * 64;
        if (c + 1 < nch) load_kv(kc + 64, b ^ 1);
        if (c + 1 < nch) { asm volatile("cp.async.wait_group 1;" ::: "memory"); }
        else             { asm volatile("cp.async.wait_group 0;" ::: "memory"); }
        __syncthreads();

        const uint32_t Kb = sb + ABUF + b * KVBUF;
        const uint32_t Vb = Kb + 2 * KVSPLIT;

        float sc[8][4];
        #pragma unroll
        for (int i = 0; i < 8; i++)
            #pragma unroll
            for (int j = 0; j < 4; j++) sc[i][j] = 0.f;
        #pragma unroll
        for (int ks = 0; ks < 4; ks++) {
            #pragma unroll
            for (int np = 0; np < 4; np++) {
                uint32_t bh4[4], bl4[4];
                const uint32_t bd = Kb
                    + (uint32_t)((np * 16 + ((lane >> 4) * 8) + (lane & 7)) * KVS_B)
                    + (((lane >> 3) & 1) * 16) + ks * 32;
                ldsm_x4(bh4, bd);
                ldsm_x4(bl4, bd + KVSPLIT);
                float* c0 = sc[np * 2];
                float* c1 = sc[np * 2 + 1];
                mma16816(c0, qfh + ks * 4, bh4);
                mma16816(c0, qfl + ks * 4, bh4);
                mma16816(c0, qfh + ks * 4, bl4);
                mma16816(c1, qfh + ks * 4, bh4 + 2);
                mma16816(c1, qfl + ks * 4, bh4 + 2);
                mma16816(c1, qfh + ks * 4, bl4 + 2);
            }
        }

        #pragma unroll
        for (int nf = 0; nf < 8; nf++) {
            #pragma unroll
            for (int j = 0; j < 4; j++) {
                const int kg = kc + nf * 8 + colb + (j & 1);
                const int q  = (j < 2) ? qrow0 : qrow1;
                const bool valid = (kg <= q) && (kg > q - WIN);
                sc[nf][j] = valid ? sc[nf][j] * 0.125f : -1e30f;
            }
        }
        float mx0 = -1e30f, mx1 = -1e30f;
        #pragma unroll
        for (int nf = 0; nf < 8; nf++) {
            mx0 = fmaxf(mx0, fmaxf(sc[nf][0], sc[nf][1]));
            mx1 = fmaxf(mx1, fmaxf(sc[nf][2], sc[nf][3]));
        }
        #pragma unroll
        for (int off = 1; off <= 2; off <<= 1) {
            mx0 = fmaxf(mx0, __shfl_xor_sync(0xffffffffu, mx0, off));
            mx1 = fmaxf(mx1, __shfl_xor_sync(0xffffffffu, mx1, off));
        }
        const float mn0 = fmaxf(m[0], mx0);
        const float mn1 = fmaxf(m[1], mx1);
        const float cr0 = __expf(m[0] - mn0);
        const float cr1 = __expf(m[1] - mn1);
        m[0] = mn0; m[1] = mn1;
        float sm0 = 0.f, sm1 = 0.f;
        #pragma unroll
        for (int nf = 0; nf < 8; nf++) {
            sc[nf][0] = __expf(sc[nf][0] - mn0);
            sc[nf][1] = __expf(sc[nf][1] - mn0);
            sc[nf][2] = __expf(sc[nf][2] - mn1);
            sc[nf][3] = __expf(sc[nf][3] - mn1);
            sm0 += sc[nf][0] + sc[nf][1];
            sm1 += sc[nf][2] + sc[nf][3];
        }
        #pragma unroll
        for (int off = 1; off <= 2; off <<= 1) {
            sm0 += __shfl_xor_sync(0xffffffffu, sm0, off);
            sm1 += __shfl_xor_sync(0xffffffffu, sm1, off);
        }
        lsum[0] = lsum[0] * cr0 + sm0;
        lsum[1] = lsum[1] * cr1 + sm1;
        #pragma unroll
        for (int nf = 0; nf < 8; nf++) {
            o[nf][0] *= cr0; o[nf][1] *= cr0;
            o[nf][2] *= cr1; o[nf][3] *= cr1;
        }

        #pragma unroll
        for (int ks = 0; ks < 4; ks++) {
            uint32_t ah4[4], al4[4];
            const float* p0 = sc[ks * 2];
            const float* p1 = sc[ks * 2 + 1];
            ah4[0] = pack_hi(p0[0], p0[1]);  al4[0] = pack_lo(p0[0], p0[1]);
            ah4[1] = pack_hi(p0[2], p0[3]);  al4[1] = pack_lo(p0[2], p0[3]);
            ah4[2] = pack_hi(p1[0], p1[1]);  al4[2] = pack_lo(p1[0], p1[1]);
            ah4[3] = pack_hi(p1[2], p1[3]);  al4[3] = pack_lo(p1[2], p1[3]);
            #pragma unroll
            for (int dg = 0; dg < 4; dg++) {
                uint32_t vh4[4], vl4[4];
                const uint32_t vd = Vb
                    + (uint32_t)((ks * 16 + (lane & 7) + ((lane >> 3) & 1) * 8) * KVS_B)
                    + dg * 32 + (((lane >> 4) & 1) * 16);
                ldsm_x4_t(vh4, vd);
                ldsm_x4_t(vl4, vd + KVSPLIT);
                float* c0 = o[dg * 2];
                float* c1 = o[dg * 2 + 1];
                mma16816(c0, ah4, vh4);
                mma16816(c0, al4, vh4);
                mma16816(c0, ah4, vl4);
                mma16816(c1, ah4, vh4 + 2);
                mma16816(c1, al4, vh4 + 2);
                mma16816(c1, ah4, vl4 + 2);
            }
        }
        __syncthreads();
    }

    const float inv0 = 1.0f / lsum[0];
    const float inv1 = 1.0f / lsum[1];
    #pragma unroll
    for (int nf = 0; nf < 8; nf++) {
        const int col = h * HD + nf * 8 + colb;
        *(float2*)(outf + (size_t)qrow0 * DIM + col) = make_float2(o[nf][0] * inv0, o[nf][1] * inv0);
        *(float2*)(outf + (size_t)qrow1 * DIM + col) = make_float2(o[nf][2] * inv1, o[nf][3] * inv1);
    }
}

// ================= int8 two-digit GEMM (CTA 128x128, warp 64x32, 6-stage) =================
// C = Sa[m]*Sb[n]*(16384*Ch + 128*Cm),  Ch = ha.hb, Cm = ha.lb + la.hb
#define IBM 128
#define IBN 128
#define IBK 32
#define IROWB 48                          // 32 B data + 16 B pad
#define I_SPLIT (128 * IROWB)             // 6144
#define ISTAGE (4 * I_SPLIT)              // 24576
#define ISTAGES 6
#define IGSMEM (ISTAGES * ISTAGE)         // 147456

template <int MODE>
__global__ __launch_bounds__(256, 1) void gemm_i8(
    const int8_t* __restrict__ Ah8, const int8_t* __restrict__ Al8, const float* __restrict__ Sa,
    const int8_t* __restrict__ Bh8, const int8_t* __restrict__ Bl8, const float* __restrict__ Sb,
    int K, int Ntot,
    float* __restrict__ Cf, const float* __restrict__ res, const float* __restrict__ scale) {
    extern __shared__ char smem[];
    const uint32_t sb = smem_u32(smem);
    const int tid  = threadIdx.x;
    const int lane = tid & 31;
    const int wid  = tid >> 5;
    const int wm   = wid & 1;             // 2 warp rows of 64
    const int wn   = wid >> 1;            // 4 warp cols of 32
    const int m0 = blockIdx.y * IBM, n0 = blockIdx.x * IBN;

    int Ch[4][4][4], Cm[4][4][4];
    #pragma unroll
    for (int i = 0; i < 4; i++)
        #pragma unroll
        for (int j = 0; j < 4; j++)
            #pragma unroll
            for (int k = 0; k < 4; k++) { Ch[i][j][k] = 0; Cm[i][j][k] = 0; }

    const int lrow = tid >> 1, lcg = tid & 1;
    auto load_stage = [&](int kc, int s) {
        const uint32_t base = sb + s * ISTAGE;
        const uint32_t off = (uint32_t)(lrow * IROWB + lcg * 16);
        const size_t ga = (size_t)(m0 + lrow) * K + kc + lcg * 16;
        const size_t gb = (size_t)(n0 + lrow) * K + kc + lcg * 16;
        cp16(base + off,               Ah8 + ga);
        cp16(base + I_SPLIT + off,     Al8 + ga);
        cp16(base + 2 * I_SPLIT + off, Bh8 + gb);
        cp16(base + 3 * I_SPLIT + off, Bl8 + gb);
        asm volatile("cp.async.commit_group;" ::: "memory");
    };

    const int NC = K / IBK;
    #pragma unroll
    for (int s = 0; s < 5; s++) load_stage(s * IBK, s);

    for (int c = 0; c < NC; c++) {
        asm volatile("cp.async.wait_group 4;" ::: "memory");
        __syncthreads();
        if (c + 5 < NC) load_stage((c + 5) * IBK, (c + 5) % ISTAGES);

        const uint32_t stb = sb + (c % ISTAGES) * ISTAGE;
        uint32_t ah[16], al[16];
        #pragma unroll
        for (int mf = 0; mf < 4; mf++) {
            const uint32_t ad = stb
                + (uint32_t)((wm * 64 + mf * 16 + (lane & 15)) * IROWB)
                + ((lane >> 4) * 16);
            ldsm_x4(ah + mf * 4, ad);
            ldsm_x4(al + mf * 4, ad + I_SPLIT);
        }
        #pragma unroll
        for (int g = 0; g < 2; g++) {
            uint32_t bh4[4], bl4[4];
            const uint32_t bd = stb + 2 * I_SPLIT
                + (uint32_t)((wn * 32 + g * 16 + ((lane >> 4) * 8) + (lane & 7)) * IROWB)
                + (((lane >> 3) & 1) * 16);
            ldsm_x4(bh4, bd);
            ldsm_x4(bl4, bd + I_SPLIT);
            #pragma unroll
            for (int mf = 0; mf < 4; mf++) {
                imma16832(Ch[mf][g * 2],     ah + mf * 4, bh4);
                imma16832(Cm[mf][g * 2],     al + mf * 4, bh4);
                imma16832(Cm[mf][g * 2],     ah + mf * 4, bl4);
                imma16832(Ch[mf][g * 2 + 1], ah + mf * 4, bh4 + 2);
                imma16832(Cm[mf][g * 2 + 1], al + mf * 4, bh4 + 2);
                imma16832(Cm[mf][g * 2 + 1], ah + mf * 4, bl4 + 2);
            }
        }
    }

    // ---- epilogue ----
    const int rb = m0 + wm * 64 + (lane >> 2);
    const int cb = n0 + wn * 32 + (lane & 3) * 2;
    #pragma unroll
    for (int mf = 0; mf < 4; mf++) {
        const int rr0 = rb + mf * 16;
        const int rr1 = rr0 + 8;
        const float sa0 = Sa[rr0], sa1 = Sa[rr1];
        #pragma unroll
        for (int nf = 0; nf < 4; nf++) {
            const int cn = cb + nf * 8;
            const float2 sbv = *(const float2*)(Sb + cn);
            const int* ch = Ch[mf][nf];
            const int* cm = Cm[mf][nf];
            float v0 = sa0 * sbv.x * (16384.f * (float)ch[0] + 128.f * (float)cm[0]);
            float v1 = sa0 * sbv.y * (16384.f * (float)ch[1] + 128.f * (float)cm[1]);
            float v2 = sa1 * sbv.x * (16384.f * (float)ch[2] + 128.f * (float)cm[2]);
            float v3 = sa1 * sbv.y * (16384.f * (float)ch[3] + 128.f * (float)cm[3]);
            if (MODE == 1) {
                const float2 sc2 = *(const float2*)(scale + cn);
                const float2 q0 = *(const float2*)(res + (size_t)rr0 * Ntot + cn);
                const float2 q1 = *(const float2*)(res + (size_t)rr1 * Ntot + cn);
                v0 = q0.x + sc2.x * v0; v1 = q0.y + sc2.y * v1;
                v2 = q1.x + sc2.x * v2; v3 = q1.y + sc2.y * v3;
            } else if (MODE == 2) {
                v0 = fmaxf(v0, 0.f); v0 *= v0;
                v1 = fmaxf(v1, 0.f); v1 *= v1;
                v2 = fmaxf(v2, 0.f); v2 *= v2;
                v3 = fmaxf(v3, 0.f); v3 *= v3;
            }
            *(float2*)(Cf + (size_t)rr0 * Ntot + cn) = make_float2(v0, v1);
            *(float2*)(Cf + (size_t)rr1 * Ntot + cn) = make_float2(v2, v3);
        }
    }
}

// ================= host launcher =================
extern "C" void kernel_launch(void* const* d_in, const int* in_sizes, int n_in,
                              void* d_out, int out_size) {
    const float* x        = (const float*)d_in[0];
    const float* qkv_w    = (const float*)d_in[1];
    const float* o_w      = (const float*)d_in[2];
    const float* o_scale  = (const float*)d_in[3];
    const float* w1       = (const float*)d_in[4];
    const float* w2       = (const float*)d_in[5];
    const float* w2_scale = (const float*)d_in[6];
    float* out = (float*)d_out;

    float *qkv, *x1, *attn, *hf;
    float2* rope;
    cudaGetSymbolAddress((void**)&qkv,  g_qkv);
    cudaGetSymbolAddress((void**)&x1,   g_x1);
    cudaGetSymbolAddress((void**)&attn, g_attn);
    cudaGetSymbolAddress((void**)&hf,   g_hf);
    cudaGetSymbolAddress((void**)&rope, g_rope);
    __nv_bfloat16 *qh, *ql, *kh, *kl, *vh, *vl;
    cudaGetSymbolAddress((void**)&qh, g_qh); cudaGetSymbolAddress((void**)&ql, g_ql);
    cudaGetSymbolAddress((void**)&kh, g_kh); cudaGetSymbolAddress((void**)&kl, g_kl);
    cudaGetSymbolAddress((void**)&vh, g_vh); cudaGetSymbolAddress((void**)&vl, g_vl);
    int8_t *xqh, *xql, *aqh, *aql, *x1qh, *x1ql, *hqh, *hql;
    int8_t *wqh, *wql, *woh, *wol, *w1h, *w1l, *w2h, *w2l;
    float *sx, *sa, *sx1, *sh, *swq, *swo, *sw1, *sw2;
    cudaGetSymbolAddress((void**)&xqh,  g_xq_h);  cudaGetSymbolAddress((void**)&xql,  g_xq_l);
    cudaGetSymbolAddress((void**)&aqh,  g_aq_h);  cudaGetSymbolAddress((void**)&aql,  g_aq_l);
    cudaGetSymbolAddress((void**)&x1qh, g_x1q_h); cudaGetSymbolAddress((void**)&x1ql, g_x1q_l);
    cudaGetSymbolAddress((void**)&hqh,  g_hq_h);  cudaGetSymbolAddress((void**)&hql,  g_hq_l);
    cudaGetSymbolAddress((void**)&wqh,  g_wq_h);  cudaGetSymbolAddress((void**)&wql,  g_wq_l);
    cudaGetSymbolAddress((void**)&woh,  g_wo_h);  cudaGetSymbolAddress((void**)&wol,  g_wo_l);
    cudaGetSymbolAddress((void**)&w1h,  g_w1_h);  cudaGetSymbolAddress((void**)&w1l,  g_w1_l);
    cudaGetSymbolAddress((void**)&w2h,  g_w2_h);  cudaGetSymbolAddress((void**)&w2l,  g_w2_l);
    cudaGetSymbolAddress((void**)&sx,  g_sx);  cudaGetSymbolAddress((void**)&sa,  g_sa);
    cudaGetSymbolAddress((void**)&sx1, g_sx1); cudaGetSymbolAddress((void**)&sh,  g_sh);
    cudaGetSymbolAddress((void**)&swq, g_swq); cudaGetSymbolAddress((void**)&swo, g_swo);
    cudaGetSymbolAddress((void**)&sw1, g_sw1); cudaGetSymbolAddress((void**)&sw2, g_sw2);

    cudaFuncSetAttribute(gemm_i8<0>, cudaFuncAttributeMaxDynamicSharedMemorySize, IGSMEM);
    cudaFuncSetAttribute(gemm_i8<1>, cudaFuncAttributeMaxDynamicSharedMemorySize, IGSMEM);
    cudaFuncSetAttribute(gemm_i8<2>, cudaFuncAttributeMaxDynamicSharedMemorySize, IGSMEM);
    cudaFuncSetAttribute(attn_mma, cudaFuncAttributeMaxDynamicSharedMemorySize, ATTN_SMEM);

    // 1. all weight quantizations (one launch)
    quant_weights<<<9216, 256>>>(qkv_w, o_w, w1, w2,
                                 wqh, wql, swq, woh, wol, swo,
                                 w1h, w1l, sw1, w2h, w2l, sw2);
    // 2. xn = rmsnorm(x) -> int8 digits
    rmsnorm_quant<<<T_LEN, 256>>>(x, xqh, xql, sx);
    // 3. rope table
    rope_tab<<<256, 256>>>(rope);
    // 4. qkv = xn @ qkv_w^T   <-- profiled slot
    gemm_i8<0><<<dim3(QKV_DIM / IBN, T_LEN / IBM), 256, IGSMEM>>>(
        xqh, xql, sx, wqh, wql, swq, DIM, QKV_DIM, qkv, nullptr, nullptr);
    // 5. q/k norm+rope, v -> bf16 hi/lo
    qk_prep<<<dim3(T_LEN, 6), 256>>>(qkv, rope, qh, ql, kh, kl, vh, vl);
    // 6. attention -> fp32
    attn_mma<<<dim3(T_LEN / 64, NHEADS), 128, ATTN_SMEM>>>(qh, ql, kh, kl, vh, vl, attn);
    // 7. quantize attention output
    quant_rows<<<T_LEN, 256>>>(attn, DIM, aqh, aql, sa);
    // 8. x1 = x + o_scale[n] * (attn @ o_w^T)
    gemm_i8<1><<<dim3(DIM / IBN, T_LEN / IBM), 256, IGSMEM>>>(
        aqh, aql, sa, woh, wol, swo, DIM, DIM, x1, x, o_scale);
    // 9. x1n = rmsnorm(x1) -> int8 digits
    rmsnorm_quant<<<T_LEN, 256>>>(x1, x1qh, x1ql, sx1);
    // 10. h = relu(x1n @ w1^T)^2 -> fp32
    gemm_i8<2><<<dim3(MLP_DIM / IBN, T_LEN / IBM), 256, IGSMEM>>>(
        x1qh, x1ql, sx1, w1h, w1l, sw1, DIM, MLP_DIM, hf, nullptr, nullptr);
    // 11. quantize h
    quant_rows<<<T_LEN, 256>>>(hf, MLP_DIM, hqh, hql, sh);
    // 12. out = x1 + w2_scale[n] * (h @ w2^T)
    gemm_i8<1><<<dim3(DIM / IBN, T_LEN / IBM), 256, IGSMEM>>>(
        hqh, hql, sh, w2h, w2l, sw2, MLP_DIM, DIM, out, x1, w2_scale);
}

// round 8
// speedup vs baseline: 3.7651x; 1.0156x over previous
#include <cuda_runtime.h>
#include <cuda_bf16.h>
#include <math_constants.h>
#include <cstdint>

#define T_LEN   4096
#define DIM     1024
#define QKV_DIM 3072
#define MLP_DIM 4096
#define NHEADS  16
#define HD      64
#define WIN     512
#define EPS_F   1.1920929e-07f
#define QMAX    16256.0f            // 127*128

// ================= helpers =================
__device__ __forceinline__ uint32_t smem_u32(const void* p) {
    uint32_t a;
    asm("{ .reg .u64 t; cvta.to.shared.u64 t, %1; cvt.u32.u64 %0, t; }" : "=r"(a) : "l"(p));
    return a;
}
__device__ __forceinline__ void cp16(uint32_t s, const void* g) {
    asm volatile("cp.async.cg.shared.global [%0], [%1], 16;" :: "r"(s), "l"(g));
}
__device__ __forceinline__ void ldsm_x4(uint32_t* r, uint32_t addr) {
    asm volatile("ldmatrix.sync.aligned.m8n8.x4.shared.b16 {%0,%1,%2,%3}, [%4];"
                 : "=r"(r[0]), "=r"(r[1]), "=r"(r[2]), "=r"(r[3]) : "r"(addr));
}
__device__ __forceinline__ void ldsm_x4_t(uint32_t* r, uint32_t addr) {
    asm volatile("ldmatrix.sync.aligned.m8n8.x4.trans.shared.b16 {%0,%1,%2,%3}, [%4];"
                 : "=r"(r[0]), "=r"(r[1]), "=r"(r[2]), "=r"(r[3]) : "r"(addr));
}
__device__ __forceinline__ void mma16816(float* c, const uint32_t* a, const uint32_t* b) {
    asm volatile("mma.sync.aligned.m16n8k16.row.col.f32.bf16.bf16.f32 "
        "{%0,%1,%2,%3}, {%4,%5,%6,%7}, {%8,%9}, {%0,%1,%2,%3};"
        : "+f"(c[0]), "+f"(c[1]), "+f"(c[2]), "+f"(c[3])
        : "r"(a[0]), "r"(a[1]), "r"(a[2]), "r"(a[3]), "r"(b[0]), "r"(b[1]));
}
__device__ __forceinline__ void imma16832(int* c, const uint32_t* a, const uint32_t* b) {
    asm volatile("mma.sync.aligned.m16n8k32.row.col.s32.s8.s8.s32 "
        "{%0,%1,%2,%3}, {%4,%5,%6,%7}, {%8,%9}, {%0,%1,%2,%3};"
        : "+r"(c[0]), "+r"(c[1]), "+r"(c[2]), "+r"(c[3])
        : "r"(a[0]), "r"(a[1]), "r"(a[2]), "r"(a[3]), "r"(b[0]), "r"(b[1]));
}
__device__ __forceinline__ void split_bf16(float a, __nv_bfloat16& hi, __nv_bfloat16& lo) {
    hi = __float2bfloat16(a);
    lo = __float2bfloat16(a - __bfloat162float(hi));
}
__device__ __forceinline__ uint32_t pack2(__nv_bfloat16 a, __nv_bfloat16 b) {
    return (uint32_t)__bfloat16_as_ushort(a) | ((uint32_t)__bfloat16_as_ushort(b) << 16);
}
__device__ __forceinline__ uint32_t pack_hi(float a, float b) {
    return pack2(__float2bfloat16(a), __float2bfloat16(b));
}
__device__ __forceinline__ uint32_t pack_lo(float a, float b) {
    __nv_bfloat16 ha = __float2bfloat16(a), hb = __float2bfloat16(b);
    return pack2(__float2bfloat16(a - __bfloat162float(ha)),
                 __float2bfloat16(b - __bfloat162float(hb)));
}

// ================= scratch =================
__device__ float g_qkv [T_LEN * QKV_DIM];
__device__ float g_x1  [T_LEN * DIM];
__device__ float g_attn[T_LEN * DIM];
__device__ float g_hf  [T_LEN * MLP_DIM];
__device__ float2 g_rope[T_LEN * 16];

#define BF16A __device__ __align__(16) __nv_bfloat16
BF16A g_qh[T_LEN * DIM]; BF16A g_ql[T_LEN * DIM];
BF16A g_kh[T_LEN * DIM]; BF16A g_kl[T_LEN * DIM];
BF16A g_vh[T_LEN * DIM]; BF16A g_vl[T_LEN * DIM];

#define I8A __device__ __align__(16) int8_t
I8A g_xq_h [T_LEN * DIM];     I8A g_xq_l [T_LEN * DIM];     __device__ float g_sx [T_LEN];
I8A g_aq_h [T_LEN * DIM];     I8A g_aq_l [T_LEN * DIM];     __device__ float g_sa [T_LEN];
I8A g_x1q_h[T_LEN * DIM];     I8A g_x1q_l[T_LEN * DIM];     __device__ float g_sx1[T_LEN];
I8A g_hq_h [T_LEN * MLP_DIM]; I8A g_hq_l [T_LEN * MLP_DIM]; __device__ float g_sh [T_LEN];
I8A g_wq_h [QKV_DIM * DIM];   I8A g_wq_l [QKV_DIM * DIM];   __device__ float g_swq[QKV_DIM];
I8A g_wo_h [DIM * DIM];       I8A g_wo_l [DIM * DIM];       __device__ float g_swo[DIM];
I8A g_w1_h [MLP_DIM * DIM];   I8A g_w1_l [MLP_DIM * DIM];   __device__ float g_sw1[MLP_DIM];
I8A g_w2_h [DIM * MLP_DIM];   I8A g_w2_l [DIM * MLP_DIM];   __device__ float g_sw2[DIM];

// ================= row quantization =================
__device__ __forceinline__ float block_max256(float v, float* red) {
    #pragma unroll
    for (int off = 16; off; off >>= 1) v = fmaxf(v, __shfl_xor_sync(0xffffffffu, v, off));
    if ((threadIdx.x & 31) == 0) red[threadIdx.x >> 5] = v;
    __syncthreads();
    float m = red[0];
    #pragma unroll
    for (int i = 1; i < 8; i++) m = fmaxf(m, red[i]);
    return m;
}
__device__ __forceinline__ void quant4(float4 v, float inv128, float s128, float invS,
                                       char4& qh, char4& ql) {
    float h0 = rintf(v.x * inv128), h1 = rintf(v.y * inv128);
    float h2 = rintf(v.z * inv128), h3 = rintf(v.w * inv128);
    qh = make_char4((signed char)__float2int_rn(h0), (signed char)__float2int_rn(h1),
                    (signed char)__float2int_rn(h2), (signed char)__float2int_rn(h3));
    ql = make_char4((signed char)__float2int_rn((v.x - h0 * s128) * invS),
                    (signed char)__float2int_rn((v.y - h1 * s128) * invS),
                    (signed char)__float2int_rn((v.z - h2 * s128) * invS),
                    (signed char)__float2int_rn((v.w - h3 * s128) * invS));
}

__device__ __forceinline__ void quant_row_body(const float* __restrict__ src, int ncols,
                                               int8_t* __restrict__ qh, int8_t* __restrict__ ql,
                                               float* __restrict__ Srow, int row) {
    __shared__ float red[8];
    const float* r = src + (size_t)row * ncols;
    const int tid = threadIdx.x;
    const int n4 = ncols >> 2;
    float amax = 0.f;
    for (int i = tid; i < n4; i += 256) {
        float4 v = ((const float4*)r)[i];
        amax = fmaxf(amax, fmaxf(fmaxf(fabsf(v.x), fabsf(v.y)), fmaxf(fabsf(v.z), fabsf(v.w))));
    }
    const float m = block_max256(amax, red);
    const float S = fmaxf(m, 1e-20f) * (1.0f / QMAX);
    const float inv128 = 1.0f / (128.0f * S), s128 = 128.0f * S, invS = 1.0f / S;
    for (int i = tid; i < n4; i += 256) {
        float4 v = ((const float4*)r)[i];
        char4 h4, l4;
        quant4(v, inv128, s128, invS, h4, l4);
        ((char4*)(qh + (size_t)row * ncols))[i] = h4;
        ((char4*)(ql + (size_t)row * ncols))[i] = l4;
    }
    if (tid == 0) Srow[row] = S;
}

__global__ __launch_bounds__(256) void quant_rows(const float* __restrict__ src, int ncols,
                                                  int8_t* __restrict__ qh, int8_t* __restrict__ ql,
                                                  float* __restrict__ S) {
    quant_row_body(src, ncols, qh, ql, S, blockIdx.x);
}

__global__ __launch_bounds__(256) void quant_weights(
    const float* qkv_w, const float* o_w, const float* w1, const float* w2,
    int8_t* wqh, int8_t* wql, float* swq,
    int8_t* woh, int8_t* wol, float* swo,
    int8_t* w1h, int8_t* w1l, float* sw1,
    int8_t* w2h, int8_t* w2l, float* sw2) {
    int r = blockIdx.x;
    if (r < 3072)       quant_row_body(qkv_w, 1024, wqh, wql, swq, r);
    else if (r < 4096)  quant_row_body(o_w,   1024, woh, wol, swo, r - 3072);
    else if (r < 8192)  quant_row_body(w1,    1024, w1h, w1l, sw1, r - 4096);
    else                quant_row_body(w2,    4096, w2h, w2l, sw2, r - 8192);
}

// ================= rmsnorm -> int8 two-digit =================
__global__ __launch_bounds__(256) void rmsnorm_quant(const float* __restrict__ x,
                                                     int8_t* __restrict__ qh,
                                                     int8_t* __restrict__ ql,
                                                     float* __restrict__ S) {
    __shared__ float red[8], redm[8];
    const int row = blockIdx.x;
    const int tid = threadIdx.x;
    float4 v = ((const float4*)(x + (size_t)row * DIM))[tid];
    float ss = v.x * v.x + v.y * v.y + v.z * v.z + v.w * v.w;
    float am = fmaxf(fmaxf(fabsf(v.x), fabsf(v.y)), fmaxf(fabsf(v.z), fabsf(v.w)));
    #pragma unroll
    for (int off = 16; off; off >>= 1) {
        ss += __shfl_xor_sync(0xffffffffu, ss, off);
        am = fmaxf(am, __shfl_xor_sync(0xffffffffu, am, off));
    }
    if ((tid & 31) == 0) { red[tid >> 5] = ss; redm[tid >> 5] = am; }
    __syncthreads();
    float tot = 0.f, m = 0.f;
    #pragma unroll
    for (int i = 0; i < 8; i++) { tot += red[i]; m = fmaxf(m, redm[i]); }
    const float r = rsqrtf(tot * (1.0f / DIM) + EPS_F);
    v.x *= r; v.y *= r; v.z *= r; v.w *= r;
    const float Sv = fmaxf(m * r, 1e-20f) * (1.0f / QMAX);
    const float inv128 = 1.0f / (128.0f * Sv), s128 = 128.0f * Sv, invS = 1.0f / Sv;
    char4 h4, l4;
    quant4(v, inv128, s128, invS, h4, l4);
    ((char4*)(qh + (size_t)row * DIM))[tid] = h4;
    ((char4*)(ql + (size_t)row * DIM))[tid] = l4;
    if (tid == 0) S[row] = Sv;
}

// ================= rope table =================
__global__ __launch_bounds__(256) void rope_tab(float2* __restrict__ tab) {
    const int idx = blockIdx.x * 256 + threadIdx.x;
    const int t = idx >> 4, j = idx & 15;
    const float f = powf(1e-4f, (float)j * (1.0f / 15.0f));
    float sn, cs;
    sincosf((float)t * f, &sn, &cs);
    tab[idx] = make_float2(cs, sn);
}

// ================= per-head q/k rmsnorm + rope; v split -> bf16 hi/lo =================
__global__ __launch_bounds__(256) void qk_prep(const float* __restrict__ qkv,
                                               const float2* __restrict__ rope,
                                               __nv_bfloat16* __restrict__ qh, __nv_bfloat16* __restrict__ ql,
                                               __nv_bfloat16* __restrict__ kh, __nv_bfloat16* __restrict__ kl,
                                               __nv_bfloat16* __restrict__ vh, __nv_bfloat16* __restrict__ vl) {
    const int t    = blockIdx.x;
    const int idx  = blockIdx.y * 8 + (threadIdx.x >> 5);
    const int lane = threadIdx.x & 31;
    const int head = idx & 15;
    const size_t dsto = (size_t)t * DIM + head * HD;
    __nv_bfloat16 *dh, *dl;
    const float* src;
    if (idx < 16) {
        src = qkv + (size_t)t * QKV_DIM + head * HD;
        dh = qh + dsto; dl = ql + dsto;
    } else if (idx < 32) {
        src = qkv + (size_t)t * QKV_DIM + DIM + head * HD;
        dh = kh + dsto; dl = kl + dsto;
    } else {
        src = qkv + (size_t)t * QKV_DIM + 2 * DIM + head * HD;
        dh = vh + dsto; dl = vl + dsto;
    }
    float a = src[lane];
    float b = src[lane + 32];
    if (idx < 32) {
        float ss = a * a + b * b;
        #pragma unroll
        for (int off = 16; off; off >>= 1) ss += __shfl_xor_sync(0xffffffffu, ss, off);
        const float r = rsqrtf(ss * (1.0f / HD) + EPS_F);
        a *= r; b *= r;
        float sn = 0.f, cs = 1.f;
        if (lane < 16) {
            const float2 e = rope[t * 16 + lane];
            cs = e.x; sn = e.y;
        }
        const float y1 =  a * cs + b * sn;
        const float y2 = -a * sn + b * cs;
        a = y1; b = y2;
    }
    __nv_bfloat16 ha, la, hb, lb;
    split_bf16(a, ha, la);
    split_bf16(b, hb, lb);
    dh[lane] = ha;      dl[lane] = la;
    dh[lane + 32] = hb; dl[lane + 32] = lb;
}

// ================= tensor-core sliding-window attention =================
#define KVS_B 144
#define KVSPLIT 9216
#define ABUF (2 * KVSPLIT)
#define KVBUF (4 * KVSPLIT)
#define ATTN_SMEM (ABUF + 2 * KVBUF)    // 92160

__global__ __launch_bounds__(128) void attn_mma(
    const __nv_bfloat16* __restrict__ qh, const __nv_bfloat16* __restrict__ ql,
    const __nv_bfloat16* __restrict__ kh, const __nv_bfloat16* __restrict__ kl,
    const __nv_bfloat16* __restrict__ vh, const __nv_bfloat16* __restrict__ vl,
    float* __restrict__ outf) {
    extern __shared__ char smem[];
    const uint32_t sb = smem_u32(smem);
    const int h    = blockIdx.y;
    const int q0   = blockIdx.x * 64;
    const int tid  = threadIdx.x;
    const int wid  = tid >> 5;
    const int lane = tid & 31;

    #pragma unroll
    for (int it = 0; it < 4; it++) {
        const int g = tid + it * 128;
        const int row = g >> 3, cg = g & 7;
        const size_t src = (size_t)(q0 + row) * DIM + h * HD + cg * 8;
        const uint32_t off = (uint32_t)(row * KVS_B + cg * 16);
        cp16(sb + off, qh + src);
        cp16(sb + KVSPLIT + off, ql + src);
    }
    asm volatile("cp.async.commit_group;" ::: "memory");

    auto load_kv = [&](int kc, int buf) {
        const uint32_t base = sb + ABUF + buf * KVBUF;
        #pragma unroll
        for (int it = 0; it < 4; it++) {
            const int g = tid + it * 128;
            const int row = g >> 3, cg = g & 7;
            const size_t src = (size_t)(kc + row) * DIM + h * HD + cg * 8;
            const uint32_t off = (uint32_t)(row * KVS_B + cg * 16);
            cp16(base + off, kh + src);
            cp16(base + KVSPLIT + off, kl + src);
            cp16(base + 2 * KVSPLIT + off, vh + src);
            cp16(base + 3 * KVSPLIT + off, vl + src);
        }
        asm volatile("cp.async.commit_group;" ::: "memory");
    };

    const int kc0 = (q0 >= WIN) ? (q0 - WIN) : 0;
    const int nch = (q0 + 64 - kc0) >> 6;
    load_kv(kc0, 0);

    asm volatile("cp.async.wait_group 1;" ::: "memory");
    __syncthreads();
    uint32_t qfh[16], qfl[16];
    #pragma unroll
    for (int ks = 0; ks < 4; ks++) {
        const uint32_t ad = sb + (uint32_t)((wid * 16 + (lane & 15)) * KVS_B)
                          + ((lane >> 4) * 16) + ks * 32;
        ldsm_x4(qfh + ks * 4, ad);
        ldsm_x4(qfl + ks * 4, ad + KVSPLIT);
    }

    float m[2] = {-1e30f, -1e30f}, lsum[2] = {0.f, 0.f};
    float o[8][4];
    #pragma unroll
    for (int i = 0; i < 8; i++)
        #pragma unroll
        for (int j = 0; j < 4; j++) o[i][j] = 0.f;

    const int r0 = lane >> 2;
    const int qrow0 = q0 + wid * 16 + r0;
    const int qrow1 = qrow0 + 8;
    const int colb = (lane & 3) * 2;

    for (int c = 0; c < nch; c++) {
        const int b = c & 1;
        const int kc = kc0 + c * 64;
        if (c + 1 < nch) load_kv(kc + 64, b ^ 1);
        if (c + 1 < nch) { asm volatile("cp.async.wait_group 1;" ::: "memory"); }
        else             { asm volatile("cp.async.wait_group 0;" ::: "memory"); }
        __syncthreads();

        const uint32_t Kb = sb + ABUF + b * KVBUF;
        const uint32_t Vb = Kb + 2 * KVSPLIT;

        float sc[8][4];
        #pragma unroll
        for (int i = 0; i < 8; i++)
            #pragma unroll
            for (int j = 0; j < 4; j++) sc[i][j] = 0.f;
        #pragma unroll
        for (int ks = 0; ks < 4; ks++) {
            #pragma unroll
            for (int np = 0; np < 4; np++) {
                uint32_t bh4[4], bl4[4];
                const uint32_t bd = Kb
                    + (uint32_t)((np * 16 + ((lane >> 4) * 8) + (lane & 7)) * KVS_B)
                    + (((lane >> 3) & 1) * 16) + ks * 32;
                ldsm_x4(bh4, bd);
                ldsm_x4(bl4, bd + KVSPLIT);
                float* c0 = sc[np * 2];
                float* c1 = sc[np * 2 + 1];
                mma16816(c0, qfh + ks * 4, bh4);
                mma16816(c0, qfl + ks * 4, bh4);
                mma16816(c0, qfh + ks * 4, bl4);
                mma16816(c1, qfh + ks * 4, bh4 + 2);
                mma16816(c1, qfl + ks * 4, bh4 + 2);
                mma16816(c1, qfh + ks * 4, bl4 + 2);
            }
        }

        #pragma unroll
        for (int nf = 0; nf < 8; nf++) {
            #pragma unroll
            for (int j = 0; j < 4; j++) {
                const int kg = kc + nf * 8 + colb + (j & 1);
                const int q  = (j < 2) ? qrow0 : qrow1;
                const bool valid = (kg <= q) && (kg > q - WIN);
                sc[nf][j] = valid ? sc[nf][j] * 0.125f : -1e30f;
            }
        }
        float mx0 = -1e30f, mx1 = -1e30f;
        #pragma unroll
        for (int nf = 0; nf < 8; nf++) {
            mx0 = fmaxf(mx0, fmaxf(sc[nf][0], sc[nf][1]));
            mx1 = fmaxf(mx1, fmaxf(sc[nf][2], sc[nf][3]));
        }
        #pragma unroll
        for (int off = 1; off <= 2; off <<= 1) {
            mx0 = fmaxf(mx0, __shfl_xor_sync(0xffffffffu, mx0, off));
            mx1 = fmaxf(mx1, __shfl_xor_sync(0xffffffffu, mx1, off));
        }
        const float mn0 = fmaxf(m[0], mx0);
        const float mn1 = fmaxf(m[1], mx1);
        const float cr0 = __expf(m[0] - mn0);
        const float cr1 = __expf(m[1] - mn1);
        m[0] = mn0; m[1] = mn1;
        float sm0 = 0.f, sm1 = 0.f;
        #pragma unroll
        for (int nf = 0; nf < 8; nf++) {
            sc[nf][0] = __expf(sc[nf][0] - mn0);
            sc[nf][1] = __expf(sc[nf][1] - mn0);
            sc[nf][2] = __expf(sc[nf][2] - mn1);
            sc[nf][3] = __expf(sc[nf][3] - mn1);
            sm0 += sc[nf][0] + sc[nf][1];
            sm1 += sc[nf][2] + sc[nf][3];
        }
        #pragma unroll
        for (int off = 1; off <= 2; off <<= 1) {
            sm0 += __shfl_xor_sync(0xffffffffu, sm0, off);
            sm1 += __shfl_xor_sync(0xffffffffu, sm1, off);
        }
        lsum[0] = lsum[0] * cr0 + sm0;
        lsum[1] = lsum[1] * cr1 + sm1;
        #pragma unroll
        for (int nf = 0; nf < 8; nf++) {
            o[nf][0] *= cr0; o[nf][1] *= cr0;
            o[nf][2] *= cr1; o[nf][3] *= cr1;
        }

        #pragma unroll
        for (int ks = 0; ks < 4; ks++) {
            uint32_t ah4[4], al4[4];
            const float* p0 = sc[ks * 2];
            const float* p1 = sc[ks * 2 + 1];
            ah4[0] = pack_hi(p0[0], p0[1]);  al4[0] = pack_lo(p0[0], p0[1]);
            ah4[1] = pack_hi(p0[2], p0[3]);  al4[1] = pack_lo(p0[2], p0[3]);
            ah4[2] = pack_hi(p1[0], p1[1]);  al4[2] = pack_lo(p1[0], p1[1]);
            ah4[3] = pack_hi(p1[2], p1[3]);  al4[3] = pack_lo(p1[2], p1[3]);
            #pragma unroll
            for (int dg = 0; dg < 4; dg++) {
                uint32_t vh4[4], vl4[4];
                const uint32_t vd = Vb
                    + (uint32_t)((ks * 16 + (lane & 7) + ((lane >> 3) & 1) * 8) * KVS_B)
                    + dg * 32 + (((lane >> 4) & 1) * 16);
                ldsm_x4_t(vh4, vd);
                ldsm_x4_t(vl4, vd + KVSPLIT);
                float* c0 = o[dg * 2];
                float* c1 = o[dg * 2 + 1];
                mma16816(c0, ah4, vh4);
                mma16816(c0, al4, vh4);
                mma16816(c0, ah4, vl4);
                mma16816(c1, ah4, vh4 + 2);
                mma16816(c1, al4, vh4 + 2);
                mma16816(c1, ah4, vl4 + 2);
            }
        }
        __syncthreads();
    }

    const float inv0 = 1.0f / lsum[0];
    const float inv1 = 1.0f / lsum[1];
    #pragma unroll
    for (int nf = 0; nf < 8; nf++) {
        const int col = h * HD + nf * 8 + colb;
        *(float2*)(outf + (size_t)qrow0 * DIM + col) = make_float2(o[nf][0] * inv0, o[nf][1] * inv0);
        *(float2*)(outf + (size_t)qrow1 * DIM + col) = make_float2(o[nf][2] * inv1, o[nf][3] * inv1);
    }
}

// ================= int8 two-digit GEMM v2 =================
// 512 threads, 16 warps (4x4), warp tile 32x32, CTA 128x128, 6-stage cp.async.
// C = Sa[m]*Sb[n]*(16384*Ch + 128*Cm)
#define IBM 128
#define IBN 128
#define IBK 32
#define IROWB 48
#define I_SPLIT (128 * IROWB)             // 6144
#define ISTAGE (4 * I_SPLIT)              // 24576
#define ISTAGES 6
#define IGSMEM (ISTAGES * ISTAGE)         // 147456

template <int MODE>
__global__ __launch_bounds__(512, 1) void gemm_i8(
    const int8_t* __restrict__ Ah8, const int8_t* __restrict__ Al8, const float* __restrict__ Sa,
    const int8_t* __restrict__ Bh8, const int8_t* __restrict__ Bl8, const float* __restrict__ Sb,
    int K, int Ntot,
    float* __restrict__ Cf, const float* __restrict__ res, const float* __restrict__ scale) {
    extern __shared__ char smem[];
    const uint32_t sb = smem_u32(smem);
    const int tid  = threadIdx.x;
    const int lane = tid & 31;
    const int wid  = tid >> 5;
    const int wm   = wid >> 2;            // 4 warp rows of 32
    const int wn   = wid & 3;             // 4 warp cols of 32
    const int m0 = blockIdx.y * IBM, n0 = blockIdx.x * IBN;

    int Ch[2][4][4], Cm[2][4][4];
    #pragma unroll
    for (int i = 0; i < 2; i++)
        #pragma unroll
        for (int j = 0; j < 4; j++)
            #pragma unroll
            for (int k = 0; k < 4; k++) { Ch[i][j][k] = 0; Cm[i][j][k] = 0; }

    // loads: warps 0-7 -> A digits, warps 8-15 -> B digits; each thread 2 cp16
    const int t2 = tid & 255;
    const int isB = tid >> 8;
    const int lrow = t2 >> 1, lcg = t2 & 1;
    auto load_stage = [&](int kc, int s) {
        const uint32_t base = sb + s * ISTAGE;
        const uint32_t off = (uint32_t)(lrow * IROWB + lcg * 16);
        if (!isB) {
            const size_t ga = (size_t)(m0 + lrow) * K + kc + lcg * 16;
            cp16(base + off,           Ah8 + ga);
            cp16(base + I_SPLIT + off, Al8 + ga);
        } else {
            const size_t gb = (size_t)(n0 + lrow) * K + kc + lcg * 16;
            cp16(base + 2 * I_SPLIT + off, Bh8 + gb);
            cp16(base + 3 * I_SPLIT + off, Bl8 + gb);
        }
        asm volatile("cp.async.commit_group;" ::: "memory");
    };

    const int NC = K / IBK;
    #pragma unroll
    for (int s = 0; s < 5; s++) load_stage(s * IBK, s);

    for (int c = 0; c < NC; c++) {
        asm volatile("cp.async.wait_group 4;" ::: "memory");
        __syncthreads();
        if (c + 5 < NC) load_stage((c + 5) * IBK, (c + 5) % ISTAGES);

        const uint32_t stb = sb + (c % ISTAGES) * ISTAGE;
        uint32_t ah[8], al[8];
        #pragma unroll
        for (int mf = 0; mf < 2; mf++) {
            const uint32_t ad = stb
                + (uint32_t)((wm * 32 + mf * 16 + (lane & 15)) * IROWB)
                + ((lane >> 4) * 16);
            ldsm_x4(ah + mf * 4, ad);
            ldsm_x4(al + mf * 4, ad + I_SPLIT);
        }
        #pragma unroll
        for (int g = 0; g < 2; g++) {
            uint32_t bh4[4], bl4[4];
            const uint32_t bd = stb + 2 * I_SPLIT
                + (uint32_t)((wn * 32 + g * 16 + ((lane >> 4) * 8) + (lane & 7)) * IROWB)
                + (((lane >> 3) & 1) * 16);
            ldsm_x4(bh4, bd);
            ldsm_x4(bl4, bd + I_SPLIT);
            #pragma unroll
            for (int mf = 0; mf < 2; mf++) {
                imma16832(Ch[mf][g * 2],     ah + mf * 4, bh4);
                imma16832(Cm[mf][g * 2],     al + mf * 4, bh4);
                imma16832(Cm[mf][g * 2],     ah + mf * 4, bl4);
                imma16832(Ch[mf][g * 2 + 1], ah + mf * 4, bh4 + 2);
                imma16832(Cm[mf][g * 2 + 1], al + mf * 4, bh4 + 2);
                imma16832(Cm[mf][g * 2 + 1], ah + mf * 4, bl4 + 2);
            }
        }
    }

    // ---- epilogue ----
    const int rb = m0 + wm * 32 + (lane >> 2);
    const int cb = n0 + wn * 32 + (lane & 3) * 2;
    #pragma unroll
    for (int mf = 0; mf < 2; mf++) {
        const int rr0 = rb + mf * 16;
        const int rr1 = rr0 + 8;
        const float sa0 = Sa[rr0], sa1 = Sa[rr1];
        #pragma unroll
        for (int nf = 0; nf < 4; nf++) {
            const int cn = cb + nf * 8;
            const float2 sbv = *(const float2*)(Sb + cn);
            const int* ch = Ch[mf][nf];
            const int* cm = Cm[mf][nf];
            float v0 = sa0 * sbv.x * (16384.f * (float)ch[0] + 128.f * (float)cm[0]);
            float v1 = sa0 * sbv.y * (16384.f * (float)ch[1] + 128.f * (float)cm[1]);
            float v2 = sa1 * sbv.x * (16384.f * (float)ch[2] + 128.f * (float)cm[2]);
            float v3 = sa1 * sbv.y * (16384.f * (float)ch[3] + 128.f * (float)cm[3]);
            if (MODE == 1) {
                const float2 sc2 = *(const float2*)(scale + cn);
                const float2 q0 = *(const float2*)(res + (size_t)rr0 * Ntot + cn);
                const float2 q1 = *(const float2*)(res + (size_t)rr1 * Ntot + cn);
                v0 = q0.x + sc2.x * v0; v1 = q0.y + sc2.y * v1;
                v2 = q1.x + sc2.x * v2; v3 = q1.y + sc2.y * v3;
            } else if (MODE == 2) {
                v0 = fmaxf(v0, 0.f); v0 *= v0;
                v1 = fmaxf(v1, 0.f); v1 *= v1;
                v2 = fmaxf(v2, 0.f); v2 *= v2;
                v3 = fmaxf(v3, 0.f); v3 *= v3;
            }
            *(float2*)(Cf + (size_t)rr0 * Ntot + cn) = make_float2(v0, v1);
            *(float2*)(Cf + (size_t)rr1 * Ntot + cn) = make_float2(v2, v3);
        }
    }
}

// ================= host launcher =================
extern "C" void kernel_launch(void* const* d_in, const int* in_sizes, int n_in,
                              void* d_out, int out_size) {
    const float* x        = (const float*)d_in[0];
    const float* qkv_w    = (const float*)d_in[1];
    const float* o_w      = (const float*)d_in[2];
    const float* o_scale  = (const float*)d_in[3];
    const float* w1       = (const float*)d_in[4];
    const float* w2       = (const float*)d_in[5];
    const float* w2_scale = (const float*)d_in[6];
    float* out = (float*)d_out;

    float *qkv, *x1, *attn, *hf;
    float2* rope;
    cudaGetSymbolAddress((void**)&qkv,  g_qkv);
    cudaGetSymbolAddress((void**)&x1,   g_x1);
    cudaGetSymbolAddress((void**)&attn, g_attn);
    cudaGetSymbolAddress((void**)&hf,   g_hf);
    cudaGetSymbolAddress((void**)&rope, g_rope);
    __nv_bfloat16 *qh, *ql, *kh, *kl, *vh, *vl;
    cudaGetSymbolAddress((void**)&qh, g_qh); cudaGetSymbolAddress((void**)&ql, g_ql);
    cudaGetSymbolAddress((void**)&kh, g_kh); cudaGetSymbolAddress((void**)&kl, g_kl);
    cudaGetSymbolAddress((void**)&vh, g_vh); cudaGetSymbolAddress((void**)&vl, g_vl);
    int8_t *xqh, *xql, *aqh, *aql, *x1qh, *x1ql, *hqh, *hql;
    int8_t *wqh, *wql, *woh, *wol, *w1h, *w1l, *w2h, *w2l;
    float *sx, *sa, *sx1, *sh, *swq, *swo, *sw1, *sw2;
    cudaGetSymbolAddress((void**)&xqh,  g_xq_h);  cudaGetSymbolAddress((void**)&xql,  g_xq_l);
    cudaGetSymbolAddress((void**)&aqh,  g_aq_h);  cudaGetSymbolAddress((void**)&aql,  g_aq_l);
    cudaGetSymbolAddress((void**)&x1qh, g_x1q_h); cudaGetSymbolAddress((void**)&x1ql, g_x1q_l);
    cudaGetSymbolAddress((void**)&hqh,  g_hq_h);  cudaGetSymbolAddress((void**)&hql,  g_hq_l);
    cudaGetSymbolAddress((void**)&wqh,  g_wq_h);  cudaGetSymbolAddress((void**)&wql,  g_wq_l);
    cudaGetSymbolAddress((void**)&woh,  g_wo_h);  cudaGetSymbolAddress((void**)&wol,  g_wo_l);
    cudaGetSymbolAddress((void**)&w1h,  g_w1_h);  cudaGetSymbolAddress((void**)&w1l,  g_w1_l);
    cudaGetSymbolAddress((void**)&w2h,  g_w2_h);  cudaGetSymbolAddress((void**)&w2l,  g_w2_l);
    cudaGetSymbolAddress((void**)&sx,  g_sx);  cudaGetSymbolAddress((void**)&sa,  g_sa);
    cudaGetSymbolAddress((void**)&sx1, g_sx1); cudaGetSymbolAddress((void**)&sh,  g_sh);
    cudaGetSymbolAddress((void**)&swq, g_swq); cudaGetSymbolAddress((void**)&swo, g_swo);
    cudaGetSymbolAddress((void**)&sw1, g_sw1); cudaGetSymbolAddress((void**)&sw2, g_sw2);

    cudaFuncSetAttribute(gemm_i8<0>, cudaFuncAttributeMaxDynamicSharedMemorySize, IGSMEM);
    cudaFuncSetAttribute(gemm_i8<1>, cudaFuncAttributeMaxDynamicSharedMemorySize, IGSMEM);
    cudaFuncSetAttribute(gemm_i8<2>, cudaFuncAttributeMaxDynamicSharedMemorySize, IGSMEM);
    cudaFuncSetAttribute(attn_mma, cudaFuncAttributeMaxDynamicSharedMemorySize, ATTN_SMEM);

    // 1. all weight quantizations
    quant_weights<<<9216, 256>>>(qkv_w, o_w, w1, w2,
                                 wqh, wql, swq, woh, wol, swo,
                                 w1h, w1l, sw1, w2h, w2l, sw2);
    // 2. xn = rmsnorm(x) -> int8 digits
    rmsnorm_quant<<<T_LEN, 256>>>(x, xqh, xql, sx);
    // 3. rope table
    rope_tab<<<256, 256>>>(rope);
    // 4. qkv = xn @ qkv_w^T   <-- profiled slot
    gemm_i8<0><<<dim3(QKV_DIM / IBN, T_LEN / IBM), 512, IGSMEM>>>(
        xqh, xql, sx, wqh, wql, swq, DIM, QKV_DIM, qkv, nullptr, nullptr);
    // 5. q/k norm+rope, v -> bf16 hi/lo
    qk_prep<<<dim3(T_LEN, 6), 256>>>(qkv, rope, qh, ql, kh, kl, vh, vl);
    // 6. attention -> fp32
    attn_mma<<<dim3(T_LEN / 64, NHEADS), 128, ATTN_SMEM>>>(qh, ql, kh, kl, vh, vl, attn);
    // 7. quantize attention output
    quant_rows<<<T_LEN, 256>>>(attn, DIM, aqh, aql, sa);
    // 8. x1 = x + o_scale[n] * (attn @ o_w^T)
    gemm_i8<1><<<dim3(DIM / IBN, T_LEN / IBM), 512, IGSMEM>>>(
        aqh, aql, sa, woh, wol, swo, DIM, DIM, x1, x, o_scale);
    // 9. x1n = rmsnorm(x1) -> int8 digits
    rmsnorm_quant<<<T_LEN, 256>>>(x1, x1qh, x1ql, sx1);
    // 10. h = relu(x1n @ w1^T)^2 -> fp32
    gemm_i8<2><<<dim3(MLP_DIM / IBN, T_LEN / IBM), 512, IGSMEM>>>(
        x1qh, x1ql, sx1, w1h, w1l, sw1, DIM, MLP_DIM, hf, nullptr, nullptr);
    // 11. quantize h
    quant_rows<<<T_LEN, 256>>>(hf, MLP_DIM, hqh, hql, sh);
    // 12. out = x1 + w2_scale[n] * (h @ w2^T)
    gemm_i8<1><<<dim3(DIM / IBN, T_LEN / IBM), 512, IGSMEM>>>(
        hqh, hql, sh, w2h, w2l, sw2, MLP_DIM, DIM, out, x1, w2_scale);
}

// round 9
// speedup vs baseline: 4.1872x; 1.1121x over previous
#include <cuda_runtime.h>
#include <cuda_bf16.h>
#include <math_constants.h>
#include <cstdint>

#define T_LEN   4096
#define DIM     1024
#define QKV_DIM 3072
#define MLP_DIM 4096
#define NHEADS  16
#define HD      64
#define WIN     512
#define EPS_F   1.1920929e-07f
#define QMAX    16256.0f            // 127*128

// ================= helpers =================
__device__ __forceinline__ uint32_t smem_u32(const void* p) {
    uint32_t a;
    asm("{ .reg .u64 t; cvta.to.shared.u64 t, %1; cvt.u32.u64 %0, t; }" : "=r"(a) : "l"(p));
    return a;
}
__device__ __forceinline__ void cp16(uint32_t s, const void* g) {
    asm volatile("cp.async.cg.shared.global [%0], [%1], 16;" :: "r"(s), "l"(g));
}
__device__ __forceinline__ void ldsm_x4(uint32_t* r, uint32_t addr) {
    asm volatile("ldmatrix.sync.aligned.m8n8.x4.shared.b16 {%0,%1,%2,%3}, [%4];"
                 : "=r"(r[0]), "=r"(r[1]), "=r"(r[2]), "=r"(r[3]) : "r"(addr));
}
__device__ __forceinline__ void ldsm_x4_t(uint32_t* r, uint32_t addr) {
    asm volatile("ldmatrix.sync.aligned.m8n8.x4.trans.shared.b16 {%0,%1,%2,%3}, [%4];"
                 : "=r"(r[0]), "=r"(r[1]), "=r"(r[2]), "=r"(r[3]) : "r"(addr));
}
__device__ __forceinline__ void mma16816(float* c, const uint32_t* a, const uint32_t* b) {
    asm volatile("mma.sync.aligned.m16n8k16.row.col.f32.bf16.bf16.f32 "
        "{%0,%1,%2,%3}, {%4,%5,%6,%7}, {%8,%9}, {%0,%1,%2,%3};"
        : "+f"(c[0]), "+f"(c[1]), "+f"(c[2]), "+f"(c[3])
        : "r"(a[0]), "r"(a[1]), "r"(a[2]), "r"(a[3]), "r"(b[0]), "r"(b[1]));
}
__device__ __forceinline__ void imma16832(int* c, const uint32_t* a, const uint32_t* b) {
    asm volatile("mma.sync.aligned.m16n8k32.row.col.s32.s8.s8.s32 "
        "{%0,%1,%2,%3}, {%4,%5,%6,%7}, {%8,%9}, {%0,%1,%2,%3};"
        : "+r"(c[0]), "+r"(c[1]), "+r"(c[2]), "+r"(c[3])
        : "r"(a[0]), "r"(a[1]), "r"(a[2]), "r"(a[3]), "r"(b[0]), "r"(b[1]));
}
__device__ __forceinline__ void split_bf16(float a, __nv_bfloat16& hi, __nv_bfloat16& lo) {
    hi = __float2bfloat16(a);
    lo = __float2bfloat16(a - __bfloat162float(hi));
}
__device__ __forceinline__ uint32_t pack2(__nv_bfloat16 a, __nv_bfloat16 b) {
    return (uint32_t)__bfloat16_as_ushort(a) | ((uint32_t)__bfloat16_as_ushort(b) << 16);
}
__device__ __forceinline__ uint32_t pack_hi(float a, float b) {
    return pack2(__float2bfloat16(a), __float2bfloat16(b));
}
__device__ __forceinline__ uint32_t pack_lo(float a, float b) {
    __nv_bfloat16 ha = __float2bfloat16(a), hb = __float2bfloat16(b);
    return pack2(__float2bfloat16(a - __bfloat162float(ha)),
                 __float2bfloat16(b - __bfloat162float(hb)));
}

// ================= scratch =================
__device__ float g_qkv [T_LEN * QKV_DIM];
__device__ float g_x1  [T_LEN * DIM];
__device__ float g_attn[T_LEN * DIM];
__device__ float g_hf  [T_LEN * MLP_DIM];
__device__ float2 g_rope[T_LEN * 16];

#define BF16A __device__ __align__(16) __nv_bfloat16
BF16A g_qh[T_LEN * DIM]; BF16A g_ql[T_LEN * DIM];
BF16A g_kh[T_LEN * DIM]; BF16A g_kl[T_LEN * DIM];
BF16A g_vh[T_LEN * DIM]; BF16A g_vl[T_LEN * DIM];

#define I8A __device__ __align__(16) int8_t
I8A g_xq_h [T_LEN * DIM];     I8A g_xq_l [T_LEN * DIM];     __device__ float g_sx [T_LEN];
I8A g_aq_h [T_LEN * DIM];     I8A g_aq_l [T_LEN * DIM];     __device__ float g_sa [T_LEN];
I8A g_x1q_h[T_LEN * DIM];     I8A g_x1q_l[T_LEN * DIM];     __device__ float g_sx1[T_LEN];
I8A g_hq_h [T_LEN * MLP_DIM]; I8A g_hq_l [T_LEN * MLP_DIM]; __device__ float g_sh [T_LEN];
I8A g_wq_h [QKV_DIM * DIM];   I8A g_wq_l [QKV_DIM * DIM];   __device__ float g_swq[QKV_DIM];
I8A g_wo_h [DIM * DIM];       I8A g_wo_l [DIM * DIM];       __device__ float g_swo[DIM];
I8A g_w1_h [MLP_DIM * DIM];   I8A g_w1_l [MLP_DIM * DIM];   __device__ float g_sw1[MLP_DIM];
I8A g_w2_h [DIM * MLP_DIM];   I8A g_w2_l [DIM * MLP_DIM];   __device__ float g_sw2[DIM];

// ================= row quantization =================
__device__ __forceinline__ float block_max256(float v, float* red) {
    #pragma unroll
    for (int off = 16; off; off >>= 1) v = fmaxf(v, __shfl_xor_sync(0xffffffffu, v, off));
    if ((threadIdx.x & 31) == 0) red[threadIdx.x >> 5] = v;
    __syncthreads();
    float m = red[0];
    #pragma unroll
    for (int i = 1; i < 8; i++) m = fmaxf(m, red[i]);
    return m;
}
__device__ __forceinline__ void quant4(float4 v, float inv128, float s128, float invS,
                                       char4& qh, char4& ql) {
    float h0 = rintf(v.x * inv128), h1 = rintf(v.y * inv128);
    float h2 = rintf(v.z * inv128), h3 = rintf(v.w * inv128);
    qh = make_char4((signed char)__float2int_rn(h0), (signed char)__float2int_rn(h1),
                    (signed char)__float2int_rn(h2), (signed char)__float2int_rn(h3));
    ql = make_char4((signed char)__float2int_rn((v.x - h0 * s128) * invS),
                    (signed char)__float2int_rn((v.y - h1 * s128) * invS),
                    (signed char)__float2int_rn((v.z - h2 * s128) * invS),
                    (signed char)__float2int_rn((v.w - h3 * s128) * invS));
}

__device__ __forceinline__ void quant_row_body(const float* __restrict__ src, int ncols,
                                               int8_t* __restrict__ qh, int8_t* __restrict__ ql,
                                               float* __restrict__ Srow, int row) {
    __shared__ float red[8];
    const float* r = src + (size_t)row * ncols;
    const int tid = threadIdx.x;
    const int n4 = ncols >> 2;
    float amax = 0.f;
    for (int i = tid; i < n4; i += 256) {
        float4 v = ((const float4*)r)[i];
        amax = fmaxf(amax, fmaxf(fmaxf(fabsf(v.x), fabsf(v.y)), fmaxf(fabsf(v.z), fabsf(v.w))));
    }
    const float m = block_max256(amax, red);
    const float S = fmaxf(m, 1e-20f) * (1.0f / QMAX);
    const float inv128 = 1.0f / (128.0f * S), s128 = 128.0f * S, invS = 1.0f / S;
    for (int i = tid; i < n4; i += 256) {
        float4 v = ((const float4*)r)[i];
        char4 h4, l4;
        quant4(v, inv128, s128, invS, h4, l4);
        ((char4*)(qh + (size_t)row * ncols))[i] = h4;
        ((char4*)(ql + (size_t)row * ncols))[i] = l4;
    }
    if (tid == 0) Srow[row] = S;
}

__global__ __launch_bounds__(256) void quant_rows(const float* __restrict__ src, int ncols,
                                                  int8_t* __restrict__ qh, int8_t* __restrict__ ql,
                                                  float* __restrict__ S) {
    quant_row_body(src, ncols, qh, ql, S, blockIdx.x);
}

__global__ __launch_bounds__(256) void quant_weights(
    const float* qkv_w, const float* o_w, const float* w1, const float* w2,
    int8_t* wqh, int8_t* wql, float* swq,
    int8_t* woh, int8_t* wol, float* swo,
    int8_t* w1h, int8_t* w1l, float* sw1,
    int8_t* w2h, int8_t* w2l, float* sw2) {
    int r = blockIdx.x;
    if (r < 3072)       quant_row_body(qkv_w, 1024, wqh, wql, swq, r);
    else if (r < 4096)  quant_row_body(o_w,   1024, woh, wol, swo, r - 3072);
    else if (r < 8192)  quant_row_body(w1,    1024, w1h, w1l, sw1, r - 4096);
    else                quant_row_body(w2,    4096, w2h, w2l, sw2, r - 8192);
}

// ================= rmsnorm -> int8 two-digit =================
__global__ __launch_bounds__(256) void rmsnorm_quant(const float* __restrict__ x,
                                                     int8_t* __restrict__ qh,
                                                     int8_t* __restrict__ ql,
                                                     float* __restrict__ S) {
    __shared__ float red[8], redm[8];
    const int row = blockIdx.x;
    const int tid = threadIdx.x;
    float4 v = ((const float4*)(x + (size_t)row * DIM))[tid];
    float ss = v.x * v.x + v.y * v.y + v.z * v.z + v.w * v.w;
    float am = fmaxf(fmaxf(fabsf(v.x), fabsf(v.y)), fmaxf(fabsf(v.z), fabsf(v.w)));
    #pragma unroll
    for (int off = 16; off; off >>= 1) {
        ss += __shfl_xor_sync(0xffffffffu, ss, off);
        am = fmaxf(am, __shfl_xor_sync(0xffffffffu, am, off));
    }
    if ((tid & 31) == 0) { red[tid >> 5] = ss; redm[tid >> 5] = am; }
    __syncthreads();
    float tot = 0.f, m = 0.f;
    #pragma unroll
    for (int i = 0; i < 8; i++) { tot += red[i]; m = fmaxf(m, redm[i]); }
    const float r = rsqrtf(tot * (1.0f / DIM) + EPS_F);
    v.x *= r; v.y *= r; v.z *= r; v.w *= r;
    const float Sv = fmaxf(m * r, 1e-20f) * (1.0f / QMAX);
    const float inv128 = 1.0f / (128.0f * Sv), s128 = 128.0f * Sv, invS = 1.0f / Sv;
    char4 h4, l4;
    quant4(v, inv128, s128, invS, h4, l4);
    ((char4*)(qh + (size_t)row * DIM))[tid] = h4;
    ((char4*)(ql + (size_t)row * DIM))[tid] = l4;
    if (tid == 0) S[row] = Sv;
}

// ================= rope table =================
__global__ __launch_bounds__(256) void rope_tab(float2* __restrict__ tab) {
    const int idx = blockIdx.x * 256 + threadIdx.x;
    const int t = idx >> 4, j = idx & 15;
    const float f = powf(1e-4f, (float)j * (1.0f / 15.0f));
    float sn, cs;
    sincosf((float)t * f, &sn, &cs);
    tab[idx] = make_float2(cs, sn);
}

// ================= per-head q/k rmsnorm + rope; v split -> bf16 hi/lo =================
__global__ __launch_bounds__(256) void qk_prep(const float* __restrict__ qkv,
                                               const float2* __restrict__ rope,
                                               __nv_bfloat16* __restrict__ qh, __nv_bfloat16* __restrict__ ql,
                                               __nv_bfloat16* __restrict__ kh, __nv_bfloat16* __restrict__ kl,
                                               __nv_bfloat16* __restrict__ vh, __nv_bfloat16* __restrict__ vl) {
    const int t    = blockIdx.x;
    const int idx  = blockIdx.y * 8 + (threadIdx.x >> 5);
    const int lane = threadIdx.x & 31;
    const int head = idx & 15;
    const size_t dsto = (size_t)t * DIM + head * HD;
    __nv_bfloat16 *dh, *dl;
    const float* src;
    if (idx < 16) {
        src = qkv + (size_t)t * QKV_DIM + head * HD;
        dh = qh + dsto; dl = ql + dsto;
    } else if (idx < 32) {
        src = qkv + (size_t)t * QKV_DIM + DIM + head * HD;
        dh = kh + dsto; dl = kl + dsto;
    } else {
        src = qkv + (size_t)t * QKV_DIM + 2 * DIM + head * HD;
        dh = vh + dsto; dl = vl + dsto;
    }
    float a = src[lane];
    float b = src[lane + 32];
    if (idx < 32) {
        float ss = a * a + b * b;
        #pragma unroll
        for (int off = 16; off; off >>= 1) ss += __shfl_xor_sync(0xffffffffu, ss, off);
        const float r = rsqrtf(ss * (1.0f / HD) + EPS_F);
        a *= r; b *= r;
        float sn = 0.f, cs = 1.f;
        if (lane < 16) {
            const float2 e = rope[t * 16 + lane];
            cs = e.x; sn = e.y;
        }
        const float y1 =  a * cs + b * sn;
        const float y2 = -a * sn + b * cs;
        a = y1; b = y2;
    }
    __nv_bfloat16 ha, la, hb, lb;
    split_bf16(a, ha, la);
    split_bf16(b, hb, lb);
    dh[lane] = ha;      dl[lane] = la;
    dh[lane + 32] = hb; dl[lane + 32] = lb;
}

// ================= tensor-core sliding-window attention =================
#define KVS_B 144
#define KVSPLIT 9216
#define ABUF (2 * KVSPLIT)
#define KVBUF (4 * KVSPLIT)
#define ATTN_SMEM (ABUF + 2 * KVBUF)    // 92160

__global__ __launch_bounds__(128) void attn_mma(
    const __nv_bfloat16* __restrict__ qh, const __nv_bfloat16* __restrict__ ql,
    const __nv_bfloat16* __restrict__ kh, const __nv_bfloat16* __restrict__ kl,
    const __nv_bfloat16* __restrict__ vh, const __nv_bfloat16* __restrict__ vl,
    float* __restrict__ outf) {
    extern __shared__ char smem[];
    const uint32_t sb = smem_u32(smem);
    const int h    = blockIdx.y;
    const int q0   = blockIdx.x * 64;
    const int tid  = threadIdx.x;
    const int wid  = tid >> 5;
    const int lane = tid & 31;

    #pragma unroll
    for (int it = 0; it < 4; it++) {
        const int g = tid + it * 128;
        const int row = g >> 3, cg = g & 7;
        const size_t src = (size_t)(q0 + row) * DIM + h * HD + cg * 8;
        const uint32_t off = (uint32_t)(row * KVS_B + cg * 16);
        cp16(sb + off, qh + src);
        cp16(sb + KVSPLIT + off, ql + src);
    }
    asm volatile("cp.async.commit_group;" ::: "memory");

    auto load_kv = [&](int kc, int buf) {
        const uint32_t base = sb + ABUF + buf * KVBUF;
        #pragma unroll
        for (int it = 0; it < 4; it++) {
            const int g = tid + it * 128;
            const int row = g >> 3, cg = g & 7;
            const size_t src = (size_t)(kc + row) * DIM + h * HD + cg * 8;
            const uint32_t off = (uint32_t)(row * KVS_B + cg * 16);
            cp16(base + off, kh + src);
            cp16(base + KVSPLIT + off, kl + src);
            cp16(base + 2 * KVSPLIT + off, vh + src);
            cp16(base + 3 * KVSPLIT + off, vl + src);
        }
        asm volatile("cp.async.commit_group;" ::: "memory");
    };

    const int kc0 = (q0 >= WIN) ? (q0 - WIN) : 0;
    const int nch = (q0 + 64 - kc0) >> 6;
    load_kv(kc0, 0);

    asm volatile("cp.async.wait_group 1;" ::: "memory");
    __syncthreads();
    uint32_t qfh[16], qfl[16];
    #pragma unroll
    for (int ks = 0; ks < 4; ks++) {
        const uint32_t ad = sb + (uint32_t)((wid * 16 + (lane & 15)) * KVS_B)
                          + ((lane >> 4) * 16) + ks * 32;
        ldsm_x4(qfh + ks * 4, ad);
        ldsm_x4(qfl + ks * 4, ad + KVSPLIT);
    }

    float m[2] = {-1e30f, -1e30f}, lsum[2] = {0.f, 0.f};
    float o[8][4];
    #pragma unroll
    for (int i = 0; i < 8; i++)
        #pragma unroll
        for (int j = 0; j < 4; j++) o[i][j] = 0.f;

    const int r0 = lane >> 2;
    const int qrow0 = q0 + wid * 16 + r0;
    const int qrow1 = qrow0 + 8;
    const int colb = (lane & 3) * 2;

    for (int c = 0; c < nch; c++) {
        const int b = c & 1;
        const int kc = kc0 + c * 64;
        if (c + 1 < nch) load_kv(kc + 64, b ^ 1);
        if (c + 1 < nch) { asm volatile("cp.async.wait_group 1;" ::: "memory"); }
        else             { asm volatile("cp.async.wait_group 0;" ::: "memory"); }
        __syncthreads();

        const uint32_t Kb = sb + ABUF + b * KVBUF;
        const uint32_t Vb = Kb + 2 * KVSPLIT;

        float sc[8][4];
        #pragma unroll
        for (int i = 0; i < 8; i++)
            #pragma unroll
            for (int j = 0; j < 4; j++) sc[i][j] = 0.f;
        #pragma unroll
        for (int ks = 0; ks < 4; ks++) {
            #pragma unroll
            for (int np = 0; np < 4; np++) {
                uint32_t bh4[4], bl4[4];
                const uint32_t bd = Kb
                    + (uint32_t)((np * 16 + ((lane >> 4) * 8) + (lane & 7)) * KVS_B)
                    + (((lane >> 3) & 1) * 16) + ks * 32;
                ldsm_x4(bh4, bd);
                ldsm_x4(bl4, bd + KVSPLIT);
                float* c0 = sc[np * 2];
                float* c1 = sc[np * 2 + 1];
                mma16816(c0, qfh + ks * 4, bh4);
                mma16816(c0, qfl + ks * 4, bh4);
                mma16816(c0, qfh + ks * 4, bl4);
                mma16816(c1, qfh + ks * 4, bh4 + 2);
                mma16816(c1, qfl + ks * 4, bh4 + 2);
                mma16816(c1, qfh + ks * 4, bl4 + 2);
            }
        }

        #pragma unroll
        for (int nf = 0; nf < 8; nf++) {
            #pragma unroll
            for (int j = 0; j < 4; j++) {
                const int kg = kc + nf * 8 + colb + (j & 1);
                const int q  = (j < 2) ? qrow0 : qrow1;
                const bool valid = (kg <= q) && (kg > q - WIN);
                sc[nf][j] = valid ? sc[nf][j] * 0.125f : -1e30f;
            }
        }
        float mx0 = -1e30f, mx1 = -1e30f;
        #pragma unroll
        for (int nf = 0; nf < 8; nf++) {
            mx0 = fmaxf(mx0, fmaxf(sc[nf][0], sc[nf][1]));
            mx1 = fmaxf(mx1, fmaxf(sc[nf][2], sc[nf][3]));
        }
        #pragma unroll
        for (int off = 1; off <= 2; off <<= 1) {
            mx0 = fmaxf(mx0, __shfl_xor_sync(0xffffffffu, mx0, off));
            mx1 = fmaxf(mx1, __shfl_xor_sync(0xffffffffu, mx1, off));
        }
        const float mn0 = fmaxf(m[0], mx0);
        const float mn1 = fmaxf(m[1], mx1);
        const float cr0 = __expf(m[0] - mn0);
        const float cr1 = __expf(m[1] - mn1);
        m[0] = mn0; m[1] = mn1;
        float sm0 = 0.f, sm1 = 0.f;
        #pragma unroll
        for (int nf = 0; nf < 8; nf++) {
            sc[nf][0] = __expf(sc[nf][0] - mn0);
            sc[nf][1] = __expf(sc[nf][1] - mn0);
            sc[nf][2] = __expf(sc[nf][2] - mn1);
            sc[nf][3] = __expf(sc[nf][3] - mn1);
            sm0 += sc[nf][0] + sc[nf][1];
            sm1 += sc[nf][2] + sc[nf][3];
        }
        #pragma unroll
        for (int off = 1; off <= 2; off <<= 1) {
            sm0 += __shfl_xor_sync(0xffffffffu, sm0, off);
            sm1 += __shfl_xor_sync(0xffffffffu, sm1, off);
        }
        lsum[0] = lsum[0] * cr0 + sm0;
        lsum[1] = lsum[1] * cr1 + sm1;
        #pragma unroll
        for (int nf = 0; nf < 8; nf++) {
            o[nf][0] *= cr0; o[nf][1] *= cr0;
            o[nf][2] *= cr1; o[nf][3] *= cr1;
        }

        #pragma unroll
        for (int ks = 0; ks < 4; ks++) {
            uint32_t ah4[4], al4[4];
            const float* p0 = sc[ks * 2];
            const float* p1 = sc[ks * 2 + 1];
            ah4[0] = pack_hi(p0[0], p0[1]);  al4[0] = pack_lo(p0[0], p0[1]);
            ah4[1] = pack_hi(p0[2], p0[3]);  al4[1] = pack_lo(p0[2], p0[3]);
            ah4[2] = pack_hi(p1[0], p1[1]);  al4[2] = pack_lo(p1[0], p1[1]);
            ah4[3] = pack_hi(p1[2], p1[3]);  al4[3] = pack_lo(p1[2], p1[3]);
            #pragma unroll
            for (int dg = 0; dg < 4; dg++) {
                uint32_t vh4[4], vl4[4];
                const uint32_t vd = Vb
                    + (uint32_t)((ks * 16 + (lane & 7) + ((lane >> 3) & 1) * 8) * KVS_B)
                    + dg * 32 + (((lane >> 4) & 1) * 16);
                ldsm_x4_t(vh4, vd);
                ldsm_x4_t(vl4, vd + KVSPLIT);
                float* c0 = o[dg * 2];
                float* c1 = o[dg * 2 + 1];
                mma16816(c0, ah4, vh4);
                mma16816(c0, al4, vh4);
                mma16816(c0, ah4, vl4);
                mma16816(c1, ah4, vh4 + 2);
                mma16816(c1, al4, vh4 + 2);
                mma16816(c1, ah4, vl4 + 2);
            }
        }
        __syncthreads();
    }

    const float inv0 = 1.0f / lsum[0];
    const float inv1 = 1.0f / lsum[1];
    #pragma unroll
    for (int nf = 0; nf < 8; nf++) {
        const int col = h * HD + nf * 8 + colb;
        *(float2*)(outf + (size_t)qrow0 * DIM + col) = make_float2(o[nf][0] * inv0, o[nf][1] * inv0);
        *(float2*)(outf + (size_t)qrow1 * DIM + col) = make_float2(o[nf][2] * inv1, o[nf][3] * inv1);
    }
}

// ================= int8 two-digit GEMM v3 =================
// 512 threads, 16 warps (4x4), warp tile 32x32, CTA 128x128, IBK=64, 4-stage.
// Long barrier-free compute region (2 k-halves) overlaps ldsm with imma.
// C = Sa[m]*Sb[n]*(16384*Ch + 128*Cm)
#define IBM 128
#define IBN 128
#define IBK 64
#define IROWB 80                          // 64 B data + 16 B pad
#define I_SPLIT (128 * IROWB)             // 10240
#define ISTAGE (4 * I_SPLIT)              // 40960
#define ISTAGES 4
#define IGSMEM (ISTAGES * ISTAGE)         // 163840

template <int MODE>
__global__ __launch_bounds__(512, 1) void gemm_i8(
    const int8_t* __restrict__ Ah8, const int8_t* __restrict__ Al8, const float* __restrict__ Sa,
    const int8_t* __restrict__ Bh8, const int8_t* __restrict__ Bl8, const float* __restrict__ Sb,
    int K, int Ntot,
    float* __restrict__ Cf, const float* __restrict__ res, const float* __restrict__ scale) {
    extern __shared__ char smem[];
    const uint32_t sb = smem_u32(smem);
    const int tid  = threadIdx.x;
    const int lane = tid & 31;
    const int wid  = tid >> 5;
    const int wm   = wid >> 2;            // 4 warp rows of 32
    const int wn   = wid & 3;             // 4 warp cols of 32
    const int m0 = blockIdx.y * IBM, n0 = blockIdx.x * IBN;

    int Ch[2][4][4], Cm[2][4][4];
    #pragma unroll
    for (int i = 0; i < 2; i++)
        #pragma unroll
        for (int j = 0; j < 4; j++)
            #pragma unroll
            for (int k = 0; k < 4; k++) { Ch[i][j][k] = 0; Cm[i][j][k] = 0; }

    // loads: each thread does 1 granule per split (128 rows x 4 cols of 16B)
    const int lrow = tid >> 2, lcg = tid & 3;
    auto load_stage = [&](int kc, int s) {
        const uint32_t base = sb + s * ISTAGE;
        const uint32_t off = (uint32_t)(lrow * IROWB + lcg * 16);
        const size_t ga = (size_t)(m0 + lrow) * K + kc + lcg * 16;
        const size_t gb = (size_t)(n0 + lrow) * K + kc + lcg * 16;
        cp16(base + off,               Ah8 + ga);
        cp16(base + I_SPLIT + off,     Al8 + ga);
        cp16(base + 2 * I_SPLIT + off, Bh8 + gb);
        cp16(base + 3 * I_SPLIT + off, Bl8 + gb);
        asm volatile("cp.async.commit_group;" ::: "memory");
    };

    const int NC = K / IBK;
    #pragma unroll
    for (int s = 0; s < 3; s++) load_stage(s * IBK, s);

    for (int c = 0; c < NC; c++) {
        asm volatile("cp.async.wait_group 2;" ::: "memory");
        __syncthreads();
        if (c + 3 < NC) load_stage((c + 3) * IBK, (c + 3) % ISTAGES);

        const uint32_t stb = sb + (c % ISTAGES) * ISTAGE;
        #pragma unroll
        for (int kh = 0; kh < 2; kh++) {
            uint32_t ah[8], al[8];
            #pragma unroll
            for (int mf = 0; mf < 2; mf++) {
                const uint32_t ad = stb
                    + (uint32_t)((wm * 32 + mf * 16 + (lane & 15)) * IROWB)
                    + ((lane >> 4) * 16) + kh * 32;
                ldsm_x4(ah + mf * 4, ad);
                ldsm_x4(al + mf * 4, ad + I_SPLIT);
            }
            #pragma unroll
            for (int g = 0; g < 2; g++) {
                uint32_t bh4[4], bl4[4];
                const uint32_t bd = stb + 2 * I_SPLIT
                    + (uint32_t)((wn * 32 + g * 16 + ((lane >> 4) * 8) + (lane & 7)) * IROWB)
                    + (((lane >> 3) & 1) * 16) + kh * 32;
                ldsm_x4(bh4, bd);
                ldsm_x4(bl4, bd + I_SPLIT);
                #pragma unroll
                for (int mf = 0; mf < 2; mf++) {
                    imma16832(Ch[mf][g * 2],     ah + mf * 4, bh4);
                    imma16832(Cm[mf][g * 2],     al + mf * 4, bh4);
                    imma16832(Cm[mf][g * 2],     ah + mf * 4, bl4);
                    imma16832(Ch[mf][g * 2 + 1], ah + mf * 4, bh4 + 2);
                    imma16832(Cm[mf][g * 2 + 1], al + mf * 4, bh4 + 2);
                    imma16832(Cm[mf][g * 2 + 1], ah + mf * 4, bl4 + 2);
                }
            }
        }
    }

    // ---- epilogue ----
    const int rb = m0 + wm * 32 + (lane >> 2);
    const int cb = n0 + wn * 32 + (lane & 3) * 2;
    #pragma unroll
    for (int mf = 0; mf < 2; mf++) {
        const int rr0 = rb + mf * 16;
        const int rr1 = rr0 + 8;
        const float sa0 = Sa[rr0], sa1 = Sa[rr1];
        #pragma unroll
        for (int nf = 0; nf < 4; nf++) {
            const int cn = cb + nf * 8;
            const float2 sbv = *(const float2*)(Sb + cn);
            const int* ch = Ch[mf][nf];
            const int* cm = Cm[mf][nf];
            float v0 = sa0 * sbv.x * (16384.f * (float)ch[0] + 128.f * (float)cm[0]);
            float v1 = sa0 * sbv.y * (16384.f * (float)ch[1] + 128.f * (float)cm[1]);
            float v2 = sa1 * sbv.x * (16384.f * (float)ch[2] + 128.f * (float)cm[2]);
            float v3 = sa1 * sbv.y * (16384.f * (float)ch[3] + 128.f * (float)cm[3]);
            if (MODE == 1) {
                const float2 sc2 = *(const float2*)(scale + cn);
                const float2 q0 = *(const float2*)(res + (size_t)rr0 * Ntot + cn);
                const float2 q1 = *(const float2*)(res + (size_t)rr1 * Ntot + cn);
                v0 = q0.x + sc2.x * v0; v1 = q0.y + sc2.y * v1;
                v2 = q1.x + sc2.x * v2; v3 = q1.y + sc2.y * v3;
            } else if (MODE == 2) {
                v0 = fmaxf(v0, 0.f); v0 *= v0;
                v1 = fmaxf(v1, 0.f); v1 *= v1;
                v2 = fmaxf(v2, 0.f); v2 *= v2;
                v3 = fmaxf(v3, 0.f); v3 *= v3;
            }
            *(float2*)(Cf + (size_t)rr0 * Ntot + cn) = make_float2(v0, v1);
            *(float2*)(Cf + (size_t)rr1 * Ntot + cn) = make_float2(v2, v3);
        }
    }
}

// ================= host launcher =================
extern "C" void kernel_launch(void* const* d_in, const int* in_sizes, int n_in,
                              void* d_out, int out_size) {
    const float* x        = (const float*)d_in[0];
    const float* qkv_w    = (const float*)d_in[1];
    const float* o_w      = (const float*)d_in[2];
    const float* o_scale  = (const float*)d_in[3];
    const float* w1       = (const float*)d_in[4];
    const float* w2       = (const float*)d_in[5];
    const float* w2_scale = (const float*)d_in[6];
    float* out = (float*)d_out;

    float *qkv, *x1, *attn, *hf;
    float2* rope;
    cudaGetSymbolAddress((void**)&qkv,  g_qkv);
    cudaGetSymbolAddress((void**)&x1,   g_x1);
    cudaGetSymbolAddress((void**)&attn, g_attn);
    cudaGetSymbolAddress((void**)&hf,   g_hf);
    cudaGetSymbolAddress((void**)&rope, g_rope);
    __nv_bfloat16 *qh, *ql, *kh, *kl, *vh, *vl;
    cudaGetSymbolAddress((void**)&qh, g_qh); cudaGetSymbolAddress((void**)&ql, g_ql);
    cudaGetSymbolAddress((void**)&kh, g_kh); cudaGetSymbolAddress((void**)&kl, g_kl);
    cudaGetSymbolAddress((void**)&vh, g_vh); cudaGetSymbolAddress((void**)&vl, g_vl);
    int8_t *xqh, *xql, *aqh, *aql, *x1qh, *x1ql, *hqh, *hql;
    int8_t *wqh, *wql, *woh, *wol, *w1h, *w1l, *w2h, *w2l;
    float *sx, *sa, *sx1, *sh, *swq, *swo, *sw1, *sw2;
    cudaGetSymbolAddress((void**)&xqh,  g_xq_h);  cudaGetSymbolAddress((void**)&xql,  g_xq_l);
    cudaGetSymbolAddress((void**)&aqh,  g_aq_h);  cudaGetSymbolAddress((void**)&aql,  g_aq_l);
    cudaGetSymbolAddress((void**)&x1qh, g_x1q_h); cudaGetSymbolAddress((void**)&x1ql, g_x1q_l);
    cudaGetSymbolAddress((void**)&hqh,  g_hq_h);  cudaGetSymbolAddress((void**)&hql,  g_hq_l);
    cudaGetSymbolAddress((void**)&wqh,  g_wq_h);  cudaGetSymbolAddress((void**)&wql,  g_wq_l);
    cudaGetSymbolAddress((void**)&woh,  g_wo_h);  cudaGetSymbolAddress((void**)&wol,  g_wo_l);
    cudaGetSymbolAddress((void**)&w1h,  g_w1_h);  cudaGetSymbolAddress((void**)&w1l,  g_w1_l);
    cudaGetSymbolAddress((void**)&w2h,  g_w2_h);  cudaGetSymbolAddress((void**)&w2l,  g_w2_l);
    cudaGetSymbolAddress((void**)&sx,  g_sx);  cudaGetSymbolAddress((void**)&sa,  g_sa);
    cudaGetSymbolAddress((void**)&sx1, g_sx1); cudaGetSymbolAddress((void**)&sh,  g_sh);
    cudaGetSymbolAddress((void**)&swq, g_swq); cudaGetSymbolAddress((void**)&swo, g_swo);
    cudaGetSymbolAddress((void**)&sw1, g_sw1); cudaGetSymbolAddress((void**)&sw2, g_sw2);

    cudaFuncSetAttribute(gemm_i8<0>, cudaFuncAttributeMaxDynamicSharedMemorySize, IGSMEM);
    cudaFuncSetAttribute(gemm_i8<1>, cudaFuncAttributeMaxDynamicSharedMemorySize, IGSMEM);
    cudaFuncSetAttribute(gemm_i8<2>, cudaFuncAttributeMaxDynamicSharedMemorySize, IGSMEM);
    cudaFuncSetAttribute(attn_mma, cudaFuncAttributeMaxDynamicSharedMemorySize, ATTN_SMEM);

    // 1. all weight quantizations
    quant_weights<<<9216, 256>>>(qkv_w, o_w, w1, w2,
                                 wqh, wql, swq, woh, wol, swo,
                                 w1h, w1l, sw1, w2h, w2l, sw2);
    // 2. xn = rmsnorm(x) -> int8 digits
    rmsnorm_quant<<<T_LEN, 256>>>(x, xqh, xql, sx);
    // 3. rope table
    rope_tab<<<256, 256>>>(rope);
    // 4. qkv = xn @ qkv_w^T   <-- profiled slot
    gemm_i8<0><<<dim3(QKV_DIM / IBN, T_LEN / IBM), 512, IGSMEM>>>(
        xqh, xql, sx, wqh, wql, swq, DIM, QKV_DIM, qkv, nullptr, nullptr);
    // 5. q/k norm+rope, v -> bf16 hi/lo
    qk_prep<<<dim3(T_LEN, 6), 256>>>(qkv, rope, qh, ql, kh, kl, vh, vl);
    // 6. attention -> fp32
    attn_mma<<<dim3(T_LEN / 64, NHEADS), 128, ATTN_SMEM>>>(qh, ql, kh, kl, vh, vl, attn);
    // 7. quantize attention output
    quant_rows<<<T_LEN, 256>>>(attn, DIM, aqh, aql, sa);
    // 8. x1 = x + o_scale[n] * (attn @ o_w^T)
    gemm_i8<1><<<dim3(DIM / IBN, T_LEN / IBM), 512, IGSMEM>>>(
        aqh, aql, sa, woh, wol, swo, DIM, DIM, x1, x, o_scale);
    // 9. x1n = rmsnorm(x1) -> int8 digits
    rmsnorm_quant<<<T_LEN, 256>>>(x1, x1qh, x1ql, sx1);
    // 10. h = relu(x1n @ w1^T)^2 -> fp32
    gemm_i8<2><<<dim3(MLP_DIM / IBN, T_LEN / IBM), 512, IGSMEM>>>(
        x1qh, x1ql, sx1, w1h, w1l, sw1, DIM, MLP_DIM, hf, nullptr, nullptr);
    // 11. quantize h
    quant_rows<<<T_LEN, 256>>>(hf, MLP_DIM, hqh, hql, sh);
    // 12. out = x1 + w2_scale[n] * (h @ w2^T)
    gemm_i8<1><<<dim3(DIM / IBN, T_LEN / IBM), 512, IGSMEM>>>(
        hqh, hql, sh, w2h, w2l, sw2, MLP_DIM, DIM, out, x1, w2_scale);
}

// round 10
// speedup vs baseline: 4.3451x; 1.0377x over previous
#include <cuda_runtime.h>
#include <cuda_bf16.h>
#include <math_constants.h>
#include <cstdint>

#define T_LEN   4096
#define DIM     1024
#define QKV_DIM 3072
#define MLP_DIM 4096
#define NHEADS  16
#define HD      64
#define WIN     512
#define EPS_F   1.1920929e-07f
#define QMAX    16256.0f            // 127*128

// ================= helpers =================
__device__ __forceinline__ uint32_t smem_u32(const void* p) {
    uint32_t a;
    asm("{ .reg .u64 t; cvta.to.shared.u64 t, %1; cvt.u32.u64 %0, t; }" : "=r"(a) : "l"(p));
    return a;
}
__device__ __forceinline__ void cp16(uint32_t s, const void* g) {
    asm volatile("cp.async.cg.shared.global [%0], [%1], 16;" :: "r"(s), "l"(g));
}
__device__ __forceinline__ void ldsm_x4(uint32_t* r, uint32_t addr) {
    asm volatile("ldmatrix.sync.aligned.m8n8.x4.shared.b16 {%0,%1,%2,%3}, [%4];"
                 : "=r"(r[0]), "=r"(r[1]), "=r"(r[2]), "=r"(r[3]) : "r"(addr));
}
__device__ __forceinline__ void ldsm_x4_t(uint32_t* r, uint32_t addr) {
    asm volatile("ldmatrix.sync.aligned.m8n8.x4.trans.shared.b16 {%0,%1,%2,%3}, [%4];"
                 : "=r"(r[0]), "=r"(r[1]), "=r"(r[2]), "=r"(r[3]) : "r"(addr));
}
__device__ __forceinline__ void mma16816(float* c, const uint32_t* a, const uint32_t* b) {
    asm volatile("mma.sync.aligned.m16n8k16.row.col.f32.bf16.bf16.f32 "
        "{%0,%1,%2,%3}, {%4,%5,%6,%7}, {%8,%9}, {%0,%1,%2,%3};"
        : "+f"(c[0]), "+f"(c[1]), "+f"(c[2]), "+f"(c[3])
        : "r"(a[0]), "r"(a[1]), "r"(a[2]), "r"(a[3]), "r"(b[0]), "r"(b[1]));
}
__device__ __forceinline__ void imma16832(int* c, const uint32_t* a, const uint32_t* b) {
    asm volatile("mma.sync.aligned.m16n8k32.row.col.s32.s8.s8.s32 "
        "{%0,%1,%2,%3}, {%4,%5,%6,%7}, {%8,%9}, {%0,%1,%2,%3};"
        : "+r"(c[0]), "+r"(c[1]), "+r"(c[2]), "+r"(c[3])
        : "r"(a[0]), "r"(a[1]), "r"(a[2]), "r"(a[3]), "r"(b[0]), "r"(b[1]));
}
__device__ __forceinline__ void split_bf16(float a, __nv_bfloat16& hi, __nv_bfloat16& lo) {
    hi = __float2bfloat16(a);
    lo = __float2bfloat16(a - __bfloat162float(hi));
}
__device__ __forceinline__ uint32_t pack2(__nv_bfloat16 a, __nv_bfloat16 b) {
    return (uint32_t)__bfloat16_as_ushort(a) | ((uint32_t)__bfloat16_as_ushort(b) << 16);
}
__device__ __forceinline__ uint32_t pack_hi(float a, float b) {
    return pack2(__float2bfloat16(a), __float2bfloat16(b));
}
__device__ __forceinline__ uint32_t pack_lo(float a, float b) {
    __nv_bfloat16 ha = __float2bfloat16(a), hb = __float2bfloat16(b);
    return pack2(__float2bfloat16(a - __bfloat162float(ha)),
                 __float2bfloat16(b - __bfloat162float(hb)));
}

// ================= scratch =================
__device__ float g_qkv [T_LEN * QKV_DIM];
__device__ float g_x1  [T_LEN * DIM];
__device__ float g_attn[T_LEN * DIM];
__device__ float g_hf  [T_LEN * MLP_DIM];
__device__ float2 g_rope[T_LEN * 16];

#define BF16A __device__ __align__(16) __nv_bfloat16
BF16A g_qh[T_LEN * DIM]; BF16A g_ql[T_LEN * DIM];
BF16A g_kh[T_LEN * DIM]; BF16A g_kl[T_LEN * DIM];
BF16A g_vh[T_LEN * DIM]; BF16A g_vl[T_LEN * DIM];

#define I8A __device__ __align__(16) int8_t
I8A g_xq_h [T_LEN * DIM];     I8A g_xq_l [T_LEN * DIM];     __device__ float g_sx [T_LEN];
I8A g_aq_h [T_LEN * DIM];     I8A g_aq_l [T_LEN * DIM];     __device__ float g_sa [T_LEN];
I8A g_x1q_h[T_LEN * DIM];     I8A g_x1q_l[T_LEN * DIM];     __device__ float g_sx1[T_LEN];
I8A g_hq_h [T_LEN * MLP_DIM]; I8A g_hq_l [T_LEN * MLP_DIM]; __device__ float g_sh [T_LEN];
I8A g_wq_h [QKV_DIM * DIM];   I8A g_wq_l [QKV_DIM * DIM];   __device__ float g_swq[QKV_DIM];
I8A g_wo_h [DIM * DIM];       I8A g_wo_l [DIM * DIM];       __device__ float g_swo[DIM];
I8A g_w1_h [MLP_DIM * DIM];   I8A g_w1_l [MLP_DIM * DIM];   __device__ float g_sw1[MLP_DIM];
I8A g_w2_h [DIM * MLP_DIM];   I8A g_w2_l [DIM * MLP_DIM];   __device__ float g_sw2[DIM];

// ================= row quantization =================
__device__ __forceinline__ float block_max256(float v, float* red) {
    #pragma unroll
    for (int off = 16; off; off >>= 1) v = fmaxf(v, __shfl_xor_sync(0xffffffffu, v, off));
    if ((threadIdx.x & 31) == 0) red[threadIdx.x >> 5] = v;
    __syncthreads();
    float m = red[0];
    #pragma unroll
    for (int i = 1; i < 8; i++) m = fmaxf(m, red[i]);
    return m;
}
__device__ __forceinline__ void quant4(float4 v, float inv128, float s128, float invS,
                                       char4& qh, char4& ql) {
    float h0 = rintf(v.x * inv128), h1 = rintf(v.y * inv128);
    float h2 = rintf(v.z * inv128), h3 = rintf(v.w * inv128);
    qh = make_char4((signed char)__float2int_rn(h0), (signed char)__float2int_rn(h1),
                    (signed char)__float2int_rn(h2), (signed char)__float2int_rn(h3));
    ql = make_char4((signed char)__float2int_rn((v.x - h0 * s128) * invS),
                    (signed char)__float2int_rn((v.y - h1 * s128) * invS),
                    (signed char)__float2int_rn((v.z - h2 * s128) * invS),
                    (signed char)__float2int_rn((v.w - h3 * s128) * invS));
}

__device__ __forceinline__ void quant_row_body(const float* __restrict__ src, int ncols,
                                               int8_t* __restrict__ qh, int8_t* __restrict__ ql,
                                               float* __restrict__ Srow, int row) {
    __shared__ float red[8];
    const float* r = src + (size_t)row * ncols;
    const int tid = threadIdx.x;
    const int n4 = ncols >> 2;
    float amax = 0.f;
    for (int i = tid; i < n4; i += 256) {
        float4 v = ((const float4*)r)[i];
        amax = fmaxf(amax, fmaxf(fmaxf(fabsf(v.x), fabsf(v.y)), fmaxf(fabsf(v.z), fabsf(v.w))));
    }
    const float m = block_max256(amax, red);
    const float S = fmaxf(m, 1e-20f) * (1.0f / QMAX);
    const float inv128 = 1.0f / (128.0f * S), s128 = 128.0f * S, invS = 1.0f / S;
    for (int i = tid; i < n4; i += 256) {
        float4 v = ((const float4*)r)[i];
        char4 h4, l4;
        quant4(v, inv128, s128, invS, h4, l4);
        ((char4*)(qh + (size_t)row * ncols))[i] = h4;
        ((char4*)(ql + (size_t)row * ncols))[i] = l4;
    }
    if (tid == 0) Srow[row] = S;
}

__global__ __launch_bounds__(256) void quant_rows(const float* __restrict__ src, int ncols,
                                                  int8_t* __restrict__ qh, int8_t* __restrict__ ql,
                                                  float* __restrict__ S) {
    quant_row_body(src, ncols, qh, ql, S, blockIdx.x);
}

__global__ __launch_bounds__(256) void quant_weights(
    const float* qkv_w, const float* o_w, const float* w1, const float* w2,
    int8_t* wqh, int8_t* wql, float* swq,
    int8_t* woh, int8_t* wol, float* swo,
    int8_t* w1h, int8_t* w1l, float* sw1,
    int8_t* w2h, int8_t* w2l, float* sw2) {
    int r = blockIdx.x;
    if (r < 3072)       quant_row_body(qkv_w, 1024, wqh, wql, swq, r);
    else if (r < 4096)  quant_row_body(o_w,   1024, woh, wol, swo, r - 3072);
    else if (r < 8192)  quant_row_body(w1,    1024, w1h, w1l, sw1, r - 4096);
    else                quant_row_body(w2,    4096, w2h, w2l, sw2, r - 8192);
}

// ================= rmsnorm -> int8 two-digit =================
__global__ __launch_bounds__(256) void rmsnorm_quant(const float* __restrict__ x,
                                                     int8_t* __restrict__ qh,
                                                     int8_t* __restrict__ ql,
                                                     float* __restrict__ S) {
    __shared__ float red[8], redm[8];
    const int row = blockIdx.x;
    const int tid = threadIdx.x;
    float4 v = ((const float4*)(x + (size_t)row * DIM))[tid];
    float ss = v.x * v.x + v.y * v.y + v.z * v.z + v.w * v.w;
    float am = fmaxf(fmaxf(fabsf(v.x), fabsf(v.y)), fmaxf(fabsf(v.z), fabsf(v.w)));
    #pragma unroll
    for (int off = 16; off; off >>= 1) {
        ss += __shfl_xor_sync(0xffffffffu, ss, off);
        am = fmaxf(am, __shfl_xor_sync(0xffffffffu, am, off));
    }
    if ((tid & 31) == 0) { red[tid >> 5] = ss; redm[tid >> 5] = am; }
    __syncthreads();
    float tot = 0.f, m = 0.f;
    #pragma unroll
    for (int i = 0; i < 8; i++) { tot += red[i]; m = fmaxf(m, redm[i]); }
    const float r = rsqrtf(tot * (1.0f / DIM) + EPS_F);
    v.x *= r; v.y *= r; v.z *= r; v.w *= r;
    const float Sv = fmaxf(m * r, 1e-20f) * (1.0f / QMAX);
    const float inv128 = 1.0f / (128.0f * Sv), s128 = 128.0f * Sv, invS = 1.0f / Sv;
    char4 h4, l4;
    quant4(v, inv128, s128, invS, h4, l4);
    ((char4*)(qh + (size_t)row * DIM))[tid] = h4;
    ((char4*)(ql + (size_t)row * DIM))[tid] = l4;
    if (tid == 0) S[row] = Sv;
}

// ================= rope table =================
__global__ __launch_bounds__(256) void rope_tab(float2* __restrict__ tab) {
    const int idx = blockIdx.x * 256 + threadIdx.x;
    const int t = idx >> 4, j = idx & 15;
    const float f = powf(1e-4f, (float)j * (1.0f / 15.0f));
    float sn, cs;
    sincosf((float)t * f, &sn, &cs);
    tab[idx] = make_float2(cs, sn);
}

// ================= per-head q/k rmsnorm + rope; v split -> bf16 hi/lo =================
__global__ __launch_bounds__(256) void qk_prep(const float* __restrict__ qkv,
                                               const float2* __restrict__ rope,
                                               __nv_bfloat16* __restrict__ qh, __nv_bfloat16* __restrict__ ql,
                                               __nv_bfloat16* __restrict__ kh, __nv_bfloat16* __restrict__ kl,
                                               __nv_bfloat16* __restrict__ vh, __nv_bfloat16* __restrict__ vl) {
    const int t    = blockIdx.x;
    const int idx  = blockIdx.y * 8 + (threadIdx.x >> 5);
    const int lane = threadIdx.x & 31;
    const int head = idx & 15;
    const size_t dsto = (size_t)t * DIM + head * HD;
    __nv_bfloat16 *dh, *dl;
    const float* src;
    if (idx < 16) {
        src = qkv + (size_t)t * QKV_DIM + head * HD;
        dh = qh + dsto; dl = ql + dsto;
    } else if (idx < 32) {
        src = qkv + (size_t)t * QKV_DIM + DIM + head * HD;
        dh = kh + dsto; dl = kl + dsto;
    } else {
        src = qkv + (size_t)t * QKV_DIM + 2 * DIM + head * HD;
        dh = vh + dsto; dl = vl + dsto;
    }
    float a = src[lane];
    float b = src[lane + 32];
    if (idx < 32) {
        float ss = a * a + b * b;
        #pragma unroll
        for (int off = 16; off; off >>= 1) ss += __shfl_xor_sync(0xffffffffu, ss, off);
        const float r = rsqrtf(ss * (1.0f / HD) + EPS_F);
        a *= r; b *= r;
        float sn = 0.f, cs = 1.f;
        if (lane < 16) {
            const float2 e = rope[t * 16 + lane];
            cs = e.x; sn = e.y;
        }
        const float y1 =  a * cs + b * sn;
        const float y2 = -a * sn + b * cs;
        a = y1; b = y2;
    }
    __nv_bfloat16 ha, la, hb, lb;
    split_bf16(a, ha, la);
    split_bf16(b, hb, lb);
    dh[lane] = ha;      dl[lane] = la;
    dh[lane + 32] = hb; dl[lane + 32] = lb;
}

// ================= tensor-core sliding-window attention =================
#define KVS_B 144
#define KVSPLIT 9216
#define ABUF (2 * KVSPLIT)
#define KVBUF (4 * KVSPLIT)
#define ATTN_SMEM (ABUF + 2 * KVBUF)    // 92160

__global__ __launch_bounds__(128) void attn_mma(
    const __nv_bfloat16* __restrict__ qh, const __nv_bfloat16* __restrict__ ql,
    const __nv_bfloat16* __restrict__ kh, const __nv_bfloat16* __restrict__ kl,
    const __nv_bfloat16* __restrict__ vh, const __nv_bfloat16* __restrict__ vl,
    float* __restrict__ outf) {
    extern __shared__ char smem[];
    const uint32_t sb = smem_u32(smem);
    const int h    = blockIdx.y;
    const int q0   = blockIdx.x * 64;
    const int tid  = threadIdx.x;
    const int wid  = tid >> 5;
    const int lane = tid & 31;

    #pragma unroll
    for (int it = 0; it < 4; it++) {
        const int g = tid + it * 128;
        const int row = g >> 3, cg = g & 7;
        const size_t src = (size_t)(q0 + row) * DIM + h * HD + cg * 8;
        const uint32_t off = (uint32_t)(row * KVS_B + cg * 16);
        cp16(sb + off, qh + src);
        cp16(sb + KVSPLIT + off, ql + src);
    }
    asm volatile("cp.async.commit_group;" ::: "memory");

    auto load_kv = [&](int kc, int buf) {
        const uint32_t base = sb + ABUF + buf * KVBUF;
        #pragma unroll
        for (int it = 0; it < 4; it++) {
            const int g = tid + it * 128;
            const int row = g >> 3, cg = g & 7;
            const size_t src = (size_t)(kc + row) * DIM + h * HD + cg * 8;
            const uint32_t off = (uint32_t)(row * KVS_B + cg * 16);
            cp16(base + off, kh + src);
            cp16(base + KVSPLIT + off, kl + src);
            cp16(base + 2 * KVSPLIT + off, vh + src);
            cp16(base + 3 * KVSPLIT + off, vl + src);
        }
        asm volatile("cp.async.commit_group;" ::: "memory");
    };

    const int kc0 = (q0 >= WIN) ? (q0 - WIN) : 0;
    const int nch = (q0 + 64 - kc0) >> 6;
    load_kv(kc0, 0);

    asm volatile("cp.async.wait_group 1;" ::: "memory");
    __syncthreads();
    uint32_t qfh[16], qfl[16];
    #pragma unroll
    for (int ks = 0; ks < 4; ks++) {
        const uint32_t ad = sb + (uint32_t)((wid * 16 + (lane & 15)) * KVS_B)
                          + ((lane >> 4) * 16) + ks * 32;
        ldsm_x4(qfh + ks * 4, ad);
        ldsm_x4(qfl + ks * 4, ad + KVSPLIT);
    }

    float m[2] = {-1e30f, -1e30f}, lsum[2] = {0.f, 0.f};
    float o[8][4];
    #pragma unroll
    for (int i = 0; i < 8; i++)
        #pragma unroll
        for (int j = 0; j < 4; j++) o[i][j] = 0.f;

    const int r0 = lane >> 2;
    const int qrow0 = q0 + wid * 16 + r0;
    const int qrow1 = qrow0 + 8;
    const int colb = (lane & 3) * 2;

    for (int c = 0; c < nch; c++) {
        const int b = c & 1;
        const int kc = kc0 + c * 64;
        if (c + 1 < nch) load_kv(kc + 64, b ^ 1);
        if (c + 1 < nch) { asm volatile("cp.async.wait_group 1;" ::: "memory"); }
        else             { asm volatile("cp.async.wait_group 0;" ::: "memory"); }
        __syncthreads();

        const uint32_t Kb = sb + ABUF + b * KVBUF;
        const uint32_t Vb = Kb + 2 * KVSPLIT;

        float sc[8][4];
        #pragma unroll
        for (int i = 0; i < 8; i++)
            #pragma unroll
            for (int j = 0; j < 4; j++) sc[i][j] = 0.f;
        #pragma unroll
        for (int ks = 0; ks < 4; ks++) {
            #pragma unroll
            for (int np = 0; np < 4; np++) {
                uint32_t bh4[4], bl4[4];
                const uint32_t bd = Kb
                    + (uint32_t)((np * 16 + ((lane >> 4) * 8) + (lane & 7)) * KVS_B)
                    + (((lane >> 3) & 1) * 16) + ks * 32;
                ldsm_x4(bh4, bd);
                ldsm_x4(bl4, bd + KVSPLIT);
                float* c0 = sc[np * 2];
                float* c1 = sc[np * 2 + 1];
                mma16816(c0, qfh + ks * 4, bh4);
                mma16816(c0, qfl + ks * 4, bh4);
                mma16816(c0, qfh + ks * 4, bl4);
                mma16816(c1, qfh + ks * 4, bh4 + 2);
                mma16816(c1, qfl + ks * 4, bh4 + 2);
                mma16816(c1, qfh + ks * 4, bl4 + 2);
            }
        }

        #pragma unroll
        for (int nf = 0; nf < 8; nf++) {
            #pragma unroll
            for (int j = 0; j < 4; j++) {
                const int kg = kc + nf * 8 + colb + (j & 1);
                const int q  = (j < 2) ? qrow0 : qrow1;
                const bool valid = (kg <= q) && (kg > q - WIN);
                sc[nf][j] = valid ? sc[nf][j] * 0.125f : -1e30f;
            }
        }
        float mx0 = -1e30f, mx1 = -1e30f;
        #pragma unroll
        for (int nf = 0; nf < 8; nf++) {
            mx0 = fmaxf(mx0, fmaxf(sc[nf][0], sc[nf][1]));
            mx1 = fmaxf(mx1, fmaxf(sc[nf][2], sc[nf][3]));
        }
        #pragma unroll
        for (int off = 1; off <= 2; off <<= 1) {
            mx0 = fmaxf(mx0, __shfl_xor_sync(0xffffffffu, mx0, off));
            mx1 = fmaxf(mx1, __shfl_xor_sync(0xffffffffu, mx1, off));
        }
        const float mn0 = fmaxf(m[0], mx0);
        const float mn1 = fmaxf(m[1], mx1);
        const float cr0 = __expf(m[0] - mn0);
        const float cr1 = __expf(m[1] - mn1);
        m[0] = mn0; m[1] = mn1;
        float sm0 = 0.f, sm1 = 0.f;
        #pragma unroll
        for (int nf = 0; nf < 8; nf++) {
            sc[nf][0] = __expf(sc[nf][0] - mn0);
            sc[nf][1] = __expf(sc[nf][1] - mn0);
            sc[nf][2] = __expf(sc[nf][2] - mn1);
            sc[nf][3] = __expf(sc[nf][3] - mn1);
            sm0 += sc[nf][0] + sc[nf][1];
            sm1 += sc[nf][2] + sc[nf][3];
        }
        #pragma unroll
        for (int off = 1; off <= 2; off <<= 1) {
            sm0 += __shfl_xor_sync(0xffffffffu, sm0, off);
            sm1 += __shfl_xor_sync(0xffffffffu, sm1, off);
        }
        lsum[0] = lsum[0] * cr0 + sm0;
        lsum[1] = lsum[1] * cr1 + sm1;
        #pragma unroll
        for (int nf = 0; nf < 8; nf++) {
            o[nf][0] *= cr0; o[nf][1] *= cr0;
            o[nf][2] *= cr1; o[nf][3] *= cr1;
        }

        #pragma unroll
        for (int ks = 0; ks < 4; ks++) {
            uint32_t ah4[4], al4[4];
            const float* p0 = sc[ks * 2];
            const float* p1 = sc[ks * 2 + 1];
            ah4[0] = pack_hi(p0[0], p0[1]);  al4[0] = pack_lo(p0[0], p0[1]);
            ah4[1] = pack_hi(p0[2], p0[3]);  al4[1] = pack_lo(p0[2], p0[3]);
            ah4[2] = pack_hi(p1[0], p1[1]);  al4[2] = pack_lo(p1[0], p1[1]);
            ah4[3] = pack_hi(p1[2], p1[3]);  al4[3] = pack_lo(p1[2], p1[3]);
            #pragma unroll
            for (int dg = 0; dg < 4; dg++) {
                uint32_t vh4[4], vl4[4];
                const uint32_t vd = Vb
                    + (uint32_t)((ks * 16 + (lane & 7) + ((lane >> 3) & 1) * 8) * KVS_B)
                    + dg * 32 + (((lane >> 4) & 1) * 16);
                ldsm_x4_t(vh4, vd);
                ldsm_x4_t(vl4, vd + KVSPLIT);
                float* c0 = o[dg * 2];
                float* c1 = o[dg * 2 + 1];
                mma16816(c0, ah4, vh4);
                mma16816(c0, al4, vh4);
                mma16816(c0, ah4, vl4);
                mma16816(c1, ah4, vh4 + 2);
                mma16816(c1, al4, vh4 + 2);
                mma16816(c1, ah4, vl4 + 2);
            }
        }
        __syncthreads();
    }

    const float inv0 = 1.0f / lsum[0];
    const float inv1 = 1.0f / lsum[1];
    #pragma unroll
    for (int nf = 0; nf < 8; nf++) {
        const int col = h * HD + nf * 8 + colb;
        *(float2*)(outf + (size_t)qrow0 * DIM + col) = make_float2(o[nf][0] * inv0, o[nf][1] * inv0);
        *(float2*)(outf + (size_t)qrow1 * DIM + col) = make_float2(o[nf][2] * inv1, o[nf][3] * inv1);
    }
}

// ================= int8 two-digit GEMM v4 =================
// CTA 128x64, 256 threads, 8 warps (4x2), warp tile 32x32, IBK=64, 3 stages.
// 2 CTAs co-resident per SM -> independent barrier domains overlap phases.
// C = Sa[m]*Sb[n]*(16384*Ch + 128*Cm)
#define IBM 128
#define IBN 64
#define IBK 64
#define IROWB 80                          // 64 B data + 16 B pad
#define A_SPL (128 * IROWB)               // 10240
#define B_SPL (64 * IROWB)                // 5120
#define ISTAGE (2 * A_SPL + 2 * B_SPL)    // 30720
#define ISTAGES 3
#define IGSMEM (ISTAGES * ISTAGE)         // 92160

template <int MODE>
__global__ __launch_bounds__(256, 2) void gemm_i8(
    const int8_t* __restrict__ Ah8, const int8_t* __restrict__ Al8, const float* __restrict__ Sa,
    const int8_t* __restrict__ Bh8, const int8_t* __restrict__ Bl8, const float* __restrict__ Sb,
    int K, int Ntot,
    float* __restrict__ Cf, const float* __restrict__ res, const float* __restrict__ scale) {
    extern __shared__ char smem[];
    const uint32_t sb = smem_u32(smem);
    const int tid  = threadIdx.x;
    const int lane = tid & 31;
    const int wid  = tid >> 5;
    const int wm   = wid >> 1;            // 4 warp rows of 32
    const int wn   = wid & 1;             // 2 warp cols of 32
    const int m0 = blockIdx.y * IBM, n0 = blockIdx.x * IBN;

    int Ch[2][4][4], Cm[2][4][4];
    #pragma unroll
    for (int i = 0; i < 2; i++)
        #pragma unroll
        for (int j = 0; j < 4; j++)
            #pragma unroll
            for (int k = 0; k < 4; k++) { Ch[i][j][k] = 0; Cm[i][j][k] = 0; }

    // loads: A 512 granules/digit (2 per thread), B 256 granules/digit (1 per thread)
    const int lrow = tid >> 2, lcg = tid & 3;
    auto load_stage = [&](int kc, int s) {
        const uint32_t base = sb + s * ISTAGE;
        const uint32_t off = (uint32_t)(lrow * IROWB + lcg * 16);
        #pragma unroll
        for (int it = 0; it < 2; it++) {
            const size_t ga = (size_t)(m0 + lrow + it * 64) * K + kc + lcg * 16;
            const uint32_t ao = off + (uint32_t)(it * 64 * IROWB);
            cp16(base + ao,         Ah8 + ga);
            cp16(base + A_SPL + ao, Al8 + ga);
        }
        const size_t gb = (size_t)(n0 + lrow) * K + kc + lcg * 16;
        cp16(base + 2 * A_SPL + off,         Bh8 + gb);
        cp16(base + 2 * A_SPL + B_SPL + off, Bl8 + gb);
        asm volatile("cp.async.commit_group;" ::: "memory");
    };

    const int NC = K / IBK;
    load_stage(0, 0);
    load_stage(IBK, 1);

    for (int c = 0; c < NC; c++) {
        asm volatile("cp.async.wait_group 1;" ::: "memory");
        __syncthreads();
        if (c + 2 < NC) load_stage((c + 2) * IBK, (c + 2) % ISTAGES);
        else            asm volatile("cp.async.commit_group;" ::: "memory");

        const uint32_t stb = sb + (c % ISTAGES) * ISTAGE;
        #pragma unroll
        for (int kh = 0; kh < 2; kh++) {
            uint32_t ah[8], al[8];
            #pragma unroll
            for (int mf = 0; mf < 2; mf++) {
                const uint32_t ad = stb
                    + (uint32_t)((wm * 32 + mf * 16 + (lane & 15)) * IROWB)
                    + ((lane >> 4) * 16) + kh * 32;
                ldsm_x4(ah + mf * 4, ad);
                ldsm_x4(al + mf * 4, ad + A_SPL);
            }
            #pragma unroll
            for (int g = 0; g < 2; g++) {
                uint32_t bh4[4], bl4[4];
                const uint32_t bd = stb + 2 * A_SPL
                    + (uint32_t)((wn * 32 + g * 16 + ((lane >> 4) * 8) + (lane & 7)) * IROWB)
                    + (((lane >> 3) & 1) * 16) + kh * 32;
                ldsm_x4(bh4, bd);
                ldsm_x4(bl4, bd + B_SPL);
                #pragma unroll
                for (int mf = 0; mf < 2; mf++) {
                    imma16832(Ch[mf][g * 2],     ah + mf * 4, bh4);
                    imma16832(Cm[mf][g * 2],     al + mf * 4, bh4);
                    imma16832(Cm[mf][g * 2],     ah + mf * 4, bl4);
                    imma16832(Ch[mf][g * 2 + 1], ah + mf * 4, bh4 + 2);
                    imma16832(Cm[mf][g * 2 + 1], al + mf * 4, bh4 + 2);
                    imma16832(Cm[mf][g * 2 + 1], ah + mf * 4, bl4 + 2);
                }
            }
        }
    }

    // ---- epilogue ----
    const int rb = m0 + wm * 32 + (lane >> 2);
    const int cb = n0 + wn * 32 + (lane & 3) * 2;
    #pragma unroll
    for (int mf = 0; mf < 2; mf++) {
        const int rr0 = rb + mf * 16;
        const int rr1 = rr0 + 8;
        const float sa0 = Sa[rr0], sa1 = Sa[rr1];
        #pragma unroll
        for (int nf = 0; nf < 4; nf++) {
            const int cn = cb + nf * 8;
            const float2 sbv = *(const float2*)(Sb + cn);
            const int* ch = Ch[mf][nf];
            const int* cm = Cm[mf][nf];
            float v0 = sa0 * sbv.x * (16384.f * (float)ch[0] + 128.f * (float)cm[0]);
            float v1 = sa0 * sbv.y * (16384.f * (float)ch[1] + 128.f * (float)cm[1]);
            float v2 = sa1 * sbv.x * (16384.f * (float)ch[2] + 128.f * (float)cm[2]);
            float v3 = sa1 * sbv.y * (16384.f * (float)ch[3] + 128.f * (float)cm[3]);
            if (MODE == 1) {
                const float2 sc2 = *(const float2*)(scale + cn);
                const float2 q0 = *(const float2*)(res + (size_t)rr0 * Ntot + cn);
                const float2 q1 = *(const float2*)(res + (size_t)rr1 * Ntot + cn);
                v0 = q0.x + sc2.x * v0; v1 = q0.y + sc2.y * v1;
                v2 = q1.x + sc2.x * v2; v3 = q1.y + sc2.y * v3;
            } else if (MODE == 2) {
                v0 = fmaxf(v0, 0.f); v0 *= v0;
                v1 = fmaxf(v1, 0.f); v1 *= v1;
                v2 = fmaxf(v2, 0.f); v2 *= v2;
                v3 = fmaxf(v3, 0.f); v3 *= v3;
            }
            *(float2*)(Cf + (size_t)rr0 * Ntot + cn) = make_float2(v0, v1);
            *(float2*)(Cf + (size_t)rr1 * Ntot + cn) = make_float2(v2, v3);
        }
    }
}

// ================= host launcher =================
extern "C" void kernel_launch(void* const* d_in, const int* in_sizes, int n_in,
                              void* d_out, int out_size) {
    const float* x        = (const float*)d_in[0];
    const float* qkv_w    = (const float*)d_in[1];
    const float* o_w      = (const float*)d_in[2];
    const float* o_scale  = (const float*)d_in[3];
    const float* w1       = (const float*)d_in[4];
    const float* w2       = (const float*)d_in[5];
    const float* w2_scale = (const float*)d_in[6];
    float* out = (float*)d_out;

    float *qkv, *x1, *attn, *hf;
    float2* rope;
    cudaGetSymbolAddress((void**)&qkv,  g_qkv);
    cudaGetSymbolAddress((void**)&x1,   g_x1);
    cudaGetSymbolAddress((void**)&attn, g_attn);
    cudaGetSymbolAddress((void**)&hf,   g_hf);
    cudaGetSymbolAddress((void**)&rope, g_rope);
    __nv_bfloat16 *qh, *ql, *kh, *kl, *vh, *vl;
    cudaGetSymbolAddress((void**)&qh, g_qh); cudaGetSymbolAddress((void**)&ql, g_ql);
    cudaGetSymbolAddress((void**)&kh, g_kh); cudaGetSymbolAddress((void**)&kl, g_kl);
    cudaGetSymbolAddress((void**)&vh, g_vh); cudaGetSymbolAddress((void**)&vl, g_vl);
    int8_t *xqh, *xql, *aqh, *aql, *x1qh, *x1ql, *hqh, *hql;
    int8_t *wqh, *wql, *woh, *wol, *w1h, *w1l, *w2h, *w2l;
    float *sx, *sa, *sx1, *sh, *swq, *swo, *sw1, *sw2;
    cudaGetSymbolAddress((void**)&xqh,  g_xq_h);  cudaGetSymbolAddress((void**)&xql,  g_xq_l);
    cudaGetSymbolAddress((void**)&aqh,  g_aq_h);  cudaGetSymbolAddress((void**)&aql,  g_aq_l);
    cudaGetSymbolAddress((void**)&x1qh, g_x1q_h); cudaGetSymbolAddress((void**)&x1ql, g_x1q_l);
    cudaGetSymbolAddress((void**)&hqh,  g_hq_h);  cudaGetSymbolAddress((void**)&hql,  g_hq_l);
    cudaGetSymbolAddress((void**)&wqh,  g_wq_h);  cudaGetSymbolAddress((void**)&wql,  g_wq_l);
    cudaGetSymbolAddress((void**)&woh,  g_wo_h);  cudaGetSymbolAddress((void**)&wol,  g_wo_l);
    cudaGetSymbolAddress((void**)&w1h,  g_w1_h);  cudaGetSymbolAddress((void**)&w1l,  g_w1_l);
    cudaGetSymbolAddress((void**)&w2h,  g_w2_h);  cudaGetSymbolAddress((void**)&w2l,  g_w2_l);
    cudaGetSymbolAddress((void**)&sx,  g_sx);  cudaGetSymbolAddress((void**)&sa,  g_sa);
    cudaGetSymbolAddress((void**)&sx1, g_sx1); cudaGetSymbolAddress((void**)&sh,  g_sh);
    cudaGetSymbolAddress((void**)&swq, g_swq); cudaGetSymbolAddress((void**)&swo, g_swo);
    cudaGetSymbolAddress((void**)&sw1, g_sw1); cudaGetSymbolAddress((void**)&sw2, g_sw2);

    cudaFuncSetAttribute(gemm_i8<0>, cudaFuncAttributeMaxDynamicSharedMemorySize, IGSMEM);
    cudaFuncSetAttribute(gemm_i8<1>, cudaFuncAttributeMaxDynamicSharedMemorySize, IGSMEM);
    cudaFuncSetAttribute(gemm_i8<2>, cudaFuncAttributeMaxDynamicSharedMemorySize, IGSMEM);
    cudaFuncSetAttribute(attn_mma, cudaFuncAttributeMaxDynamicSharedMemorySize, ATTN_SMEM);

    // 1. all weight quantizations
    quant_weights<<<9216, 256>>>(qkv_w, o_w, w1, w2,
                                 wqh, wql, swq, woh, wol, swo,
                                 w1h, w1l, sw1, w2h, w2l, sw2);
    // 2. xn = rmsnorm(x) -> int8 digits
    rmsnorm_quant<<<T_LEN, 256>>>(x, xqh, xql, sx);
    // 3. rope table
    rope_tab<<<256, 256>>>(rope);
    // 4. qkv = xn @ qkv_w^T   <-- profiled slot
    gemm_i8<0><<<dim3(QKV_DIM / IBN, T_LEN / IBM), 256, IGSMEM>>>(
        xqh, xql, sx, wqh, wql, swq, DIM, QKV_DIM, qkv, nullptr, nullptr);
    // 5. q/k norm+rope, v -> bf16 hi/lo
    qk_prep<<<dim3(T_LEN, 6), 256>>>(qkv, rope, qh, ql, kh, kl, vh, vl);
    // 6. attention -> fp32
    attn_mma<<<dim3(T_LEN / 64, NHEADS), 128, ATTN_SMEM>>>(qh, ql, kh, kl, vh, vl, attn);
    // 7. quantize attention output
    quant_rows<<<T_LEN, 256>>>(attn, DIM, aqh, aql, sa);
    // 8. x1 = x + o_scale[n] * (attn @ o_w^T)
    gemm_i8<1><<<dim3(DIM / IBN, T_LEN / IBM), 256, IGSMEM>>>(
        aqh, aql, sa, woh, wol, swo, DIM, DIM, x1, x, o_scale);
    // 9. x1n = rmsnorm(x1) -> int8 digits
    rmsnorm_quant<<<T_LEN, 256>>>(x1, x1qh, x1ql, sx1);
    // 10. h = relu(x1n @ w1^T)^2 -> fp32
    gemm_i8<2><<<dim3(MLP_DIM / IBN, T_LEN / IBM), 256, IGSMEM>>>(
        x1qh, x1ql, sx1, w1h, w1l, sw1, DIM, MLP_DIM, hf, nullptr, nullptr);
    // 11. quantize h
    quant_rows<<<T_LEN, 256>>>(hf, MLP_DIM, hqh, hql, sh);
    // 12. out = x1 + w2_scale[n] * (h @ w2^T)
    gemm_i8<1><<<dim3(DIM / IBN, T_LEN / IBM), 256, IGSMEM>>>(
        hqh, hql, sh, w2h, w2l, sw2, MLP_DIM, DIM, out, x1, w2_scale);
}

// round 11
// speedup vs baseline: 4.5604x; 1.0496x over previous
#include <cuda_runtime.h>
#include <cuda_bf16.h>
#include <math_constants.h>
#include <cstdint>

#define T_LEN   4096
#define DIM     1024
#define QKV_DIM 3072
#define MLP_DIM 4096
#define NHEADS  16
#define HD      64
#define WIN     512
#define EPS_F   1.1920929e-07f
#define QMAX    16256.0f            // 127*128

// ================= helpers =================
__device__ __forceinline__ uint32_t smem_u32(const void* p) {
    uint32_t a;
    asm("{ .reg .u64 t; cvta.to.shared.u64 t, %1; cvt.u32.u64 %0, t; }" : "=r"(a) : "l"(p));
    return a;
}
__device__ __forceinline__ void cp16(uint32_t s, const void* g) {
    asm volatile("cp.async.cg.shared.global [%0], [%1], 16;" :: "r"(s), "l"(g));
}
__device__ __forceinline__ void ldsm_x4(uint32_t* r, uint32_t addr) {
    asm volatile("ldmatrix.sync.aligned.m8n8.x4.shared.b16 {%0,%1,%2,%3}, [%4];"
                 : "=r"(r[0]), "=r"(r[1]), "=r"(r[2]), "=r"(r[3]) : "r"(addr));
}
__device__ __forceinline__ void ldsm_x4_t(uint32_t* r, uint32_t addr) {
    asm volatile("ldmatrix.sync.aligned.m8n8.x4.trans.shared.b16 {%0,%1,%2,%3}, [%4];"
                 : "=r"(r[0]), "=r"(r[1]), "=r"(r[2]), "=r"(r[3]) : "r"(addr));
}
__device__ __forceinline__ void mma16816(float* c, const uint32_t* a, const uint32_t* b) {
    asm volatile("mma.sync.aligned.m16n8k16.row.col.f32.bf16.bf16.f32 "
        "{%0,%1,%2,%3}, {%4,%5,%6,%7}, {%8,%9}, {%0,%1,%2,%3};"
        : "+f"(c[0]), "+f"(c[1]), "+f"(c[2]), "+f"(c[3])
        : "r"(a[0]), "r"(a[1]), "r"(a[2]), "r"(a[3]), "r"(b[0]), "r"(b[1]));
}
__device__ __forceinline__ void imma16832(int* c, const uint32_t* a, const uint32_t* b) {
    asm volatile("mma.sync.aligned.m16n8k32.row.col.s32.s8.s8.s32 "
        "{%0,%1,%2,%3}, {%4,%5,%6,%7}, {%8,%9}, {%0,%1,%2,%3};"
        : "+r"(c[0]), "+r"(c[1]), "+r"(c[2]), "+r"(c[3])
        : "r"(a[0]), "r"(a[1]), "r"(a[2]), "r"(a[3]), "r"(b[0]), "r"(b[1]));
}
__device__ __forceinline__ void split_bf16(float a, __nv_bfloat16& hi, __nv_bfloat16& lo) {
    hi = __float2bfloat16(a);
    lo = __float2bfloat16(a - __bfloat162float(hi));
}
__device__ __forceinline__ uint32_t pack2(__nv_bfloat16 a, __nv_bfloat16 b) {
    return (uint32_t)__bfloat16_as_ushort(a) | ((uint32_t)__bfloat16_as_ushort(b) << 16);
}
__device__ __forceinline__ uint32_t pack_hi(float a, float b) {
    return pack2(__float2bfloat16(a), __float2bfloat16(b));
}
__device__ __forceinline__ uint32_t pack_lo(float a, float b) {
    __nv_bfloat16 ha = __float2bfloat16(a), hb = __float2bfloat16(b);
    return pack2(__float2bfloat16(a - __bfloat162float(ha)),
                 __float2bfloat16(b - __bfloat162float(hb)));
}

// ================= scratch =================
__device__ float g_qkv [T_LEN * QKV_DIM];
__device__ float g_x1  [T_LEN * DIM];
__device__ float g_attn[T_LEN * DIM];
__device__ float g_hf  [T_LEN * MLP_DIM];
__device__ float2 g_rope[T_LEN * 16];

#define BF16A __device__ __align__(16) __nv_bfloat16
BF16A g_qh[T_LEN * DIM]; BF16A g_ql[T_LEN * DIM];
BF16A g_kh[T_LEN * DIM]; BF16A g_kl[T_LEN * DIM];
BF16A g_vh[T_LEN * DIM]; BF16A g_vl[T_LEN * DIM];

#define I8A __device__ __align__(16) int8_t
I8A g_xq_h [T_LEN * DIM];     I8A g_xq_l [T_LEN * DIM];     __device__ float g_sx [T_LEN];
I8A g_aq_h [T_LEN * DIM];     I8A g_aq_l [T_LEN * DIM];     __device__ float g_sa [T_LEN];
I8A g_x1q_h[T_LEN * DIM];     I8A g_x1q_l[T_LEN * DIM];     __device__ float g_sx1[T_LEN];
I8A g_hq_h [T_LEN * MLP_DIM]; I8A g_hq_l [T_LEN * MLP_DIM]; __device__ float g_sh [T_LEN];
I8A g_wq_h [QKV_DIM * DIM];   I8A g_wq_l [QKV_DIM * DIM];   __device__ float g_swq[QKV_DIM];
I8A g_wo_h [DIM * DIM];       I8A g_wo_l [DIM * DIM];       __device__ float g_swo[DIM];
I8A g_w1_h [MLP_DIM * DIM];   I8A g_w1_l [MLP_DIM * DIM];   __device__ float g_sw1[MLP_DIM];
I8A g_w2_h [DIM * MLP_DIM];   I8A g_w2_l [DIM * MLP_DIM];   __device__ float g_sw2[DIM];

// ================= row quantization =================
__device__ __forceinline__ float block_max256(float v, float* red) {
    #pragma unroll
    for (int off = 16; off; off >>= 1) v = fmaxf(v, __shfl_xor_sync(0xffffffffu, v, off));
    if ((threadIdx.x & 31) == 0) red[threadIdx.x >> 5] = v;
    __syncthreads();
    float m = red[0];
    #pragma unroll
    for (int i = 1; i < 8; i++) m = fmaxf(m, red[i]);
    return m;
}
__device__ __forceinline__ void quant4(float4 v, float inv128, float s128, float invS,
                                       char4& qh, char4& ql) {
    float h0 = rintf(v.x * inv128), h1 = rintf(v.y * inv128);
    float h2 = rintf(v.z * inv128), h3 = rintf(v.w * inv128);
    qh = make_char4((signed char)__float2int_rn(h0), (signed char)__float2int_rn(h1),
                    (signed char)__float2int_rn(h2), (signed char)__float2int_rn(h3));
    ql = make_char4((signed char)__float2int_rn((v.x - h0 * s128) * invS),
                    (signed char)__float2int_rn((v.y - h1 * s128) * invS),
                    (signed char)__float2int_rn((v.z - h2 * s128) * invS),
                    (signed char)__float2int_rn((v.w - h3 * s128) * invS));
}

__device__ __forceinline__ void quant_row_body(const float* __restrict__ src, int ncols,
                                               int8_t* __restrict__ qh, int8_t* __restrict__ ql,
                                               float* __restrict__ Srow, int row) {
    __shared__ float red[8];
    const float* r = src + (size_t)row * ncols;
    const int tid = threadIdx.x;
    const int n4 = ncols >> 2;
    float amax = 0.f;
    for (int i = tid; i < n4; i += 256) {
        float4 v = ((const float4*)r)[i];
        amax = fmaxf(amax, fmaxf(fmaxf(fabsf(v.x), fabsf(v.y)), fmaxf(fabsf(v.z), fabsf(v.w))));
    }
    const float m = block_max256(amax, red);
    const float S = fmaxf(m, 1e-20f) * (1.0f / QMAX);
    const float inv128 = 1.0f / (128.0f * S), s128 = 128.0f * S, invS = 1.0f / S;
    for (int i = tid; i < n4; i += 256) {
        float4 v = ((const float4*)r)[i];
        char4 h4, l4;
        quant4(v, inv128, s128, invS, h4, l4);
        ((char4*)(qh + (size_t)row * ncols))[i] = h4;
        ((char4*)(ql + (size_t)row * ncols))[i] = l4;
    }
    if (tid == 0) Srow[row] = S;
}

__global__ __launch_bounds__(256) void quant_rows(const float* __restrict__ src, int ncols,
                                                  int8_t* __restrict__ qh, int8_t* __restrict__ ql,
                                                  float* __restrict__ S) {
    quant_row_body(src, ncols, qh, ql, S, blockIdx.x);
}

__global__ __launch_bounds__(256) void quant_weights(
    const float* qkv_w, const float* o_w, const float* w1, const float* w2,
    int8_t* wqh, int8_t* wql, float* swq,
    int8_t* woh, int8_t* wol, float* swo,
    int8_t* w1h, int8_t* w1l, float* sw1,
    int8_t* w2h, int8_t* w2l, float* sw2) {
    int r = blockIdx.x;
    if (r < 3072)       quant_row_body(qkv_w, 1024, wqh, wql, swq, r);
    else if (r < 4096)  quant_row_body(o_w,   1024, woh, wol, swo, r - 3072);
    else if (r < 8192)  quant_row_body(w1,    1024, w1h, w1l, sw1, r - 4096);
    else                quant_row_body(w2,    4096, w2h, w2l, sw2, r - 8192);
}

// ================= rmsnorm -> int8 two-digit =================
__global__ __launch_bounds__(256) void rmsnorm_quant(const float* __restrict__ x,
                                                     int8_t* __restrict__ qh,
                                                     int8_t* __restrict__ ql,
                                                     float* __restrict__ S) {
    __shared__ float red[8], redm[8];
    const int row = blockIdx.x;
    const int tid = threadIdx.x;
    float4 v = ((const float4*)(x + (size_t)row * DIM))[tid];
    float ss = v.x * v.x + v.y * v.y + v.z * v.z + v.w * v.w;
    float am = fmaxf(fmaxf(fabsf(v.x), fabsf(v.y)), fmaxf(fabsf(v.z), fabsf(v.w)));
    #pragma unroll
    for (int off = 16; off; off >>= 1) {
        ss += __shfl_xor_sync(0xffffffffu, ss, off);
        am = fmaxf(am, __shfl_xor_sync(0xffffffffu, am, off));
    }
    if ((tid & 31) == 0) { red[tid >> 5] = ss; redm[tid >> 5] = am; }
    __syncthreads();
    float tot = 0.f, m = 0.f;
    #pragma unroll
    for (int i = 0; i < 8; i++) { tot += red[i]; m = fmaxf(m, redm[i]); }
    const float r = rsqrtf(tot * (1.0f / DIM) + EPS_F);
    v.x *= r; v.y *= r; v.z *= r; v.w *= r;
    const float Sv = fmaxf(m * r, 1e-20f) * (1.0f / QMAX);
    const float inv128 = 1.0f / (128.0f * Sv), s128 = 128.0f * Sv, invS = 1.0f / Sv;
    char4 h4, l4;
    quant4(v, inv128, s128, invS, h4, l4);
    ((char4*)(qh + (size_t)row * DIM))[tid] = h4;
    ((char4*)(ql + (size_t)row * DIM))[tid] = l4;
    if (tid == 0) S[row] = Sv;
}

// ================= rope table =================
__global__ __launch_bounds__(256) void rope_tab(float2* __restrict__ tab) {
    const int idx = blockIdx.x * 256 + threadIdx.x;
    const int t = idx >> 4, j = idx & 15;
    const float f = powf(1e-4f, (float)j * (1.0f / 15.0f));
    float sn, cs;
    sincosf((float)t * f, &sn, &cs);
    tab[idx] = make_float2(cs, sn);
}

// ================= per-head q/k rmsnorm + rope; v split -> bf16 hi/lo =================
__global__ __launch_bounds__(256) void qk_prep(const float* __restrict__ qkv,
                                               const float2* __restrict__ rope,
                                               __nv_bfloat16* __restrict__ qh, __nv_bfloat16* __restrict__ ql,
                                               __nv_bfloat16* __restrict__ kh, __nv_bfloat16* __restrict__ kl,
                                               __nv_bfloat16* __restrict__ vh, __nv_bfloat16* __restrict__ vl) {
    const int t    = blockIdx.x;
    const int idx  = blockIdx.y * 8 + (threadIdx.x >> 5);
    const int lane = threadIdx.x & 31;
    const int head = idx & 15;
    const size_t dsto = (size_t)t * DIM + head * HD;
    __nv_bfloat16 *dh, *dl;
    const float* src;
    if (idx < 16) {
        src = qkv + (size_t)t * QKV_DIM + head * HD;
        dh = qh + dsto; dl = ql + dsto;
    } else if (idx < 32) {
        src = qkv + (size_t)t * QKV_DIM + DIM + head * HD;
        dh = kh + dsto; dl = kl + dsto;
    } else {
        src = qkv + (size_t)t * QKV_DIM + 2 * DIM + head * HD;
        dh = vh + dsto; dl = vl + dsto;
    }
    float a = src[lane];
    float b = src[lane + 32];
    if (idx < 32) {
        float ss = a * a + b * b;
        #pragma unroll
        for (int off = 16; off; off >>= 1) ss += __shfl_xor_sync(0xffffffffu, ss, off);
        const float r = rsqrtf(ss * (1.0f / HD) + EPS_F);
        a *= r; b *= r;
        float sn = 0.f, cs = 1.f;
        if (lane < 16) {
            const float2 e = rope[t * 16 + lane];
            cs = e.x; sn = e.y;
        }
        const float y1 =  a * cs + b * sn;
        const float y2 = -a * sn + b * cs;
        a = y1; b = y2;
    }
    __nv_bfloat16 ha, la, hb, lb;
    split_bf16(a, ha, la);
    split_bf16(b, hb, lb);
    dh[lane] = ha;      dl[lane] = la;
    dh[lane + 32] = hb; dl[lane + 32] = lb;
}

// ================= tensor-core sliding-window attention =================
#define KVS_B 144
#define KVSPLIT 9216
#define ABUF (2 * KVSPLIT)
#define KVBUF (4 * KVSPLIT)
#define ATTN_SMEM (ABUF + 2 * KVBUF)    // 92160

__global__ __launch_bounds__(128) void attn_mma(
    const __nv_bfloat16* __restrict__ qh, const __nv_bfloat16* __restrict__ ql,
    const __nv_bfloat16* __restrict__ kh, const __nv_bfloat16* __restrict__ kl,
    const __nv_bfloat16* __restrict__ vh, const __nv_bfloat16* __restrict__ vl,
    float* __restrict__ outf) {
    extern __shared__ char smem[];
    const uint32_t sb = smem_u32(smem);
    const int h    = blockIdx.y;
    const int q0   = blockIdx.x * 64;
    const int tid  = threadIdx.x;
    const int wid  = tid >> 5;
    const int lane = tid & 31;

    #pragma unroll
    for (int it = 0; it < 4; it++) {
        const int g = tid + it * 128;
        const int row = g >> 3, cg = g & 7;
        const size_t src = (size_t)(q0 + row) * DIM + h * HD + cg * 8;
        const uint32_t off = (uint32_t)(row * KVS_B + cg * 16);
        cp16(sb + off, qh + src);
        cp16(sb + KVSPLIT + off, ql + src);
    }
    asm volatile("cp.async.commit_group;" ::: "memory");

    auto load_kv = [&](int kc, int buf) {
        const uint32_t base = sb + ABUF + buf * KVBUF;
        #pragma unroll
        for (int it = 0; it < 4; it++) {
            const int g = tid + it * 128;
            const int row = g >> 3, cg = g & 7;
            const size_t src = (size_t)(kc + row) * DIM + h * HD + cg * 8;
            const uint32_t off = (uint32_t)(row * KVS_B + cg * 16);
            cp16(base + off, kh + src);
            cp16(base + KVSPLIT + off, kl + src);
            cp16(base + 2 * KVSPLIT + off, vh + src);
            cp16(base + 3 * KVSPLIT + off, vl + src);
        }
        asm volatile("cp.async.commit_group;" ::: "memory");
    };

    const int kc0 = (q0 >= WIN) ? (q0 - WIN) : 0;
    const int nch = (q0 + 64 - kc0) >> 6;
    load_kv(kc0, 0);

    asm volatile("cp.async.wait_group 1;" ::: "memory");
    __syncthreads();
    uint32_t qfh[16], qfl[16];
    #pragma unroll
    for (int ks = 0; ks < 4; ks++) {
        const uint32_t ad = sb + (uint32_t)((wid * 16 + (lane & 15)) * KVS_B)
                          + ((lane >> 4) * 16) + ks * 32;
        ldsm_x4(qfh + ks * 4, ad);
        ldsm_x4(qfl + ks * 4, ad + KVSPLIT);
    }

    float m[2] = {-1e30f, -1e30f}, lsum[2] = {0.f, 0.f};
    float o[8][4];
    #pragma unroll
    for (int i = 0; i < 8; i++)
        #pragma unroll
        for (int j = 0; j < 4; j++) o[i][j] = 0.f;

    const int r0 = lane >> 2;
    const int qrow0 = q0 + wid * 16 + r0;
    const int qrow1 = qrow0 + 8;
    const int colb = (lane & 3) * 2;

    for (int c = 0; c < nch; c++) {
        const int b = c & 1;
        const int kc = kc0 + c * 64;
        if (c + 1 < nch) load_kv(kc + 64, b ^ 1);
        if (c + 1 < nch) { asm volatile("cp.async.wait_group 1;" ::: "memory"); }
        else             { asm volatile("cp.async.wait_group 0;" ::: "memory"); }
        __syncthreads();

        const uint32_t Kb = sb + ABUF + b * KVBUF;
        const uint32_t Vb = Kb + 2 * KVSPLIT;

        float sc[8][4];
        #pragma unroll
        for (int i = 0; i < 8; i++)
            #pragma unroll
            for (int j = 0; j < 4; j++) sc[i][j] = 0.f;
        #pragma unroll
        for (int ks = 0; ks < 4; ks++) {
            #pragma unroll
            for (int np = 0; np < 4; np++) {
                uint32_t bh4[4], bl4[4];
                const uint32_t bd = Kb
                    + (uint32_t)((np * 16 + ((lane >> 4) * 8) + (lane & 7)) * KVS_B)
                    + (((lane >> 3) & 1) * 16) + ks * 32;
                ldsm_x4(bh4, bd);
                ldsm_x4(bl4, bd + KVSPLIT);
                float* c0 = sc[np * 2];
                float* c1 = sc[np * 2 + 1];
                mma16816(c0, qfh + ks * 4, bh4);
                mma16816(c0, qfl + ks * 4, bh4);
                mma16816(c0, qfh + ks * 4, bl4);
                mma16816(c1, qfh + ks * 4, bh4 + 2);
                mma16816(c1, qfl + ks * 4, bh4 + 2);
                mma16816(c1, qfh + ks * 4, bl4 + 2);
            }
        }

        #pragma unroll
        for (int nf = 0; nf < 8; nf++) {
            #pragma unroll
            for (int j = 0; j < 4; j++) {
                const int kg = kc + nf * 8 + colb + (j & 1);
                const int q  = (j < 2) ? qrow0 : qrow1;
                const bool valid = (kg <= q) && (kg > q - WIN);
                sc[nf][j] = valid ? sc[nf][j] * 0.125f : -1e30f;
            }
        }
        float mx0 = -1e30f, mx1 = -1e30f;
        #pragma unroll
        for (int nf = 0; nf < 8; nf++) {
            mx0 = fmaxf(mx0, fmaxf(sc[nf][0], sc[nf][1]));
            mx1 = fmaxf(mx1, fmaxf(sc[nf][2], sc[nf][3]));
        }
        #pragma unroll
        for (int off = 1; off <= 2; off <<= 1) {
            mx0 = fmaxf(mx0, __shfl_xor_sync(0xffffffffu, mx0, off));
            mx1 = fmaxf(mx1, __shfl_xor_sync(0xffffffffu, mx1, off));
        }
        const float mn0 = fmaxf(m[0], mx0);
        const float mn1 = fmaxf(m[1], mx1);
        const float cr0 = __expf(m[0] - mn0);
        const float cr1 = __expf(m[1] - mn1);
        m[0] = mn0; m[1] = mn1;
        float sm0 = 0.f, sm1 = 0.f;
        #pragma unroll
        for (int nf = 0; nf < 8; nf++) {
            sc[nf][0] = __expf(sc[nf][0] - mn0);
            sc[nf][1] = __expf(sc[nf][1] - mn0);
            sc[nf][2] = __expf(sc[nf][2] - mn1);
            sc[nf][3] = __expf(sc[nf][3] - mn1);
            sm0 += sc[nf][0] + sc[nf][1];
            sm1 += sc[nf][2] + sc[nf][3];
        }
        #pragma unroll
        for (int off = 1; off <= 2; off <<= 1) {
            sm0 += __shfl_xor_sync(0xffffffffu, sm0, off);
            sm1 += __shfl_xor_sync(0xffffffffu, sm1, off);
        }
        lsum[0] = lsum[0] * cr0 + sm0;
        lsum[1] = lsum[1] * cr1 + sm1;
        #pragma unroll
        for (int nf = 0; nf < 8; nf++) {
            o[nf][0] *= cr0; o[nf][1] *= cr0;
            o[nf][2] *= cr1; o[nf][3] *= cr1;
        }

        #pragma unroll
        for (int ks = 0; ks < 4; ks++) {
            uint32_t ah4[4], al4[4];
            const float* p0 = sc[ks * 2];
            const float* p1 = sc[ks * 2 + 1];
            ah4[0] = pack_hi(p0[0], p0[1]);  al4[0] = pack_lo(p0[0], p0[1]);
            ah4[1] = pack_hi(p0[2], p0[3]);  al4[1] = pack_lo(p0[2], p0[3]);
            ah4[2] = pack_hi(p1[0], p1[1]);  al4[2] = pack_lo(p1[0], p1[1]);
            ah4[3] = pack_hi(p1[2], p1[3]);  al4[3] = pack_lo(p1[2], p1[3]);
            #pragma unroll
            for (int dg = 0; dg < 4; dg++) {
                uint32_t vh4[4], vl4[4];
                const uint32_t vd = Vb
                    + (uint32_t)((ks * 16 + (lane & 7) + ((lane >> 3) & 1) * 8) * KVS_B)
                    + dg * 32 + (((lane >> 4) & 1) * 16);
                ldsm_x4_t(vh4, vd);
                ldsm_x4_t(vl4, vd + KVSPLIT);
                float* c0 = o[dg * 2];
                float* c1 = o[dg * 2 + 1];
                mma16816(c0, ah4, vh4);
                mma16816(c0, al4, vh4);
                mma16816(c0, ah4, vl4);
                mma16816(c1, ah4, vh4 + 2);
                mma16816(c1, al4, vh4 + 2);
                mma16816(c1, ah4, vl4 + 2);
            }
        }
        __syncthreads();
    }

    const float inv0 = 1.0f / lsum[0];
    const float inv1 = 1.0f / lsum[1];
    #pragma unroll
    for (int nf = 0; nf < 8; nf++) {
        const int col = h * HD + nf * 8 + colb;
        *(float2*)(outf + (size_t)qrow0 * DIM + col) = make_float2(o[nf][0] * inv0, o[nf][1] * inv0);
        *(float2*)(outf + (size_t)qrow1 * DIM + col) = make_float2(o[nf][2] * inv1, o[nf][3] * inv1);
    }
}

// ================= int8 two-digit GEMM v5 =================
// CTA 64x64, 128 threads, 4 warps (2x2), warp tile 32x32, IBK=64, 3 stages.
// 3 CTAs co-resident per SM -> 3 independent barrier domains.
// C = Sa[m]*Sb[n]*(16384*Ch + 128*Cm)
#define IBM 64
#define IBN 64
#define IBK 64
#define IROWB 80                          // 64 B data + 16 B pad
#define I_SPL (64 * IROWB)                // 5120
#define ISTAGE (4 * I_SPL)                // 20480
#define ISTAGES 3
#define IGSMEM (ISTAGES * ISTAGE)         // 61440

template <int MODE>
__global__ __launch_bounds__(128, 3) void gemm_i8(
    const int8_t* __restrict__ Ah8, const int8_t* __restrict__ Al8, const float* __restrict__ Sa,
    const int8_t* __restrict__ Bh8, const int8_t* __restrict__ Bl8, const float* __restrict__ Sb,
    int K, int Ntot,
    float* __restrict__ Cf, const float* __restrict__ res, const float* __restrict__ scale) {
    extern __shared__ char smem[];
    const uint32_t sb = smem_u32(smem);
    const int tid  = threadIdx.x;
    const int lane = tid & 31;
    const int wid  = tid >> 5;
    const int wm   = wid >> 1;            // 2 warp rows of 32
    const int wn   = wid & 1;             // 2 warp cols of 32
    const int m0 = blockIdx.y * IBM, n0 = blockIdx.x * IBN;

    int Ch[2][4][4], Cm[2][4][4];
    #pragma unroll
    for (int i = 0; i < 2; i++)
        #pragma unroll
        for (int j = 0; j < 4; j++)
            #pragma unroll
            for (int k = 0; k < 4; k++) { Ch[i][j][k] = 0; Cm[i][j][k] = 0; }

    // loads: 64 rows x 4 granules of 16B per split; 128 threads -> 2 rows-passes
    const int lrow = tid >> 2, lcg = tid & 3;
    auto load_stage = [&](int kc, int s) {
        const uint32_t base = sb + s * ISTAGE;
        #pragma unroll
        for (int it = 0; it < 2; it++) {
            const int row = lrow + it * 32;
            const uint32_t off = (uint32_t)(row * IROWB + lcg * 16);
            const size_t ga = (size_t)(m0 + row) * K + kc + lcg * 16;
            const size_t gb = (size_t)(n0 + row) * K + kc + lcg * 16;
            cp16(base + off,             Ah8 + ga);
            cp16(base + I_SPL + off,     Al8 + ga);
            cp16(base + 2 * I_SPL + off, Bh8 + gb);
            cp16(base + 3 * I_SPL + off, Bl8 + gb);
        }
        asm volatile("cp.async.commit_group;" ::: "memory");
    };

    const int NC = K / IBK;
    load_stage(0, 0);
    load_stage(IBK, 1);

    for (int c = 0; c < NC; c++) {
        asm volatile("cp.async.wait_group 1;" ::: "memory");
        __syncthreads();
        if (c + 2 < NC) load_stage((c + 2) * IBK, (c + 2) % ISTAGES);
        else            asm volatile("cp.async.commit_group;" ::: "memory");

        const uint32_t stb = sb + (c % ISTAGES) * ISTAGE;
        #pragma unroll
        for (int kh = 0; kh < 2; kh++) {
            uint32_t ah[8], al[8];
            #pragma unroll
            for (int mf = 0; mf < 2; mf++) {
                const uint32_t ad = stb
                    + (uint32_t)((wm * 32 + mf * 16 + (lane & 15)) * IROWB)
                    + ((lane >> 4) * 16) + kh * 32;
                ldsm_x4(ah + mf * 4, ad);
                ldsm_x4(al + mf * 4, ad + I_SPL);
            }
            #pragma unroll
            for (int g = 0; g < 2; g++) {
                uint32_t bh4[4], bl4[4];
                const uint32_t bd = stb + 2 * I_SPL
                    + (uint32_t)((wn * 32 + g * 16 + ((lane >> 4) * 8) + (lane & 7)) * IROWB)
                    + (((lane >> 3) & 1) * 16) + kh * 32;
                ldsm_x4(bh4, bd);
                ldsm_x4(bl4, bd + I_SPL);
                #pragma unroll
                for (int mf = 0; mf < 2; mf++) {
                    imma16832(Ch[mf][g * 2],     ah + mf * 4, bh4);
                    imma16832(Cm[mf][g * 2],     al + mf * 4, bh4);
                    imma16832(Cm[mf][g * 2],     ah + mf * 4, bl4);
                    imma16832(Ch[mf][g * 2 + 1], ah + mf * 4, bh4 + 2);
                    imma16832(Cm[mf][g * 2 + 1], al + mf * 4, bh4 + 2);
                    imma16832(Cm[mf][g * 2 + 1], ah + mf * 4, bl4 + 2);
                }
            }
        }
    }

    // ---- epilogue ----
    const int rb = m0 + wm * 32 + (lane >> 2);
    const int cb = n0 + wn * 32 + (lane & 3) * 2;
    #pragma unroll
    for (int mf = 0; mf < 2; mf++) {
        const int rr0 = rb + mf * 16;
        const int rr1 = rr0 + 8;
        const float sa0 = Sa[rr0], sa1 = Sa[rr1];
        #pragma unroll
        for (int nf = 0; nf < 4; nf++) {
            const int cn = cb + nf * 8;
            const float2 sbv = *(const float2*)(Sb + cn);
            const int* ch = Ch[mf][nf];
            const int* cm = Cm[mf][nf];
            float v0 = sa0 * sbv.x * (16384.f * (float)ch[0] + 128.f * (float)cm[0]);
            float v1 = sa0 * sbv.y * (16384.f * (float)ch[1] + 128.f * (float)cm[1]);
            float v2 = sa1 * sbv.x * (16384.f * (float)ch[2] + 128.f * (float)cm[2]);
            float v3 = sa1 * sbv.y * (16384.f * (float)ch[3] + 128.f * (float)cm[3]);
            if (MODE == 1) {
                const float2 sc2 = *(const float2*)(scale + cn);
                const float2 q0 = *(const float2*)(res + (size_t)rr0 * Ntot + cn);
                const float2 q1 = *(const float2*)(res + (size_t)rr1 * Ntot + cn);
                v0 = q0.x + sc2.x * v0; v1 = q0.y + sc2.y * v1;
                v2 = q1.x + sc2.x * v2; v3 = q1.y + sc2.y * v3;
            } else if (MODE == 2) {
                v0 = fmaxf(v0, 0.f); v0 *= v0;
                v1 = fmaxf(v1, 0.f); v1 *= v1;
                v2 = fmaxf(v2, 0.f); v2 *= v2;
                v3 = fmaxf(v3, 0.f); v3 *= v3;
            }
            *(float2*)(Cf + (size_t)rr0 * Ntot + cn) = make_float2(v0, v1);
            *(float2*)(Cf + (size_t)rr1 * Ntot + cn) = make_float2(v2, v3);
        }
    }
}

// ================= host launcher =================
extern "C" void kernel_launch(void* const* d_in, const int* in_sizes, int n_in,
                              void* d_out, int out_size) {
    const float* x        = (const float*)d_in[0];
    const float* qkv_w    = (const float*)d_in[1];
    const float* o_w      = (const float*)d_in[2];
    const float* o_scale  = (const float*)d_in[3];
    const float* w1       = (const float*)d_in[4];
    const float* w2       = (const float*)d_in[5];
    const float* w2_scale = (const float*)d_in[6];
    float* out = (float*)d_out;

    float *qkv, *x1, *attn, *hf;
    float2* rope;
    cudaGetSymbolAddress((void**)&qkv,  g_qkv);
    cudaGetSymbolAddress((void**)&x1,   g_x1);
    cudaGetSymbolAddress((void**)&attn, g_attn);
    cudaGetSymbolAddress((void**)&hf,   g_hf);
    cudaGetSymbolAddress((void**)&rope, g_rope);
    __nv_bfloat16 *qh, *ql, *kh, *kl, *vh, *vl;
    cudaGetSymbolAddress((void**)&qh, g_qh); cudaGetSymbolAddress((void**)&ql, g_ql);
    cudaGetSymbolAddress((void**)&kh, g_kh); cudaGetSymbolAddress((void**)&kl, g_kl);
    cudaGetSymbolAddress((void**)&vh, g_vh); cudaGetSymbolAddress((void**)&vl, g_vl);
    int8_t *xqh, *xql, *aqh, *aql, *x1qh, *x1ql, *hqh, *hql;
    int8_t *wqh, *wql, *woh, *wol, *w1h, *w1l, *w2h, *w2l;
    float *sx, *sa, *sx1, *sh, *swq, *swo, *sw1, *sw2;
    cudaGetSymbolAddress((void**)&xqh,  g_xq_h);  cudaGetSymbolAddress((void**)&xql,  g_xq_l);
    cudaGetSymbolAddress((void**)&aqh,  g_aq_h);  cudaGetSymbolAddress((void**)&aql,  g_aq_l);
    cudaGetSymbolAddress((void**)&x1qh, g_x1q_h); cudaGetSymbolAddress((void**)&x1ql, g_x1q_l);
    cudaGetSymbolAddress((void**)&hqh,  g_hq_h);  cudaGetSymbolAddress((void**)&hql,  g_hq_l);
    cudaGetSymbolAddress((void**)&wqh,  g_wq_h);  cudaGetSymbolAddress((void**)&wql,  g_wq_l);
    cudaGetSymbolAddress((void**)&woh,  g_wo_h);  cudaGetSymbolAddress((void**)&wol,  g_wo_l);
    cudaGetSymbolAddress((void**)&w1h,  g_w1_h);  cudaGetSymbolAddress((void**)&w1l,  g_w1_l);
    cudaGetSymbolAddress((void**)&w2h,  g_w2_h);  cudaGetSymbolAddress((void**)&w2l,  g_w2_l);
    cudaGetSymbolAddress((void**)&sx,  g_sx);  cudaGetSymbolAddress((void**)&sa,  g_sa);
    cudaGetSymbolAddress((void**)&sx1, g_sx1); cudaGetSymbolAddress((void**)&sh,  g_sh);
    cudaGetSymbolAddress((void**)&swq, g_swq); cudaGetSymbolAddress((void**)&swo, g_swo);
    cudaGetSymbolAddress((void**)&sw1, g_sw1); cudaGetSymbolAddress((void**)&sw2, g_sw2);

    cudaFuncSetAttribute(gemm_i8<0>, cudaFuncAttributeMaxDynamicSharedMemorySize, IGSMEM);
    cudaFuncSetAttribute(gemm_i8<1>, cudaFuncAttributeMaxDynamicSharedMemorySize, IGSMEM);
    cudaFuncSetAttribute(gemm_i8<2>, cudaFuncAttributeMaxDynamicSharedMemorySize, IGSMEM);
    cudaFuncSetAttribute(attn_mma, cudaFuncAttributeMaxDynamicSharedMemorySize, ATTN_SMEM);

    // 1. all weight quantizations
    quant_weights<<<9216, 256>>>(qkv_w, o_w, w1, w2,
                                 wqh, wql, swq, woh, wol, swo,
                                 w1h, w1l, sw1, w2h, w2l, sw2);
    // 2. xn = rmsnorm(x) -> int8 digits
    rmsnorm_quant<<<T_LEN, 256>>>(x, xqh, xql, sx);
    // 3. rope table
    rope_tab<<<256, 256>>>(rope);
    // 4. qkv = xn @ qkv_w^T   <-- profiled slot
    gemm_i8<0><<<dim3(QKV_DIM / IBN, T_LEN / IBM), 128, IGSMEM>>>(
        xqh, xql, sx, wqh, wql, swq, DIM, QKV_DIM, qkv, nullptr, nullptr);
    // 5. q/k norm+rope, v -> bf16 hi/lo
    qk_prep<<<dim3(T_LEN, 6), 256>>>(qkv, rope, qh, ql, kh, kl, vh, vl);
    // 6. attention -> fp32
    attn_mma<<<dim3(T_LEN / 64, NHEADS), 128, ATTN_SMEM>>>(qh, ql, kh, kl, vh, vl, attn);
    // 7. quantize attention output
    quant_rows<<<T_LEN, 256>>>(attn, DIM, aqh, aql, sa);
    // 8. x1 = x + o_scale[n] * (attn @ o_w^T)
    gemm_i8<1><<<dim3(DIM / IBN, T_LEN / IBM), 128, IGSMEM>>>(
        aqh, aql, sa, woh, wol, swo, DIM, DIM, x1, x, o_scale);
    // 9. x1n = rmsnorm(x1) -> int8 digits
    rmsnorm_quant<<<T_LEN, 256>>>(x1, x1qh, x1ql, sx1);
    // 10. h = relu(x1n @ w1^T)^2 -> fp32
    gemm_i8<2><<<dim3(MLP_DIM / IBN, T_LEN / IBM), 128, IGSMEM>>>(
        x1qh, x1ql, sx1, w1h, w1l, sw1, DIM, MLP_DIM, hf, nullptr, nullptr);
    // 11. quantize h
    quant_rows<<<T_LEN, 256>>>(hf, MLP_DIM, hqh, hql, sh);
    // 12. out = x1 + w2_scale[n] * (h @ w2^T)
    gemm_i8<1><<<dim3(DIM / IBN, T_LEN / IBM), 128, IGSMEM>>>(
        hqh, hql, sh, w2h, w2l, sw2, MLP_DIM, DIM, out, x1, w2_scale);
}

// round 12
// speedup vs baseline: 4.9216x; 1.0792x over previous
#include <cuda_runtime.h>
#include <cuda_bf16.h>
#include <math_constants.h>
#include <cstdint>

#define T_LEN   4096
#define DIM     1024
#define QKV_DIM 3072
#define MLP_DIM 4096
#define NHEADS  16
#define HD      64
#define WIN     512
#define EPS_F   1.1920929e-07f
#define QMAX    16256.0f            // 127*128

// ================= helpers =================
__device__ __forceinline__ uint32_t smem_u32(const void* p) {
    uint32_t a;
    asm("{ .reg .u64 t; cvta.to.shared.u64 t, %1; cvt.u32.u64 %0, t; }" : "=r"(a) : "l"(p));
    return a;
}
__device__ __forceinline__ void cp16(uint32_t s, const void* g) {
    asm volatile("cp.async.cg.shared.global [%0], [%1], 16;" :: "r"(s), "l"(g));
}
__device__ __forceinline__ void ldsm_x4(uint32_t* r, uint32_t addr) {
    asm volatile("ldmatrix.sync.aligned.m8n8.x4.shared.b16 {%0,%1,%2,%3}, [%4];"
                 : "=r"(r[0]), "=r"(r[1]), "=r"(r[2]), "=r"(r[3]) : "r"(addr));
}
__device__ __forceinline__ void ldsm_x4_t(uint32_t* r, uint32_t addr) {
    asm volatile("ldmatrix.sync.aligned.m8n8.x4.trans.shared.b16 {%0,%1,%2,%3}, [%4];"
                 : "=r"(r[0]), "=r"(r[1]), "=r"(r[2]), "=r"(r[3]) : "r"(addr));
}
__device__ __forceinline__ void mma16816(float* c, const uint32_t* a, const uint32_t* b) {
    asm volatile("mma.sync.aligned.m16n8k16.row.col.f32.bf16.bf16.f32 "
        "{%0,%1,%2,%3}, {%4,%5,%6,%7}, {%8,%9}, {%0,%1,%2,%3};"
        : "+f"(c[0]), "+f"(c[1]), "+f"(c[2]), "+f"(c[3])
        : "r"(a[0]), "r"(a[1]), "r"(a[2]), "r"(a[3]), "r"(b[0]), "r"(b[1]));
}
__device__ __forceinline__ void imma16832(int* c, const uint32_t* a, const uint32_t* b) {
    asm volatile("mma.sync.aligned.m16n8k32.row.col.s32.s8.s8.s32 "
        "{%0,%1,%2,%3}, {%4,%5,%6,%7}, {%8,%9}, {%0,%1,%2,%3};"
        : "+r"(c[0]), "+r"(c[1]), "+r"(c[2]), "+r"(c[3])
        : "r"(a[0]), "r"(a[1]), "r"(a[2]), "r"(a[3]), "r"(b[0]), "r"(b[1]));
}
__device__ __forceinline__ void split_bf16(float a, __nv_bfloat16& hi, __nv_bfloat16& lo) {
    hi = __float2bfloat16(a);
    lo = __float2bfloat16(a - __bfloat162float(hi));
}
__device__ __forceinline__ uint32_t pack2(__nv_bfloat16 a, __nv_bfloat16 b) {
    return (uint32_t)__bfloat16_as_ushort(a) | ((uint32_t)__bfloat16_as_ushort(b) << 16);
}
__device__ __forceinline__ uint32_t pack_hi(float a, float b) {
    return pack2(__float2bfloat16(a), __float2bfloat16(b));
}
__device__ __forceinline__ uint32_t pack_lo(float a, float b) {
    __nv_bfloat16 ha = __float2bfloat16(a), hb = __float2bfloat16(b);
    return pack2(__float2bfloat16(a - __bfloat162float(ha)),
                 __float2bfloat16(b - __bfloat162float(hb)));
}

#define MBARRIER_INIT(addr, cnt) \
    asm volatile("mbarrier.init.shared.b64 [%0], %1;" :: "r"((uint32_t)(addr)), "r"((uint32_t)(cnt)) : "memory")
#define MBARRIER_ARRIVE(addr) \
    asm volatile("mbarrier.arrive.shared::cta.b64 _, [%0];" :: "r"((uint32_t)(addr)) : "memory")
#define CPASYNC_MBAR_ARRIVE(addr) \
    asm volatile("cp.async.mbarrier.arrive.noinc.shared::cta.b64 [%0];" :: "r"((uint32_t)(addr)) : "memory")
#define MBARRIER_WAIT_PARITY(addr, par) do { \
    uint32_t _m = (uint32_t)(addr); uint32_t _p = (uint32_t)(par); uint32_t _d; \
    asm volatile("{\n\t.reg .pred p;\n\tmbarrier.try_wait.parity.acquire.cta.shared::cta.b64 p, [%1], %2;\n\tselp.b32 %0, 1, 0, p;\n\t}" \
        : "=r"(_d) : "r"(_m), "r"(_p) : "memory"); \
    if (!_d) { \
        asm volatile("{\n\t.reg .pred P1;\n\tWL_%=:\n\tmbarrier.try_wait.parity.acquire.cta.shared::cta.b64 P1, [%0], %1, 0x989680;\n\t@P1 bra.uni WD_%=;\n\tbra.uni WL_%=;\n\tWD_%=:\n\t}" \
            :: "r"(_m), "r"(_p) : "memory"); \
    } } while (0)

// ================= scratch =================
__device__ float g_qkv [T_LEN * QKV_DIM];
__device__ float g_x1  [T_LEN * DIM];
__device__ float g_attn[T_LEN * DIM];
__device__ float g_hf  [T_LEN * MLP_DIM];
__device__ float2 g_rope[T_LEN * 16];

#define BF16A __device__ __align__(16) __nv_bfloat16
BF16A g_qh[T_LEN * DIM]; BF16A g_ql[T_LEN * DIM];
BF16A g_kh[T_LEN * DIM]; BF16A g_kl[T_LEN * DIM];
BF16A g_vh[T_LEN * DIM]; BF16A g_vl[T_LEN * DIM];

#define I8A __device__ __align__(16) int8_t
I8A g_xq_h [T_LEN * DIM];     I8A g_xq_l [T_LEN * DIM];     __device__ float g_sx [T_LEN];
I8A g_aq_h [T_LEN * DIM];     I8A g_aq_l [T_LEN * DIM];     __device__ float g_sa [T_LEN];
I8A g_x1q_h[T_LEN * DIM];     I8A g_x1q_l[T_LEN * DIM];     __device__ float g_sx1[T_LEN];
I8A g_hq_h [T_LEN * MLP_DIM]; I8A g_hq_l [T_LEN * MLP_DIM]; __device__ float g_sh [T_LEN];
I8A g_wq_h [QKV_DIM * DIM];   I8A g_wq_l [QKV_DIM * DIM];   __device__ float g_swq[QKV_DIM];
I8A g_wo_h [DIM * DIM];       I8A g_wo_l [DIM * DIM];       __device__ float g_swo[DIM];
I8A g_w1_h [MLP_DIM * DIM];   I8A g_w1_l [MLP_DIM * DIM];   __device__ float g_sw1[MLP_DIM];
I8A g_w2_h [DIM * MLP_DIM];   I8A g_w2_l [DIM * MLP_DIM];   __device__ float g_sw2[DIM];

// ================= row quantization =================
__device__ __forceinline__ float block_max256(float v, float* red) {
    #pragma unroll
    for (int off = 16; off; off >>= 1) v = fmaxf(v, __shfl_xor_sync(0xffffffffu, v, off));
    if ((threadIdx.x & 31) == 0) red[threadIdx.x >> 5] = v;
    __syncthreads();
    float m = red[0];
    #pragma unroll
    for (int i = 1; i < 8; i++) m = fmaxf(m, red[i]);
    return m;
}
__device__ __forceinline__ void quant4(float4 v, float inv128, float s128, float invS,
                                       char4& qh, char4& ql) {
    float h0 = rintf(v.x * inv128), h1 = rintf(v.y * inv128);
    float h2 = rintf(v.z * inv128), h3 = rintf(v.w * inv128);
    qh = make_char4((signed char)__float2int_rn(h0), (signed char)__float2int_rn(h1),
                    (signed char)__float2int_rn(h2), (signed char)__float2int_rn(h3));
    ql = make_char4((signed char)__float2int_rn((v.x - h0 * s128) * invS),
                    (signed char)__float2int_rn((v.y - h1 * s128) * invS),
                    (signed char)__float2int_rn((v.z - h2 * s128) * invS),
                    (signed char)__float2int_rn((v.w - h3 * s128) * invS));
}

__device__ __forceinline__ void quant_row_body(const float* __restrict__ src, int ncols,
                                               int8_t* __restrict__ qh, int8_t* __restrict__ ql,
                                               float* __restrict__ Srow, int row) {
    __shared__ float red[8];
    const float* r = src + (size_t)row * ncols;
    const int tid = threadIdx.x;
    const int n4 = ncols >> 2;
    float amax = 0.f;
    for (int i = tid; i < n4; i += 256) {
        float4 v = ((const float4*)r)[i];
        amax = fmaxf(amax, fmaxf(fmaxf(fabsf(v.x), fabsf(v.y)), fmaxf(fabsf(v.z), fabsf(v.w))));
    }
    const float m = block_max256(amax, red);
    const float S = fmaxf(m, 1e-20f) * (1.0f / QMAX);
    const float inv128 = 1.0f / (128.0f * S), s128 = 128.0f * S, invS = 1.0f / S;
    for (int i = tid; i < n4; i += 256) {
        float4 v = ((const float4*)r)[i];
        char4 h4, l4;
        quant4(v, inv128, s128, invS, h4, l4);
        ((char4*)(qh + (size_t)row * ncols))[i] = h4;
        ((char4*)(ql + (size_t)row * ncols))[i] = l4;
    }
    if (tid == 0) Srow[row] = S;
}

__global__ __launch_bounds__(256) void quant_rows(const float* __restrict__ src, int ncols,
                                                  int8_t* __restrict__ qh, int8_t* __restrict__ ql,
                                                  float* __restrict__ S) {
    quant_row_body(src, ncols, qh, ql, S, blockIdx.x);
}

__global__ __launch_bounds__(256) void quant_weights(
    const float* qkv_w, const float* o_w, const float* w1, const float* w2,
    int8_t* wqh, int8_t* wql, float* swq,
    int8_t* woh, int8_t* wol, float* swo,
    int8_t* w1h, int8_t* w1l, float* sw1,
    int8_t* w2h, int8_t* w2l, float* sw2) {
    int r = blockIdx.x;
    if (r < 3072)       quant_row_body(qkv_w, 1024, wqh, wql, swq, r);
    else if (r < 4096)  quant_row_body(o_w,   1024, woh, wol, swo, r - 3072);
    else if (r < 8192)  quant_row_body(w1,    1024, w1h, w1l, sw1, r - 4096);
    else                quant_row_body(w2,    4096, w2h, w2l, sw2, r - 8192);
}

// ================= rmsnorm -> int8 two-digit =================
__global__ __launch_bounds__(256) void rmsnorm_quant(const float* __restrict__ x,
                                                     int8_t* __restrict__ qh,
                                                     int8_t* __restrict__ ql,
                                                     float* __restrict__ S) {
    __shared__ float red[8], redm[8];
    const int row = blockIdx.x;
    const int tid = threadIdx.x;
    float4 v = ((const float4*)(x + (size_t)row * DIM))[tid];
    float ss = v.x * v.x + v.y * v.y + v.z * v.z + v.w * v.w;
    float am = fmaxf(fmaxf(fabsf(v.x), fabsf(v.y)), fmaxf(fabsf(v.z), fabsf(v.w)));
    #pragma unroll
    for (int off = 16; off; off >>= 1) {
        ss += __shfl_xor_sync(0xffffffffu, ss, off);
        am = fmaxf(am, __shfl_xor_sync(0xffffffffu, am, off));
    }
    if ((tid & 31) == 0) { red[tid >> 5] = ss; redm[tid >> 5] = am; }
    __syncthreads();
    float tot = 0.f, m = 0.f;
    #pragma unroll
    for (int i = 0; i < 8; i++) { tot += red[i]; m = fmaxf(m, redm[i]); }
    const float r = rsqrtf(tot * (1.0f / DIM) + EPS_F);
    v.x *= r; v.y *= r; v.z *= r; v.w *= r;
    const float Sv = fmaxf(m * r, 1e-20f) * (1.0f / QMAX);
    const float inv128 = 1.0f / (128.0f * Sv), s128 = 128.0f * Sv, invS = 1.0f / Sv;
    char4 h4, l4;
    quant4(v, inv128, s128, invS, h4, l4);
    ((char4*)(qh + (size_t)row * DIM))[tid] = h4;
    ((char4*)(ql + (size_t)row * DIM))[tid] = l4;
    if (tid == 0) S[row] = Sv;
}

// ================= rope table =================
__global__ __launch_bounds__(256) void rope_tab(float2* __restrict__ tab) {
    const int idx = blockIdx.x * 256 + threadIdx.x;
    const int t = idx >> 4, j = idx & 15;
    const float f = powf(1e-4f, (float)j * (1.0f / 15.0f));
    float sn, cs;
    sincosf((float)t * f, &sn, &cs);
    tab[idx] = make_float2(cs, sn);
}

// ================= per-head q/k rmsnorm + rope; v split -> bf16 hi/lo =================
__global__ __launch_bounds__(256) void qk_prep(const float* __restrict__ qkv,
                                               const float2* __restrict__ rope,
                                               __nv_bfloat16* __restrict__ qh, __nv_bfloat16* __restrict__ ql,
                                               __nv_bfloat16* __restrict__ kh, __nv_bfloat16* __restrict__ kl,
                                               __nv_bfloat16* __restrict__ vh, __nv_bfloat16* __restrict__ vl) {
    const int t    = blockIdx.x;
    const int idx  = blockIdx.y * 8 + (threadIdx.x >> 5);
    const int lane = threadIdx.x & 31;
    const int head = idx & 15;
    const size_t dsto = (size_t)t * DIM + head * HD;
    __nv_bfloat16 *dh, *dl;
    const float* src;
    if (idx < 16) {
        src = qkv + (size_t)t * QKV_DIM + head * HD;
        dh = qh + dsto; dl = ql + dsto;
    } else if (idx < 32) {
        src = qkv + (size_t)t * QKV_DIM + DIM + head * HD;
        dh = kh + dsto; dl = kl + dsto;
    } else {
        src = qkv + (size_t)t * QKV_DIM + 2 * DIM + head * HD;
        dh = vh + dsto; dl = vl + dsto;
    }
    float a = src[lane];
    float b = src[lane + 32];
    if (idx < 32) {
        float ss = a * a + b * b;
        #pragma unroll
        for (int off = 16; off; off >>= 1) ss += __shfl_xor_sync(0xffffffffu, ss, off);
        const float r = rsqrtf(ss * (1.0f / HD) + EPS_F);
        a *= r; b *= r;
        float sn = 0.f, cs = 1.f;
        if (lane < 16) {
            const float2 e = rope[t * 16 + lane];
            cs = e.x; sn = e.y;
        }
        const float y1 =  a * cs + b * sn;
        const float y2 = -a * sn + b * cs;
        a = y1; b = y2;
    }
    __nv_bfloat16 ha, la, hb, lb;
    split_bf16(a, ha, la);
    split_bf16(b, hb, lb);
    dh[lane] = ha;      dl[lane] = la;
    dh[lane + 32] = hb; dl[lane + 32] = lb;
}

// ================= tensor-core sliding-window attention =================
#define KVS_B 144
#define KVSPLIT 9216
#define ABUF (2 * KVSPLIT)
#define KVBUF (4 * KVSPLIT)
#define ATTN_SMEM (ABUF + 2 * KVBUF)    // 92160

__global__ __launch_bounds__(128) void attn_mma(
    const __nv_bfloat16* __restrict__ qh, const __nv_bfloat16* __restrict__ ql,
    const __nv_bfloat16* __restrict__ kh, const __nv_bfloat16* __restrict__ kl,
    const __nv_bfloat16* __restrict__ vh, const __nv_bfloat16* __restrict__ vl,
    float* __restrict__ outf) {
    extern __shared__ char smem[];
    const uint32_t sb = smem_u32(smem);
    const int h    = blockIdx.y;
    const int q0   = blockIdx.x * 64;
    const int tid  = threadIdx.x;
    const int wid  = tid >> 5;
    const int lane = tid & 31;

    #pragma unroll
    for (int it = 0; it < 4; it++) {
        const int g = tid + it * 128;
        const int row = g >> 3, cg = g & 7;
        const size_t src = (size_t)(q0 + row) * DIM + h * HD + cg * 8;
        const uint32_t off = (uint32_t)(row * KVS_B + cg * 16);
        cp16(sb + off, qh + src);
        cp16(sb + KVSPLIT + off, ql + src);
    }
    asm volatile("cp.async.commit_group;" ::: "memory");

    auto load_kv = [&](int kc, int buf) {
        const uint32_t base = sb + ABUF + buf * KVBUF;
        #pragma unroll
        for (int it = 0; it < 4; it++) {
            const int g = tid + it * 128;
            const int row = g >> 3, cg = g & 7;
            const size_t src = (size_t)(kc + row) * DIM + h * HD + cg * 8;
            const uint32_t off = (uint32_t)(row * KVS_B + cg * 16);
            cp16(base + off, kh + src);
            cp16(base + KVSPLIT + off, kl + src);
            cp16(base + 2 * KVSPLIT + off, vh + src);
            cp16(base + 3 * KVSPLIT + off, vl + src);
        }
        asm volatile("cp.async.commit_group;" ::: "memory");
    };

    const int kc0 = (q0 >= WIN) ? (q0 - WIN) : 0;
    const int nch = (q0 + 64 - kc0) >> 6;
    load_kv(kc0, 0);

    asm volatile("cp.async.wait_group 1;" ::: "memory");
    __syncthreads();
    uint32_t qfh[16], qfl[16];
    #pragma unroll
    for (int ks = 0; ks < 4; ks++) {
        const uint32_t ad = sb + (uint32_t)((wid * 16 + (lane & 15)) * KVS_B)
                          + ((lane >> 4) * 16) + ks * 32;
        ldsm_x4(qfh + ks * 4, ad);
        ldsm_x4(qfl + ks * 4, ad + KVSPLIT);
    }

    float m[2] = {-1e30f, -1e30f}, lsum[2] = {0.f, 0.f};
    float o[8][4];
    #pragma unroll
    for (int i = 0; i < 8; i++)
        #pragma unroll
        for (int j = 0; j < 4; j++) o[i][j] = 0.f;

    const int r0 = lane >> 2;
    const int qrow0 = q0 + wid * 16 + r0;
    const int qrow1 = qrow0 + 8;
    const int colb = (lane & 3) * 2;

    for (int c = 0; c < nch; c++) {
        const int b = c & 1;
        const int kc = kc0 + c * 64;
        if (c + 1 < nch) load_kv(kc + 64, b ^ 1);
        if (c + 1 < nch) { asm volatile("cp.async.wait_group 1;" ::: "memory"); }
        else             { asm volatile("cp.async.wait_group 0;" ::: "memory"); }
        __syncthreads();

        const uint32_t Kb = sb + ABUF + b * KVBUF;
        const uint32_t Vb = Kb + 2 * KVSPLIT;

        float sc[8][4];
        #pragma unroll
        for (int i = 0; i < 8; i++)
            #pragma unroll
            for (int j = 0; j < 4; j++) sc[i][j] = 0.f;
        #pragma unroll
        for (int ks = 0; ks < 4; ks++) {
            #pragma unroll
            for (int np = 0; np < 4; np++) {
                uint32_t bh4[4], bl4[4];
                const uint32_t bd = Kb
                    + (uint32_t)((np * 16 + ((lane >> 4) * 8) + (lane & 7)) * KVS_B)
                    + (((lane >> 3) & 1) * 16) + ks * 32;
                ldsm_x4(bh4, bd);
                ldsm_x4(bl4, bd + KVSPLIT);
                float* c0 = sc[np * 2];
                float* c1 = sc[np * 2 + 1];
                mma16816(c0, qfh + ks * 4, bh4);
                mma16816(c0, qfl + ks * 4, bh4);
                mma16816(c0, qfh + ks * 4, bl4);
                mma16816(c1, qfh + ks * 4, bh4 + 2);
                mma16816(c1, qfl + ks * 4, bh4 + 2);
                mma16816(c1, qfh + ks * 4, bl4 + 2);
            }
        }

        #pragma unroll
        for (int nf = 0; nf < 8; nf++) {
            #pragma unroll
            for (int j = 0; j < 4; j++) {
                const int kg = kc + nf * 8 + colb + (j & 1);
                const int q  = (j < 2) ? qrow0 : qrow1;
                const bool valid = (kg <= q) && (kg > q - WIN);
                sc[nf][j] = valid ? sc[nf][j] * 0.125f : -1e30f;
            }
        }
        float mx0 = -1e30f, mx1 = -1e30f;
        #pragma unroll
        for (int nf = 0; nf < 8; nf++) {
            mx0 = fmaxf(mx0, fmaxf(sc[nf][0], sc[nf][1]));
            mx1 = fmaxf(mx1, fmaxf(sc[nf][2], sc[nf][3]));
        }
        #pragma unroll
        for (int off = 1; off <= 2; off <<= 1) {
            mx0 = fmaxf(mx0, __shfl_xor_sync(0xffffffffu, mx0, off));
            mx1 = fmaxf(mx1, __shfl_xor_sync(0xffffffffu, mx1, off));
        }
        const float mn0 = fmaxf(m[0], mx0);
        const float mn1 = fmaxf(m[1], mx1);
        const float cr0 = __expf(m[0] - mn0);
        const float cr1 = __expf(m[1] - mn1);
        m[0] = mn0; m[1] = mn1;
        float sm0 = 0.f, sm1 = 0.f;
        #pragma unroll
        for (int nf = 0; nf < 8; nf++) {
            sc[nf][0] = __expf(sc[nf][0] - mn0);
            sc[nf][1] = __expf(sc[nf][1] - mn0);
            sc[nf][2] = __expf(sc[nf][2] - mn1);
            sc[nf][3] = __expf(sc[nf][3] - mn1);
            sm0 += sc[nf][0] + sc[nf][1];
            sm1 += sc[nf][2] + sc[nf][3];
        }
        #pragma unroll
        for (int off = 1; off <= 2; off <<= 1) {
            sm0 += __shfl_xor_sync(0xffffffffu, sm0, off);
            sm1 += __shfl_xor_sync(0xffffffffu, sm1, off);
        }
        lsum[0] = lsum[0] * cr0 + sm0;
        lsum[1] = lsum[1] * cr1 + sm1;
        #pragma unroll
        for (int nf = 0; nf < 8; nf++) {
            o[nf][0] *= cr0; o[nf][1] *= cr0;
            o[nf][2] *= cr1; o[nf][3] *= cr1;
        }

        #pragma unroll
        for (int ks = 0; ks < 4; ks++) {
            uint32_t ah4[4], al4[4];
            const float* p0 = sc[ks * 2];
            const float* p1 = sc[ks * 2 + 1];
            ah4[0] = pack_hi(p0[0], p0[1]);  al4[0] = pack_lo(p0[0], p0[1]);
            ah4[1] = pack_hi(p0[2], p0[3]);  al4[1] = pack_lo(p0[2], p0[3]);
            ah4[2] = pack_hi(p1[0], p1[1]);  al4[2] = pack_lo(p1[0], p1[1]);
            ah4[3] = pack_hi(p1[2], p1[3]);  al4[3] = pack_lo(p1[2], p1[3]);
            #pragma unroll
            for (int dg = 0; dg < 4; dg++) {
                uint32_t vh4[4], vl4[4];
                const uint32_t vd = Vb
                    + (uint32_t)((ks * 16 + (lane & 7) + ((lane >> 3) & 1) * 8) * KVS_B)
                    + dg * 32 + (((lane >> 4) & 1) * 16);
                ldsm_x4_t(vh4, vd);
                ldsm_x4_t(vl4, vd + KVSPLIT);
                float* c0 = o[dg * 2];
                float* c1 = o[dg * 2 + 1];
                mma16816(c0, ah4, vh4);
                mma16816(c0, al4, vh4);
                mma16816(c0, ah4, vl4);
                mma16816(c1, ah4, vh4 + 2);
                mma16816(c1, al4, vh4 + 2);
                mma16816(c1, ah4, vl4 + 2);
            }
        }
        __syncthreads();
    }

    const float inv0 = 1.0f / lsum[0];
    const float inv1 = 1.0f / lsum[1];
    #pragma unroll
    for (int nf = 0; nf < 8; nf++) {
        const int col = h * HD + nf * 8 + colb;
        *(float2*)(outf + (size_t)qrow0 * DIM + col) = make_float2(o[nf][0] * inv0, o[nf][1] * inv0);
        *(float2*)(outf + (size_t)qrow1 * DIM + col) = make_float2(o[nf][2] * inv1, o[nf][3] * inv1);
    }
}

// ================= int8 two-digit GEMM v6: mbarrier pipeline =================
// CTA 128x128, 256 threads, 8 warps (2x4), warp tile 64x32, k32 stages (16KB,
// XOR-swizzled, zero padding), 8 stages, per-stage full/empty mbarriers,
// NO __syncthreads in mainloop -> warp phases drift freely.
// C = Sa[m]*Sb[n]*(16384*Ch + 128*Cm)
#define IBM 128
#define IBN 128
#define NSTG 8
#define STGB 16384
#define IGSMEM (NSTG * STGB + 128)        // 131200

__device__ __forceinline__ uint32_t swz32(uint32_t row, uint32_t g16) {
    return (row * 32u + g16 * 16u) ^ ((row & 4u) << 2);
}

template <int MODE>
__global__ __launch_bounds__(256, 1) void gemm_i8(
    const int8_t* __restrict__ Ah8, const int8_t* __restrict__ Al8, const float* __restrict__ Sa,
    const int8_t* __restrict__ Bh8, const int8_t* __restrict__ Bl8, const float* __restrict__ Sb,
    int K, int Ntot,
    float* __restrict__ Cf, const float* __restrict__ res, const float* __restrict__ scale) {
    extern __shared__ char smem[];
    const uint32_t sb  = smem_u32(smem);
    const uint32_t mbF = sb + NSTG * STGB;        // full[8]
    const uint32_t mbE = mbF + 64;                // empty[8]
    const int tid  = threadIdx.x;
    const int lane = tid & 31;
    const int wid  = tid >> 5;
    const int wm   = wid >> 2;            // 2 warp rows of 64
    const int wn   = wid & 3;             // 4 warp cols of 32
    const int m0 = blockIdx.y * IBM, n0 = blockIdx.x * IBN;

    int Ch[4][4][4], Cm[4][4][4];
    #pragma unroll
    for (int i = 0; i < 4; i++)
        #pragma unroll
        for (int j = 0; j < 4; j++)
            #pragma unroll
            for (int k = 0; k < 4; k++) { Ch[i][j][k] = 0; Cm[i][j][k] = 0; }

    if (tid == 0) {
        #pragma unroll
        for (int i = 0; i < NSTG; i++) {
            MBARRIER_INIT(mbF + i * 8, 256);
            MBARRIER_INIT(mbE + i * 8, 256);
        }
    }
    __syncthreads();

    // producer: each thread loads one 16B granule per split (A hi/lo, B hi/lo)
    const int prow = tid >> 1, pg = tid & 1;
    const uint32_t pso = swz32((uint32_t)prow, (uint32_t)pg);
    const size_t pa = (size_t)(m0 + prow) * K + pg * 16;
    const size_t pb = (size_t)(n0 + prow) * K + pg * 16;
    auto produce = [&](int c, int stage) {
        const uint32_t base = sb + stage * STGB;
        const int kc = c * 32;
        cp16(base + pso,         Ah8 + pa + kc);
        cp16(base + 4096 + pso,  Al8 + pa + kc);
        cp16(base + 8192 + pso,  Bh8 + pb + kc);
        cp16(base + 12288 + pso, Bl8 + pb + kc);
        CPASYNC_MBAR_ARRIVE(mbF + stage * 8);
    };

    const int NC = K / 32;
    #pragma unroll
    for (int c0 = 0; c0 < NSTG - 1; c0++) produce(c0, c0);

    for (int c = 0; c < NC; c++) {
        const int stg = c & (NSTG - 1);
        const uint32_t stb = sb + stg * STGB;
        MBARRIER_WAIT_PARITY(mbF + stg * 8, (c >> 3) & 1);

        uint32_t ah[16], al[16];
        #pragma unroll
        for (int mf = 0; mf < 4; mf++) {
            const uint32_t arow = (uint32_t)(wm * 64 + mf * 16 + (lane & 15));
            const uint32_t ad = stb + swz32(arow, (uint32_t)(lane >> 4));
            ldsm_x4(ah + mf * 4, ad);
            ldsm_x4(al + mf * 4, ad + 4096);
        }
        #pragma unroll
        for (int g = 0; g < 2; g++) {
            uint32_t bh4[4], bl4[4];
            const uint32_t brow = (uint32_t)(wn * 32 + g * 16 + ((lane >> 4) * 8) + (lane & 7));
            const uint32_t bd = stb + 8192 + swz32(brow, (uint32_t)((lane >> 3) & 1));
            ldsm_x4(bh4, bd);
            ldsm_x4(bl4, bd + 4096);
            #pragma unroll
            for (int mf = 0; mf < 4; mf++) {
                imma16832(Ch[mf][g * 2],     ah + mf * 4, bh4);
                imma16832(Cm[mf][g * 2],     al + mf * 4, bh4);
                imma16832(Cm[mf][g * 2],     ah + mf * 4, bl4);
                imma16832(Ch[mf][g * 2 + 1], ah + mf * 4, bh4 + 2);
                imma16832(Cm[mf][g * 2 + 1], al + mf * 4, bh4 + 2);
                imma16832(Cm[mf][g * 2 + 1], ah + mf * 4, bl4 + 2);
            }
        }
        MBARRIER_ARRIVE(mbE + stg * 8);

        const int p = c + NSTG - 1;
        if (p < NC) {
            const int ps = p & (NSTG - 1);
            if (p >= NSTG) MBARRIER_WAIT_PARITY(mbE + ps * 8, ((p >> 3) + 1) & 1);
            produce(p, ps);
        }
    }

    // ---- epilogue (R7-verified 64x32 layout) ----
    const int rb = m0 + wm * 64 + (lane >> 2);
    const int cb = n0 + wn * 32 + (lane & 3) * 2;
    #pragma unroll
    for (int mf = 0; mf < 4; mf++) {
        const int rr0 = rb + mf * 16;
        const int rr1 = rr0 + 8;
        const float sa0 = Sa[rr0], sa1 = Sa[rr1];
        #pragma unroll
        for (int nf = 0; nf < 4; nf++) {
            const int cn = cb + nf * 8;
            const float2 sbv = *(const float2*)(Sb + cn);
            const int* ch = Ch[mf][nf];
            const int* cm = Cm[mf][nf];
            float v0 = sa0 * sbv.x * (16384.f * (float)ch[0] + 128.f * (float)cm[0]);
            float v1 = sa0 * sbv.y * (16384.f * (float)ch[1] + 128.f * (float)cm[1]);
            float v2 = sa1 * sbv.x * (16384.f * (float)ch[2] + 128.f * (float)cm[2]);
            float v3 = sa1 * sbv.y * (16384.f * (float)ch[3] + 128.f * (float)cm[3]);
            if (MODE == 1) {
                const float2 sc2 = *(const float2*)(scale + cn);
                const float2 q0 = *(const float2*)(res + (size_t)rr0 * Ntot + cn);
                const float2 q1 = *(const float2*)(res + (size_t)rr1 * Ntot + cn);
                v0 = q0.x + sc2.x * v0; v1 = q0.y + sc2.y * v1;
                v2 = q1.x + sc2.x * v2; v3 = q1.y + sc2.y * v3;
            } else if (MODE == 2) {
                v0 = fmaxf(v0, 0.f); v0 *= v0;
                v1 = fmaxf(v1, 0.f); v1 *= v1;
                v2 = fmaxf(v2, 0.f); v2 *= v2;
                v3 = fmaxf(v3, 0.f); v3 *= v3;
            }
            *(float2*)(Cf + (size_t)rr0 * Ntot + cn) = make_float2(v0, v1);
            *(float2*)(Cf + (size_t)rr1 * Ntot + cn) = make_float2(v2, v3);
        }
    }
}

// ================= host launcher =================
extern "C" void kernel_launch(void* const* d_in, const int* in_sizes, int n_in,
                              void* d_out, int out_size) {
    const float* x        = (const float*)d_in[0];
    const float* qkv_w    = (const float*)d_in[1];
    const float* o_w      = (const float*)d_in[2];
    const float* o_scale  = (const float*)d_in[3];
    const float* w1       = (const float*)d_in[4];
    const float* w2       = (const float*)d_in[5];
    const float* w2_scale = (const float*)d_in[6];
    float* out = (float*)d_out;

    float *qkv, *x1, *attn, *hf;
    float2* rope;
    cudaGetSymbolAddress((void**)&qkv,  g_qkv);
    cudaGetSymbolAddress((void**)&x1,   g_x1);
    cudaGetSymbolAddress((void**)&attn, g_attn);
    cudaGetSymbolAddress((void**)&hf,   g_hf);
    cudaGetSymbolAddress((void**)&rope, g_rope);
    __nv_bfloat16 *qh, *ql, *kh, *kl, *vh, *vl;
    cudaGetSymbolAddress((void**)&qh, g_qh); cudaGetSymbolAddress((void**)&ql, g_ql);
    cudaGetSymbolAddress((void**)&kh, g_kh); cudaGetSymbolAddress((void**)&kl, g_kl);
    cudaGetSymbolAddress((void**)&vh, g_vh); cudaGetSymbolAddress((void**)&vl, g_vl);
    int8_t *xqh, *xql, *aqh, *aql, *x1qh, *x1ql, *hqh, *hql;
    int8_t *wqh, *wql, *woh, *wol, *w1h, *w1l, *w2h, *w2l;
    float *sx, *sa, *sx1, *sh, *swq, *swo, *sw1, *sw2;
    cudaGetSymbolAddress((void**)&xqh,  g_xq_h);  cudaGetSymbolAddress((void**)&xql,  g_xq_l);
    cudaGetSymbolAddress((void**)&aqh,  g_aq_h);  cudaGetSymbolAddress((void**)&aql,  g_aq_l);
    cudaGetSymbolAddress((void**)&x1qh, g_x1q_h); cudaGetSymbolAddress((void**)&x1ql, g_x1q_l);
    cudaGetSymbolAddress((void**)&hqh,  g_hq_h);  cudaGetSymbolAddress((void**)&hql,  g_hq_l);
    cudaGetSymbolAddress((void**)&wqh,  g_wq_h);  cudaGetSymbolAddress((void**)&wql,  g_wq_l);
    cudaGetSymbolAddress((void**)&woh,  g_wo_h);  cudaGetSymbolAddress((void**)&wol,  g_wo_l);
    cudaGetSymbolAddress((void**)&w1h,  g_w1_h);  cudaGetSymbolAddress((void**)&w1l,  g_w1_l);
    cudaGetSymbolAddress((void**)&w2h,  g_w2_h);  cudaGetSymbolAddress((void**)&w2l,  g_w2_l);
    cudaGetSymbolAddress((void**)&sx,  g_sx);  cudaGetSymbolAddress((void**)&sa,  g_sa);
    cudaGetSymbolAddress((void**)&sx1, g_sx1); cudaGetSymbolAddress((void**)&sh,  g_sh);
    cudaGetSymbolAddress((void**)&swq, g_swq); cudaGetSymbolAddress((void**)&swo, g_swo);
    cudaGetSymbolAddress((void**)&sw1, g_sw1); cudaGetSymbolAddress((void**)&sw2, g_sw2);

    cudaFuncSetAttribute(gemm_i8<0>, cudaFuncAttributeMaxDynamicSharedMemorySize, IGSMEM);
    cudaFuncSetAttribute(gemm_i8<1>, cudaFuncAttributeMaxDynamicSharedMemorySize, IGSMEM);
    cudaFuncSetAttribute(gemm_i8<2>, cudaFuncAttributeMaxDynamicSharedMemorySize, IGSMEM);
    cudaFuncSetAttribute(attn_mma, cudaFuncAttributeMaxDynamicSharedMemorySize, ATTN_SMEM);

    // 1. all weight quantizations
    quant_weights<<<9216, 256>>>(qkv_w, o_w, w1, w2,
                                 wqh, wql, swq, woh, wol, swo,
                                 w1h, w1l, sw1, w2h, w2l, sw2);
    // 2. xn = rmsnorm(x) -> int8 digits
    rmsnorm_quant<<<T_LEN, 256>>>(x, xqh, xql, sx);
    // 3. rope table
    rope_tab<<<256, 256>>>(rope);
    // 4. qkv = xn @ qkv_w^T   <-- profiled slot
    gemm_i8<0><<<dim3(QKV_DIM / IBN, T_LEN / IBM), 256, IGSMEM>>>(
        xqh, xql, sx, wqh, wql, swq, DIM, QKV_DIM, qkv, nullptr, nullptr);
    // 5. q/k norm+rope, v -> bf16 hi/lo
    qk_prep<<<dim3(T_LEN, 6), 256>>>(qkv, rope, qh, ql, kh, kl, vh, vl);
    // 6. attention -> fp32
    attn_mma<<<dim3(T_LEN / 64, NHEADS), 128, ATTN_SMEM>>>(qh, ql, kh, kl, vh, vl, attn);
    // 7. quantize attention output
    quant_rows<<<T_LEN, 256>>>(attn, DIM, aqh, aql, sa);
    // 8. x1 = x + o_scale[n] * (attn @ o_w^T)
    gemm_i8<1><<<dim3(DIM / IBN, T_LEN / IBM), 256, IGSMEM>>>(
        aqh, aql, sa, woh, wol, swo, DIM, DIM, x1, x, o_scale);
    // 9. x1n = rmsnorm(x1) -> int8 digits
    rmsnorm_quant<<<T_LEN, 256>>>(x1, x1qh, x1ql, sx1);
    // 10. h = relu(x1n @ w1^T)^2 -> fp32
    gemm_i8<2><<<dim3(MLP_DIM / IBN, T_LEN / IBM), 256, IGSMEM>>>(
        x1qh, x1ql, sx1, w1h, w1l, sw1, DIM, MLP_DIM, hf, nullptr, nullptr);
    // 11. quantize h
    quant_rows<<<T_LEN, 256>>>(hf, MLP_DIM, hqh, hql, sh);
    // 12. out = x1 + w2_scale[n] * (h @ w2^T)
    gemm_i8<1><<<dim3(DIM / IBN, T_LEN / IBM), 256, IGSMEM>>>(
        hqh, hql, sh, w2h, w2l, sw2, MLP_DIM, DIM, out, x1, w2_scale);
}

// round 13
// speedup vs baseline: 8.4084x; 1.7085x over previous
#include <cuda_runtime.h>
#include <cuda_bf16.h>
#include <math_constants.h>
#include <cstdint>

#define T_LEN   4096
#define DIM     1024
#define QKV_DIM 3072
#define MLP_DIM 4096
#define NHEADS  16
#define HD      64
#define WIN     512
#define EPS_F   1.1920929e-07f

// ================= helpers =================
__device__ __forceinline__ uint32_t smem_u32(const void* p) {
    uint32_t a;
    asm("{ .reg .u64 t; cvta.to.shared.u64 t, %1; cvt.u32.u64 %0, t; }" : "=r"(a) : "l"(p));
    return a;
}
__device__ __forceinline__ void cp16(uint32_t s, const void* g) {
    asm volatile("cp.async.cg.shared.global [%0], [%1], 16;" :: "r"(s), "l"(g));
}
__device__ __forceinline__ void ldsm_x4(uint32_t* r, uint32_t addr) {
    asm volatile("ldmatrix.sync.aligned.m8n8.x4.shared.b16 {%0,%1,%2,%3}, [%4];"
                 : "=r"(r[0]), "=r"(r[1]), "=r"(r[2]), "=r"(r[3]) : "r"(addr));
}
__device__ __forceinline__ void ldsm_x4_t(uint32_t* r, uint32_t addr) {
    asm volatile("ldmatrix.sync.aligned.m8n8.x4.trans.shared.b16 {%0,%1,%2,%3}, [%4];"
                 : "=r"(r[0]), "=r"(r[1]), "=r"(r[2]), "=r"(r[3]) : "r"(addr));
}
__device__ __forceinline__ void mma16816(float* c, const uint32_t* a, const uint32_t* b) {
    asm volatile("mma.sync.aligned.m16n8k16.row.col.f32.bf16.bf16.f32 "
        "{%0,%1,%2,%3}, {%4,%5,%6,%7}, {%8,%9}, {%0,%1,%2,%3};"
        : "+f"(c[0]), "+f"(c[1]), "+f"(c[2]), "+f"(c[3])
        : "r"(a[0]), "r"(a[1]), "r"(a[2]), "r"(a[3]), "r"(b[0]), "r"(b[1]));
}
__device__ __forceinline__ void imma16832(int* c, const uint32_t* a, const uint32_t* b) {
    asm volatile("mma.sync.aligned.m16n8k32.row.col.s32.s8.s8.s32 "
        "{%0,%1,%2,%3}, {%4,%5,%6,%7}, {%8,%9}, {%0,%1,%2,%3};"
        : "+r"(c[0]), "+r"(c[1]), "+r"(c[2]), "+r"(c[3])
        : "r"(a[0]), "r"(a[1]), "r"(a[2]), "r"(a[3]), "r"(b[0]), "r"(b[1]));
}
__device__ __forceinline__ void split_bf16(float a, __nv_bfloat16& hi, __nv_bfloat16& lo) {
    hi = __float2bfloat16(a);
    lo = __float2bfloat16(a - __bfloat162float(hi));
}
__device__ __forceinline__ uint32_t pack2(__nv_bfloat16 a, __nv_bfloat16 b) {
    return (uint32_t)__bfloat16_as_ushort(a) | ((uint32_t)__bfloat16_as_ushort(b) << 16);
}
__device__ __forceinline__ uint32_t pack_hi(float a, float b) {
    return pack2(__float2bfloat16(a), __float2bfloat16(b));
}
__device__ __forceinline__ uint32_t pack_lo(float a, float b) {
    __nv_bfloat16 ha = __float2bfloat16(a), hb = __float2bfloat16(b);
    return pack2(__float2bfloat16(a - __bfloat162float(ha)),
                 __float2bfloat16(b - __bfloat162float(hb)));
}

#define MBARRIER_INIT(addr, cnt) \
    asm volatile("mbarrier.init.shared.b64 [%0], %1;" :: "r"((uint32_t)(addr)), "r"((uint32_t)(cnt)) : "memory")
#define MBARRIER_ARRIVE(addr) \
    asm volatile("mbarrier.arrive.shared::cta.b64 _, [%0];" :: "r"((uint32_t)(addr)) : "memory")
#define CPASYNC_MBAR_ARRIVE(addr) \
    asm volatile("cp.async.mbarrier.arrive.noinc.shared::cta.b64 [%0];" :: "r"((uint32_t)(addr)) : "memory")
#define MBARRIER_WAIT_PARITY(addr, par) do { \
    uint32_t _m = (uint32_t)(addr); uint32_t _p = (uint32_t)(par); uint32_t _d; \
    asm volatile("{\n\t.reg .pred p;\n\tmbarrier.try_wait.parity.acquire.cta.shared::cta.b64 p, [%1], %2;\n\tselp.b32 %0, 1, 0, p;\n\t}" \
        : "=r"(_d) : "r"(_m), "r"(_p) : "memory"); \
    if (!_d) { \
        asm volatile("{\n\t.reg .pred P1;\n\tWL_%=:\n\tmbarrier.try_wait.parity.acquire.cta.shared::cta.b64 P1, [%0], %1, 0x989680;\n\t@P1 bra.uni WD_%=;\n\tbra.uni WL_%=;\n\tWD_%=:\n\t}" \
            :: "r"(_m), "r"(_p) : "memory"); \
    } } while (0)

// ================= scratch =================
__device__ float g_qkv [T_LEN * QKV_DIM];
__device__ float g_x1  [T_LEN * DIM];
__device__ float g_attn[T_LEN * DIM];
__device__ float g_hf  [T_LEN * MLP_DIM];
__device__ float2 g_rope[T_LEN * 16];

#define BF16A __device__ __align__(16) __nv_bfloat16
BF16A g_qh[T_LEN * DIM]; BF16A g_ql[T_LEN * DIM];
BF16A g_kh[T_LEN * DIM]; BF16A g_kl[T_LEN * DIM];
BF16A g_vh[T_LEN * DIM]; BF16A g_vl[T_LEN * DIM];

#define I8A __device__ __align__(16) int8_t
I8A g_xq [T_LEN * DIM];     __device__ float g_sx [T_LEN];
I8A g_aq [T_LEN * DIM];     __device__ float g_sa [T_LEN];
I8A g_x1q[T_LEN * DIM];     __device__ float g_sx1[T_LEN];
I8A g_hq [T_LEN * MLP_DIM]; __device__ float g_sh [T_LEN];
I8A g_wq [QKV_DIM * DIM];   __device__ float g_swq[QKV_DIM];
I8A g_wo [DIM * DIM];       __device__ float g_swo[DIM];
I8A g_w1q[MLP_DIM * DIM];   __device__ float g_sw1[MLP_DIM];
I8A g_w2q[DIM * MLP_DIM];   __device__ float g_sw2[DIM];

// ================= single-digit row quantization =================
__device__ __forceinline__ float block_max256(float v, float* red) {
    #pragma unroll
    for (int off = 16; off; off >>= 1) v = fmaxf(v, __shfl_xor_sync(0xffffffffu, v, off));
    if ((threadIdx.x & 31) == 0) red[threadIdx.x >> 5] = v;
    __syncthreads();
    float m = red[0];
    #pragma unroll
    for (int i = 1; i < 8; i++) m = fmaxf(m, red[i]);
    return m;
}
__device__ __forceinline__ char4 quant4s(float4 v, float invS) {
    return make_char4((signed char)__float2int_rn(v.x * invS),
                      (signed char)__float2int_rn(v.y * invS),
                      (signed char)__float2int_rn(v.z * invS),
                      (signed char)__float2int_rn(v.w * invS));
}

__device__ __forceinline__ void quant_row_body(const float* __restrict__ src, int ncols,
                                               int8_t* __restrict__ q,
                                               float* __restrict__ Srow, int row) {
    __shared__ float red[8];
    const float* r = src + (size_t)row * ncols;
    const int tid = threadIdx.x;
    const int n4 = ncols >> 2;
    float amax = 0.f;
    for (int i = tid; i < n4; i += 256) {
        float4 v = ((const float4*)r)[i];
        amax = fmaxf(amax, fmaxf(fmaxf(fabsf(v.x), fabsf(v.y)), fmaxf(fabsf(v.z), fabsf(v.w))));
    }
    const float m = block_max256(amax, red);
    const float S = fmaxf(m, 1e-20f) * (1.0f / 127.0f);
    const float invS = 1.0f / S;
    for (int i = tid; i < n4; i += 256) {
        float4 v = ((const float4*)r)[i];
        ((char4*)(q + (size_t)row * ncols))[i] = quant4s(v, invS);
    }
    if (tid == 0) Srow[row] = S;
}

__global__ __launch_bounds__(256) void quant_rows(const float* __restrict__ src, int ncols,
                                                  int8_t* __restrict__ q,
                                                  float* __restrict__ S) {
    quant_row_body(src, ncols, q, S, blockIdx.x);
}

__global__ __launch_bounds__(256) void quant_weights(
    const float* qkv_w, const float* o_w, const float* w1, const float* w2,
    int8_t* wq, float* swq, int8_t* wo, float* swo,
    int8_t* w1q, float* sw1, int8_t* w2q, float* sw2) {
    int r = blockIdx.x;
    if (r < 3072)       quant_row_body(qkv_w, 1024, wq,  swq, r);
    else if (r < 4096)  quant_row_body(o_w,   1024, wo,  swo, r - 3072);
    else if (r < 8192)  quant_row_body(w1,    1024, w1q, sw1, r - 4096);
    else                quant_row_body(w2,    4096, w2q, sw2, r - 8192);
}

// ================= rmsnorm -> int8 single-digit =================
__global__ __launch_bounds__(256) void rmsnorm_quant(const float* __restrict__ x,
                                                     int8_t* __restrict__ q,
                                                     float* __restrict__ S) {
    __shared__ float red[8], redm[8];
    const int row = blockIdx.x;
    const int tid = threadIdx.x;
    float4 v = ((const float4*)(x + (size_t)row * DIM))[tid];
    float ss = v.x * v.x + v.y * v.y + v.z * v.z + v.w * v.w;
    float am = fmaxf(fmaxf(fabsf(v.x), fabsf(v.y)), fmaxf(fabsf(v.z), fabsf(v.w)));
    #pragma unroll
    for (int off = 16; off; off >>= 1) {
        ss += __shfl_xor_sync(0xffffffffu, ss, off);
        am = fmaxf(am, __shfl_xor_sync(0xffffffffu, am, off));
    }
    if ((tid & 31) == 0) { red[tid >> 5] = ss; redm[tid >> 5] = am; }
    __syncthreads();
    float tot = 0.f, m = 0.f;
    #pragma unroll
    for (int i = 0; i < 8; i++) { tot += red[i]; m = fmaxf(m, redm[i]); }
    const float r = rsqrtf(tot * (1.0f / DIM) + EPS_F);
    v.x *= r; v.y *= r; v.z *= r; v.w *= r;
    const float Sv = fmaxf(m * r, 1e-20f) * (1.0f / 127.0f);
    ((char4*)(q + (size_t)row * DIM))[tid] = quant4s(v, 1.0f / Sv);
    if (tid == 0) S[row] = Sv;
}

// ================= rope table =================
__global__ __launch_bounds__(256) void rope_tab(float2* __restrict__ tab) {
    const int idx = blockIdx.x * 256 + threadIdx.x;
    const int t = idx >> 4, j = idx & 15;
    const float f = powf(1e-4f, (float)j * (1.0f / 15.0f));
    float sn, cs;
    sincosf((float)t * f, &sn, &cs);
    tab[idx] = make_float2(cs, sn);
}

// ================= per-head q/k rmsnorm + rope; v split -> bf16 hi/lo =================
__global__ __launch_bounds__(256) void qk_prep(const float* __restrict__ qkv,
                                               const float2* __restrict__ rope,
                                               __nv_bfloat16* __restrict__ qh, __nv_bfloat16* __restrict__ ql,
                                               __nv_bfloat16* __restrict__ kh, __nv_bfloat16* __restrict__ kl,
                                               __nv_bfloat16* __restrict__ vh, __nv_bfloat16* __restrict__ vl) {
    const int t    = blockIdx.x;
    const int idx  = blockIdx.y * 8 + (threadIdx.x >> 5);
    const int lane = threadIdx.x & 31;
    const int head = idx & 15;
    const size_t dsto = (size_t)t * DIM + head * HD;
    __nv_bfloat16 *dh, *dl;
    const float* src;
    if (idx < 16) {
        src = qkv + (size_t)t * QKV_DIM + head * HD;
        dh = qh + dsto; dl = ql + dsto;
    } else if (idx < 32) {
        src = qkv + (size_t)t * QKV_DIM + DIM + head * HD;
        dh = kh + dsto; dl = kl + dsto;
    } else {
        src = qkv + (size_t)t * QKV_DIM + 2 * DIM + head * HD;
        dh = vh + dsto; dl = vl + dsto;
    }
    float a = src[lane];
    float b = src[lane + 32];
    if (idx < 32) {
        float ss = a * a + b * b;
        #pragma unroll
        for (int off = 16; off; off >>= 1) ss += __shfl_xor_sync(0xffffffffu, ss, off);
        const float r = rsqrtf(ss * (1.0f / HD) + EPS_F);
        a *= r; b *= r;
        float sn = 0.f, cs = 1.f;
        if (lane < 16) {
            const float2 e = rope[t * 16 + lane];
            cs = e.x; sn = e.y;
        }
        const float y1 =  a * cs + b * sn;
        const float y2 = -a * sn + b * cs;
        a = y1; b = y2;
    }
    __nv_bfloat16 ha, la, hb, lb;
    split_bf16(a, ha, la);
    split_bf16(b, hb, lb);
    dh[lane] = ha;      dl[lane] = la;
    dh[lane + 32] = hb; dl[lane + 32] = lb;
}

// ================= tensor-core sliding-window attention =================
#define KVS_B 144
#define KVSPLIT 9216
#define ABUF (2 * KVSPLIT)
#define KVBUF (4 * KVSPLIT)
#define ATTN_SMEM (ABUF + 2 * KVBUF)    // 92160

__global__ __launch_bounds__(128) void attn_mma(
    const __nv_bfloat16* __restrict__ qh, const __nv_bfloat16* __restrict__ ql,
    const __nv_bfloat16* __restrict__ kh, const __nv_bfloat16* __restrict__ kl,
    const __nv_bfloat16* __restrict__ vh, const __nv_bfloat16* __restrict__ vl,
    float* __restrict__ outf) {
    extern __shared__ char smem[];
    const uint32_t sb = smem_u32(smem);
    const int h    = blockIdx.y;
    const int q0   = blockIdx.x * 64;
    const int tid  = threadIdx.x;
    const int wid  = tid >> 5;
    const int lane = tid & 31;

    #pragma unroll
    for (int it = 0; it < 4; it++) {
        const int g = tid + it * 128;
        const int row = g >> 3, cg = g & 7;
        const size_t src = (size_t)(q0 + row) * DIM + h * HD + cg * 8;
        const uint32_t off = (uint32_t)(row * KVS_B + cg * 16);
        cp16(sb + off, qh + src);
        cp16(sb + KVSPLIT + off, ql + src);
    }
    asm volatile("cp.async.commit_group;" ::: "memory");

    auto load_kv = [&](int kc, int buf) {
        const uint32_t base = sb + ABUF + buf * KVBUF;
        #pragma unroll
        for (int it = 0; it < 4; it++) {
            const int g = tid + it * 128;
            const int row = g >> 3, cg = g & 7;
            const size_t src = (size_t)(kc + row) * DIM + h * HD + cg * 8;
            const uint32_t off = (uint32_t)(row * KVS_B + cg * 16);
            cp16(base + off, kh + src);
            cp16(base + KVSPLIT + off, kl + src);
            cp16(base + 2 * KVSPLIT + off, vh + src);
            cp16(base + 3 * KVSPLIT + off, vl + src);
        }
        asm volatile("cp.async.commit_group;" ::: "memory");
    };

    const int kc0 = (q0 >= WIN) ? (q0 - WIN) : 0;
    const int nch = (q0 + 64 - kc0) >> 6;
    load_kv(kc0, 0);

    asm volatile("cp.async.wait_group 1;" ::: "memory");
    __syncthreads();
    uint32_t qfh[16], qfl[16];
    #pragma unroll
    for (int ks = 0; ks < 4; ks++) {
        const uint32_t ad = sb + (uint32_t)((wid * 16 + (lane & 15)) * KVS_B)
                          + ((lane >> 4) * 16) + ks * 32;
        ldsm_x4(qfh + ks * 4, ad);
        ldsm_x4(qfl + ks * 4, ad + KVSPLIT);
    }

    float m[2] = {-1e30f, -1e30f}, lsum[2] = {0.f, 0.f};
    float o[8][4];
    #pragma unroll
    for (int i = 0; i < 8; i++)
        #pragma unroll
        for (int j = 0; j < 4; j++) o[i][j] = 0.f;

    const int r0 = lane >> 2;
    const int qrow0 = q0 + wid * 16 + r0;
    const int qrow1 = qrow0 + 8;
    const int colb = (lane & 3) * 2;

    for (int c = 0; c < nch; c++) {
        const int b = c & 1;
        const int kc = kc0 + c * 64;
        if (c + 1 < nch) load_kv(kc + 64, b ^ 1);
        if (c + 1 < nch) { asm volatile("cp.async.wait_group 1;" ::: "memory"); }
        else             { asm volatile("cp.async.wait_group 0;" ::: "memory"); }
        __syncthreads();

        const uint32_t Kb = sb + ABUF + b * KVBUF;
        const uint32_t Vb = Kb + 2 * KVSPLIT;

        float sc[8][4];
        #pragma unroll
        for (int i = 0; i < 8; i++)
            #pragma unroll
            for (int j = 0; j < 4; j++) sc[i][j] = 0.f;
        #pragma unroll
        for (int ks = 0; ks < 4; ks++) {
            #pragma unroll
            for (int np = 0; np < 4; np++) {
                uint32_t bh4[4], bl4[4];
                const uint32_t bd = Kb
                    + (uint32_t)((np * 16 + ((lane >> 4) * 8) + (lane & 7)) * KVS_B)
                    + (((lane >> 3) & 1) * 16) + ks * 32;
                ldsm_x4(bh4, bd);
                ldsm_x4(bl4, bd + KVSPLIT);
                float* c0 = sc[np * 2];
                float* c1 = sc[np * 2 + 1];
                mma16816(c0, qfh + ks * 4, bh4);
                mma16816(c0, qfl + ks * 4, bh4);
                mma16816(c0, qfh + ks * 4, bl4);
                mma16816(c1, qfh + ks * 4, bh4 + 2);
                mma16816(c1, qfl + ks * 4, bh4 + 2);
                mma16816(c1, qfh + ks * 4, bl4 + 2);
            }
        }

        #pragma unroll
        for (int nf = 0; nf < 8; nf++) {
            #pragma unroll
            for (int j = 0; j < 4; j++) {
                const int kg = kc + nf * 8 + colb + (j & 1);
                const int q  = (j < 2) ? qrow0 : qrow1;
                const bool valid = (kg <= q) && (kg > q - WIN);
                sc[nf][j] = valid ? sc[nf][j] * 0.125f : -1e30f;
            }
        }
        float mx0 = -1e30f, mx1 = -1e30f;
        #pragma unroll
        for (int nf = 0; nf < 8; nf++) {
            mx0 = fmaxf(mx0, fmaxf(sc[nf][0], sc[nf][1]));
            mx1 = fmaxf(mx1, fmaxf(sc[nf][2], sc[nf][3]));
        }
        #pragma unroll
        for (int off = 1; off <= 2; off <<= 1) {
            mx0 = fmaxf(mx0, __shfl_xor_sync(0xffffffffu, mx0, off));
            mx1 = fmaxf(mx1, __shfl_xor_sync(0xffffffffu, mx1, off));
        }
        const float mn0 = fmaxf(m[0], mx0);
        const float mn1 = fmaxf(m[1], mx1);
        const float cr0 = __expf(m[0] - mn0);
        const float cr1 = __expf(m[1] - mn1);
        m[0] = mn0; m[1] = mn1;
        float sm0 = 0.f, sm1 = 0.f;
        #pragma unroll
        for (int nf = 0; nf < 8; nf++) {
            sc[nf][0] = __expf(sc[nf][0] - mn0);
            sc[nf][1] = __expf(sc[nf][1] - mn0);
            sc[nf][2] = __expf(sc[nf][2] - mn1);
            sc[nf][3] = __expf(sc[nf][3] - mn1);
            sm0 += sc[nf][0] + sc[nf][1];
            sm1 += sc[nf][2] + sc[nf][3];
        }
        #pragma unroll
        for (int off = 1; off <= 2; off <<= 1) {
            sm0 += __shfl_xor_sync(0xffffffffu, sm0, off);
            sm1 += __shfl_xor_sync(0xffffffffu, sm1, off);
        }
        lsum[0] = lsum[0] * cr0 + sm0;
        lsum[1] = lsum[1] * cr1 + sm1;
        #pragma unroll
        for (int nf = 0; nf < 8; nf++) {
            o[nf][0] *= cr0; o[nf][1] *= cr0;
            o[nf][2] *= cr1; o[nf][3] *= cr1;
        }

        #pragma unroll
        for (int ks = 0; ks < 4; ks++) {
            uint32_t ah4[4], al4[4];
            const float* p0 = sc[ks * 2];
            const float* p1 = sc[ks * 2 + 1];
            ah4[0] = pack_hi(p0[0], p0[1]);  al4[0] = pack_lo(p0[0], p0[1]);
            ah4[1] = pack_hi(p0[2], p0[3]);  al4[1] = pack_lo(p0[2], p0[3]);
            ah4[2] = pack_hi(p1[0], p1[1]);  al4[2] = pack_lo(p1[0], p1[1]);
            ah4[3] = pack_hi(p1[2], p1[3]);  al4[3] = pack_lo(p1[2], p1[3]);
            #pragma unroll
            for (int dg = 0; dg < 4; dg++) {
                uint32_t vh4[4], vl4[4];
                const uint32_t vd = Vb
                    + (uint32_t)((ks * 16 + (lane & 7) + ((lane >> 3) & 1) * 8) * KVS_B)
                    + dg * 32 + (((lane >> 4) & 1) * 16);
                ldsm_x4_t(vh4, vd);
                ldsm_x4_t(vl4, vd + KVSPLIT);
                float* c0 = o[dg * 2];
                float* c1 = o[dg * 2 + 1];
                mma16816(c0, ah4, vh4);
                mma16816(c0, al4, vh4);
                mma16816(c0, ah4, vl4);
                mma16816(c1, ah4, vh4 + 2);
                mma16816(c1, al4, vh4 + 2);
                mma16816(c1, ah4, vl4 + 2);
            }
        }
        __syncthreads();
    }

    const float inv0 = 1.0f / lsum[0];
    const float inv1 = 1.0f / lsum[1];
    #pragma unroll
    for (int nf = 0; nf < 8; nf++) {
        const int col = h * HD + nf * 8 + colb;
        *(float2*)(outf + (size_t)qrow0 * DIM + col) = make_float2(o[nf][0] * inv0, o[nf][1] * inv0);
        *(float2*)(outf + (size_t)qrow1 * DIM + col) = make_float2(o[nf][2] * inv1, o[nf][3] * inv1);
    }
}

// ================= int8 single-digit GEMM v7: mbarrier pipeline =================
// CTA 128x128, 256 threads, 8 warps (2x4), warp tile 64x32, k32 stages (8KB,
// XOR-swizzled), 8 stages, per-stage full/empty mbarriers, no __syncthreads in
// mainloop; 2 CTAs co-resident.  C = Sa[m]*Sb[n]*Ch
#define IBM 128
#define IBN 128
#define NSTG 8
#define STGB 8192
#define IGSMEM (NSTG * STGB + 128)        // 65664

__device__ __forceinline__ uint32_t swz32(uint32_t row, uint32_t g16) {
    return (row * 32u + g16 * 16u) ^ ((row & 4u) << 2);
}

template <int MODE>
__global__ __launch_bounds__(256, 2) void gemm_i8(
    const int8_t* __restrict__ Aq, const float* __restrict__ Sa,
    const int8_t* __restrict__ Bq, const float* __restrict__ Sb,
    int K, int Ntot,
    float* __restrict__ Cf, const float* __restrict__ res, const float* __restrict__ scale) {
    extern __shared__ char smem[];
    const uint32_t sb  = smem_u32(smem);
    const uint32_t mbF = sb + NSTG * STGB;        // full[8]
    const uint32_t mbE = mbF + 64;                // empty[8]
    const int tid  = threadIdx.x;
    const int lane = tid & 31;
    const int wid  = tid >> 5;
    const int wm   = wid >> 2;            // 2 warp rows of 64
    const int wn   = wid & 3;             // 4 warp cols of 32
    const int m0 = blockIdx.y * IBM, n0 = blockIdx.x * IBN;

    int Ch[4][4][4];
    #pragma unroll
    for (int i = 0; i < 4; i++)
        #pragma unroll
        for (int j = 0; j < 4; j++)
            #pragma unroll
            for (int k = 0; k < 4; k++) Ch[i][j][k] = 0;

    if (tid == 0) {
        #pragma unroll
        for (int i = 0; i < NSTG; i++) {
            MBARRIER_INIT(mbF + i * 8, 256);
            MBARRIER_INIT(mbE + i * 8, 256);
        }
    }
    __syncthreads();

    // producer: each thread loads one 16B granule of A and one of B
    const int prow = tid >> 1, pg = tid & 1;
    const uint32_t pso = swz32((uint32_t)prow, (uint32_t)pg);
    const size_t pa = (size_t)(m0 + prow) * K + pg * 16;
    const size_t pb = (size_t)(n0 + prow) * K + pg * 16;
    auto produce = [&](int c, int stage) {
        const uint32_t base = sb + stage * STGB;
        const int kc = c * 32;
        cp16(base + pso,        Aq + pa + kc);
        cp16(base + 4096 + pso, Bq + pb + kc);
        CPASYNC_MBAR_ARRIVE(mbF + stage * 8);
    };

    const int NC = K / 32;
    #pragma unroll
    for (int c0 = 0; c0 < NSTG - 1; c0++) produce(c0, c0);

    for (int c = 0; c < NC; c++) {
        const int stg = c & (NSTG - 1);
        const uint32_t stb = sb + stg * STGB;
        MBARRIER_WAIT_PARITY(mbF + stg * 8, (c >> 3) & 1);

        uint32_t ah[16];
        #pragma unroll
        for (int mf = 0; mf < 4; mf++) {
            const uint32_t arow = (uint32_t)(wm * 64 + mf * 16 + (lane & 15));
            ldsm_x4(ah + mf * 4, stb + swz32(arow, (uint32_t)(lane >> 4)));
        }
        #pragma unroll
        for (int g = 0; g < 2; g++) {
            uint32_t bh4[4];
            const uint32_t brow = (uint32_t)(wn * 32 + g * 16 + ((lane >> 4) * 8) + (lane & 7));
            ldsm_x4(bh4, stb + 4096 + swz32(brow, (uint32_t)((lane >> 3) & 1)));
            #pragma unroll
            for (int mf = 0; mf < 4; mf++) {
                imma16832(Ch[mf][g * 2],     ah + mf * 4, bh4);
                imma16832(Ch[mf][g * 2 + 1], ah + mf * 4, bh4 + 2);
            }
        }
        MBARRIER_ARRIVE(mbE + stg * 8);

        const int p = c + NSTG - 1;
        if (p < NC) {
            const int ps = p & (NSTG - 1);
            if (p >= NSTG) MBARRIER_WAIT_PARITY(mbE + ps * 8, ((p >> 3) + 1) & 1);
            produce(p, ps);
        }
    }

    // ---- epilogue ----
    const int rb = m0 + wm * 64 + (lane >> 2);
    const int cb = n0 + wn * 32 + (lane & 3) * 2;
    #pragma unroll
    for (int mf = 0; mf < 4; mf++) {
        const int rr0 = rb + mf * 16;
        const int rr1 = rr0 + 8;
        const float sa0 = Sa[rr0], sa1 = Sa[rr1];
        #pragma unroll
        for (int nf = 0; nf < 4; nf++) {
            const int cn = cb + nf * 8;
            const float2 sbv = *(const float2*)(Sb + cn);
            const int* ch = Ch[mf][nf];
            float v0 = sa0 * sbv.x * (float)ch[0];
            float v1 = sa0 * sbv.y * (float)ch[1];
            float v2 = sa1 * sbv.x * (float)ch[2];
            float v3 = sa1 * sbv.y * (float)ch[3];
            if (MODE == 1) {
                const float2 sc2 = *(const float2*)(scale + cn);
                const float2 q0 = *(const float2*)(res + (size_t)rr0 * Ntot + cn);
                const float2 q1 = *(const float2*)(res + (size_t)rr1 * Ntot + cn);
                v0 = q0.x + sc2.x * v0; v1 = q0.y + sc2.y * v1;
                v2 = q1.x + sc2.x * v2; v3 = q1.y + sc2.y * v3;
            } else if (MODE == 2) {
                v0 = fmaxf(v0, 0.f); v0 *= v0;
                v1 = fmaxf(v1, 0.f); v1 *= v1;
                v2 = fmaxf(v2, 0.f); v2 *= v2;
                v3 = fmaxf(v3, 0.f); v3 *= v3;
            }
            *(float2*)(Cf + (size_t)rr0 * Ntot + cn) = make_float2(v0, v1);
            *(float2*)(Cf + (size_t)rr1 * Ntot + cn) = make_float2(v2, v3);
        }
    }
}

// ================= host launcher =================
extern "C" void kernel_launch(void* const* d_in, const int* in_sizes, int n_in,
                              void* d_out, int out_size) {
    const float* x        = (const float*)d_in[0];
    const float* qkv_w    = (const float*)d_in[1];
    const float* o_w      = (const float*)d_in[2];
    const float* o_scale  = (const float*)d_in[3];
    const float* w1       = (const float*)d_in[4];
    const float* w2       = (const float*)d_in[5];
    const float* w2_scale = (const float*)d_in[6];
    float* out = (float*)d_out;

    float *qkv, *x1, *attn, *hf;
    float2* rope;
    cudaGetSymbolAddress((void**)&qkv,  g_qkv);
    cudaGetSymbolAddress((void**)&x1,   g_x1);
    cudaGetSymbolAddress((void**)&attn, g_attn);
    cudaGetSymbolAddress((void**)&hf,   g_hf);
    cudaGetSymbolAddress((void**)&rope, g_rope);
    __nv_bfloat16 *qh, *ql, *kh, *kl, *vh, *vl;
    cudaGetSymbolAddress((void**)&qh, g_qh); cudaGetSymbolAddress((void**)&ql, g_ql);
    cudaGetSymbolAddress((void**)&kh, g_kh); cudaGetSymbolAddress((void**)&kl, g_kl);
    cudaGetSymbolAddress((void**)&vh, g_vh); cudaGetSymbolAddress((void**)&vl, g_vl);
    int8_t *xq, *aq, *x1q, *hq, *wq, *wo, *w1q, *w2q;
    float *sx, *sa, *sx1, *sh, *swq, *swo, *sw1, *sw2;
    cudaGetSymbolAddress((void**)&xq,  g_xq);  cudaGetSymbolAddress((void**)&aq,  g_aq);
    cudaGetSymbolAddress((void**)&x1q, g_x1q); cudaGetSymbolAddress((void**)&hq,  g_hq);
    cudaGetSymbolAddress((void**)&wq,  g_wq);  cudaGetSymbolAddress((void**)&wo,  g_wo);
    cudaGetSymbolAddress((void**)&w1q, g_w1q); cudaGetSymbolAddress((void**)&w2q, g_w2q);
    cudaGetSymbolAddress((void**)&sx,  g_sx);  cudaGetSymbolAddress((void**)&sa,  g_sa);
    cudaGetSymbolAddress((void**)&sx1, g_sx1); cudaGetSymbolAddress((void**)&sh,  g_sh);
    cudaGetSymbolAddress((void**)&swq, g_swq); cudaGetSymbolAddress((void**)&swo, g_swo);
    cudaGetSymbolAddress((void**)&sw1, g_sw1); cudaGetSymbolAddress((void**)&sw2, g_sw2);

    cudaFuncSetAttribute(gemm_i8<0>, cudaFuncAttributeMaxDynamicSharedMemorySize, IGSMEM);
    cudaFuncSetAttribute(gemm_i8<1>, cudaFuncAttributeMaxDynamicSharedMemorySize, IGSMEM);
    cudaFuncSetAttribute(gemm_i8<2>, cudaFuncAttributeMaxDynamicSharedMemorySize, IGSMEM);
    cudaFuncSetAttribute(attn_mma, cudaFuncAttributeMaxDynamicSharedMemorySize, ATTN_SMEM);

    // 1. all weight quantizations
    quant_weights<<<9216, 256>>>(qkv_w, o_w, w1, w2,
                                 wq, swq, wo, swo, w1q, sw1, w2q, sw2);
    // 2. xn = rmsnorm(x) -> int8
    rmsnorm_quant<<<T_LEN, 256>>>(x, xq, sx);
    // 3. rope table
    rope_tab<<<256, 256>>>(rope);
    // 4. qkv = xn @ qkv_w^T   <-- profiled slot
    gemm_i8<0><<<dim3(QKV_DIM / IBN, T_LEN / IBM), 256, IGSMEM>>>(
        xq, sx, wq, swq, DIM, QKV_DIM, qkv, nullptr, nullptr);
    // 5. q/k norm+rope, v -> bf16 hi/lo
    qk_prep<<<dim3(T_LEN, 6), 256>>>(qkv, rope, qh, ql, kh, kl, vh, vl);
    // 6. attention -> fp32
    attn_mma<<<dim3(T_LEN / 64, NHEADS), 128, ATTN_SMEM>>>(qh, ql, kh, kl, vh, vl, attn);
    // 7. quantize attention output
    quant_rows<<<T_LEN, 256>>>(attn, DIM, aq, sa);
    // 8. x1 = x + o_scale[n] * (attn @ o_w^T)
    gemm_i8<1><<<dim3(DIM / IBN, T_LEN / IBM), 256, IGSMEM>>>(
        aq, sa, wo, swo, DIM, DIM, x1, x, o_scale);
    // 9. x1n = rmsnorm(x1) -> int8
    rmsnorm_quant<<<T_LEN, 256>>>(x1, x1q, sx1);
    // 10. h = relu(x1n @ w1^T)^2 -> fp32
    gemm_i8<2><<<dim3(MLP_DIM / IBN, T_LEN / IBM), 256, IGSMEM>>>(
        x1q, sx1, w1q, sw1, DIM, MLP_DIM, hf, nullptr, nullptr);
    // 11. quantize h
    quant_rows<<<T_LEN, 256>>>(hf, MLP_DIM, hq, sh);
    // 12. out = x1 + w2_scale[n] * (h @ w2^T)
    gemm_i8<1><<<dim3(DIM / IBN, T_LEN / IBM), 256, IGSMEM>>>(
        hq, sh, w2q, sw2, MLP_DIM, DIM, out, x1, w2_scale);
}